// round 3
// baseline (speedup 1.0000x reference)
#include <cuda_runtime.h>
#include <cstdint>

#define N_PTS 200000
#define M_PTS 100000

// ---- scratch (device-global, no allocation) ----
__device__ float g_feats_x[N_PTS * 32];            // 25.6 MB
__device__ float g_guid_x[N_PTS * 32];             // 25.6 MB
__device__ float g_agg[(size_t)M_PTS * 512];       // 204.8 MB
__device__ float g_maxf[M_PTS * 64];               // 25.6 MB

// =====================================================================
// Kernel A: per dense point n:
//   feats_x = leaky_relu(dense_feats @ w_unary1 + b, 0.1)   [N,32]
//   guid_x  = feats_x @ w_gu + b_gu                          [N,32]
// warp-per-point, 4 warps/block
// =====================================================================
__global__ __launch_bounds__(128) void kA(const float* __restrict__ df,
                                          const float* __restrict__ w1,
                                          const float* __restrict__ b1,
                                          const float* __restrict__ wgu,
                                          const float* __restrict__ bgu) {
    __shared__ float s_w1[64 * 32], s_wgu[32 * 32], s_b1[32], s_bgu[32];
    int tid = threadIdx.x;
    for (int i = tid; i < 64 * 32; i += 128) s_w1[i] = w1[i];
    for (int i = tid; i < 32 * 32; i += 128) s_wgu[i] = wgu[i];
    if (tid < 32) { s_b1[tid] = b1[tid]; s_bgu[tid] = bgu[tid]; }
    __syncthreads();

    int lane = tid & 31;
    int n = blockIdx.x * 4 + (tid >> 5);
    if (n >= N_PTS) return;

    float f0 = df[n * 64 + lane];
    float f1 = df[n * 64 + 32 + lane];
    float fx = s_b1[lane];
#pragma unroll
    for (int j = 0; j < 32; j++)
        fx = fmaf(__shfl_sync(~0u, f0, j), s_w1[j * 32 + lane], fx);
#pragma unroll
    for (int j = 0; j < 32; j++)
        fx = fmaf(__shfl_sync(~0u, f1, j), s_w1[(32 + j) * 32 + lane], fx);
    fx = fx > 0.f ? fx : 0.1f * fx;
    g_feats_x[n * 32 + lane] = fx;

    float gx = s_bgu[lane];
#pragma unroll
    for (int j = 0; j < 32; j++)
        gx = fmaf(__shfl_sync(~0u, fx, j), s_wgu[j * 32 + lane], gx);
    g_guid_x[n * 32 + lane] = gx;
}

// =====================================================================
// Kernel B: per sparse point m (warp-per-point, 4 warps/block):
//   gathers, PE MLP, guidance scores, WeightNet, einsum -> agg[m,512]
//   plus shortcut max-pool of dense feats -> g_maxf[m,64]
// =====================================================================
__global__ __launch_bounds__(128) void kB(
    const float* __restrict__ df, const float* __restrict__ vi,
    const int* __restrict__ nei,
    const float* __restrict__ wpe, const float* __restrict__ bpe,
    const float* __restrict__ wg1, const float* __restrict__ bg1,
    const float* __restrict__ wg2, const float* __restrict__ bg2,
    const float* __restrict__ wn1, const float* __restrict__ bn1,
    const float* __restrict__ wn2, const float* __restrict__ bn2,
    const float* __restrict__ wn3, const float* __restrict__ bn3) {
    __shared__ float s_wpe[384], s_bpe[32];
    __shared__ float s_wg1p[544], s_bg1[8], s_wg2[64], s_bg2[8];   // wg1 in conflict-free layout [g][cc][h], stride 136 per g
    __shared__ float s_w1[96], s_b1[8], s_w2[64], s_b2[8], s_w3[128], s_b3[16];
    __shared__ float s_vi[4][192];
    __shared__ float s_gfeat[4][16 * 64];
    __shared__ float s_gf[4][16 * 32];
    __shared__ float s_wn[4][256];
    __shared__ float s_gmax[4][64];
    __shared__ int   s_idx[4][16];

    int tid = threadIdx.x;
    for (int i = tid; i < 384; i += 128) s_wpe[i] = wpe[i];
    for (int i = tid; i < 512; i += 128) {
        int c = i >> 3, h = i & 7;
        s_wg1p[(c >> 4) * 136 + (c & 15) * 8 + h] = wg1[i];
    }
    if (tid < 64)  s_wg2[tid] = wg2[tid];
    if (tid < 96)  s_w1[tid] = wn1[tid];
    if (tid < 64)  s_w2[tid] = wn2[tid];
    if (tid < 128) s_w3[tid] = wn3[tid];
    if (tid < 32)  s_bpe[tid] = bpe[tid];
    if (tid < 8) { s_bg1[tid] = bg1[tid]; s_bg2[tid] = bg2[tid];
                   s_b1[tid] = bn1[tid]; s_b2[tid] = bn2[tid]; }
    if (tid < 16) s_b3[tid] = bn3[tid];
    __syncthreads();

    int lane = tid & 31, w = tid >> 5;
    int m = blockIdx.x * 4 + w;
    if (m >= M_PTS) return;

    for (int i = lane; i < 192; i += 32) s_vi[w][i] = vi[m * 192 + i];
    if (lane < 16) s_idx[w][lane] = nei[m * 16 + lane];
    __syncwarp();

    float gmax0 = -1e30f, gmax1 = -1e30f, sc0 = -1e30f, sc1 = -1e30f;
    int h = lane & 7;
    int hw = lane & 15;

    // ---------- Phase 1: per-neighbor gathers + small MLPs ----------
    for (int k = 0; k < 16; k++) {
        int n = s_idx[w][k];
        const float* vk = &s_vi[w][k * 12];

        float gg = g_guid_x[n * 32 + lane];
        float pe = s_bpe[lane];
#pragma unroll
        for (int j = 0; j < 12; j++) pe = fmaf(vk[j], s_wpe[j * 32 + lane], pe);
        pe = fmaxf(pe, 0.f);
        s_gfeat[w][k * 64 + lane] = gg;
        s_gfeat[w][k * 64 + 32 + lane] = pe;
        gmax0 = fmaxf(gmax0, gg);
        gmax1 = fmaxf(gmax1, pe);

        s_gf[w][k * 32 + lane] = g_feats_x[n * 32 + lane];
        sc0 = fmaxf(sc0, df[n * 64 + lane]);
        sc1 = fmaxf(sc1, df[n * 64 + 32 + lane]);

        // WeightNet 12->8->8->16 (lane-replicated compute, shfl between layers)
        float h1 = s_b1[h];
#pragma unroll
        for (int j = 0; j < 12; j++) h1 = fmaf(vk[j], s_w1[j * 8 + h], h1);
        h1 = fmaxf(h1, 0.f);
        float h2 = s_b2[h];
#pragma unroll
        for (int j = 0; j < 8; j++) h2 = fmaf(__shfl_sync(~0u, h1, j), s_w2[j * 8 + h], h2);
        h2 = fmaxf(h2, 0.f);
        float wnv = s_b3[hw];
#pragma unroll
        for (int j = 0; j < 8; j++) wnv = fmaf(__shfl_sync(~0u, h2, j), s_w3[j * 16 + hw], wnv);
        wnv = fmaxf(wnv, 0.f);
        if (lane < 16) s_wn[w][k * 16 + lane] = wnv;
    }
    s_gmax[w][lane] = gmax0;
    s_gmax[w][32 + lane] = gmax1;
    __syncwarp();

    // ---------- Phase 2: scores + weighted einsum accumulate ----------
    float acc[16];
#pragma unroll
    for (int i = 0; i < 16; i++) acc[i] = 0.f;
    int g = lane >> 3;
    const float* wg1g = &s_wg1p[g * 136];

    for (int k = 0; k < 16; k++) {
        // hid[h] = relu( sum_c (gfeat[c]-gmax[c]) * wg1[c][h] + b )
        float hid = 0.f;
#pragma unroll
        for (int cc = 0; cc < 16; cc++) {
            int c = g * 16 + cc;
            hid = fmaf(s_gfeat[w][k * 64 + c] - s_gmax[w][c], wg1g[cc * 8 + h], hid);
        }
        hid += __shfl_xor_sync(~0u, hid, 8);
        hid += __shfl_xor_sync(~0u, hid, 16);
        hid = fmaxf(hid + s_bg1[h], 0.f);

        float scz = s_bg2[h];
#pragma unroll
        for (int j = 0; j < 8; j++)
            scz = fmaf(__shfl_sync(~0u, hid, j), s_wg2[j * 8 + h], scz);
        float score = 1.f / (1.f + __expf(-scz));   // lane holds score[lane&7]

        float sC = __shfl_sync(~0u, score, lane >> 2);  // head = channel/4
        float nf = s_gf[w][k * 32 + lane] * sC;
#pragma unroll
        for (int q = 0; q < 16; q++)
            acc[q] = fmaf(nf, s_wn[w][k * 16 + q], acc[q]);
    }

    // agg[m][c*16+w], c = lane -> each lane writes 64B contiguous (4x STG.128)
    size_t base = (size_t)m * 512 + lane * 16;
#pragma unroll
    for (int q4 = 0; q4 < 4; q4++) {
        float4 v = make_float4(acc[q4 * 4], acc[q4 * 4 + 1],
                               acc[q4 * 4 + 2], acc[q4 * 4 + 3]);
        *(float4*)&g_agg[base + q4 * 4] = v;
    }
    g_maxf[m * 64 + lane] = sc0;
    g_maxf[m * 64 + 32 + lane] = sc1;
}

// =====================================================================
// Kernel C: out64 = relu(agg @ w_lin + b_lin)          [64 m-tile, 64]
//           out   = leaky(out64 @ w_u2 + maxf @ w_sc + b_u2 + b_sc)
// 256 threads, BM=64, BN=64, BK=16, TM=TN=4; epilogue TM=4, TN=8.
// =====================================================================
__global__ __launch_bounds__(256) void kC(
    const float* __restrict__ wlin, const float* __restrict__ blin,
    const float* __restrict__ wu2, const float* __restrict__ bu2,
    const float* __restrict__ wsc, const float* __restrict__ bsc,
    float* __restrict__ out) {
    extern __shared__ float sm[];
    float* As  = sm;               // [64][16]
    float* Bs  = As + 64 * 16;     // [16][64]
    float* o64 = Bs + 16 * 64;     // [64][65]
    float* mfs = o64 + 64 * 65;    // [64][65]
    float* su2 = mfs + 64 * 65;    // [64][128]
    float* ssc = su2 + 64 * 128;   // [64][128]

    int tid = threadIdx.x;
    int m0 = blockIdx.x * 64;

    for (int i = tid; i < 8192; i += 256) { su2[i] = wu2[i]; ssc[i] = wsc[i]; }
    for (int i = tid; i < 4096; i += 256) {
        int mm = i >> 6, j = i & 63;
        int m = m0 + mm;
        mfs[mm * 65 + j] = (m < M_PTS) ? g_maxf[m * 64 + j] : 0.f;
    }

    int tx = tid & 15, ty = tid >> 4;
    float acc[4][4];
#pragma unroll
    for (int i = 0; i < 4; i++)
#pragma unroll
        for (int j = 0; j < 4; j++) acc[i][j] = 0.f;

    int lmm = tid >> 2, lk4 = (tid & 3) * 4;
    int lkk = tid >> 4, lo4 = (tid & 15) * 4;
    bool avalid = (m0 + lmm) < M_PTS;
    int mrow = m0 + lmm; if (mrow >= M_PTS) mrow = M_PTS - 1;
    const float* aptr = &g_agg[(size_t)mrow * 512 + lk4];
    __syncthreads();

    for (int kb = 0; kb < 32; kb++) {
        float4 av = avalid ? *(const float4*)(aptr + kb * 16)
                           : make_float4(0.f, 0.f, 0.f, 0.f);
        float4 bv = *(const float4*)&wlin[(kb * 16 + lkk) * 64 + lo4];
        *(float4*)&As[lmm * 16 + lk4] = av;
        *(float4*)&Bs[lkk * 64 + lo4] = bv;
        __syncthreads();
#pragma unroll
        for (int kk = 0; kk < 16; kk++) {
            float a0 = As[(ty * 4 + 0) * 16 + kk];
            float a1 = As[(ty * 4 + 1) * 16 + kk];
            float a2 = As[(ty * 4 + 2) * 16 + kk];
            float a3 = As[(ty * 4 + 3) * 16 + kk];
            float b0 = Bs[kk * 64 + tx * 4 + 0];
            float b1 = Bs[kk * 64 + tx * 4 + 1];
            float b2 = Bs[kk * 64 + tx * 4 + 2];
            float b3 = Bs[kk * 64 + tx * 4 + 3];
            acc[0][0] = fmaf(a0, b0, acc[0][0]); acc[0][1] = fmaf(a0, b1, acc[0][1]);
            acc[0][2] = fmaf(a0, b2, acc[0][2]); acc[0][3] = fmaf(a0, b3, acc[0][3]);
            acc[1][0] = fmaf(a1, b0, acc[1][0]); acc[1][1] = fmaf(a1, b1, acc[1][1]);
            acc[1][2] = fmaf(a1, b2, acc[1][2]); acc[1][3] = fmaf(a1, b3, acc[1][3]);
            acc[2][0] = fmaf(a2, b0, acc[2][0]); acc[2][1] = fmaf(a2, b1, acc[2][1]);
            acc[2][2] = fmaf(a2, b2, acc[2][2]); acc[2][3] = fmaf(a2, b3, acc[2][3]);
            acc[3][0] = fmaf(a3, b0, acc[3][0]); acc[3][1] = fmaf(a3, b1, acc[3][1]);
            acc[3][2] = fmaf(a3, b2, acc[3][2]); acc[3][3] = fmaf(a3, b3, acc[3][3]);
        }
        __syncthreads();
    }

    // relu + bias -> o64 smem
#pragma unroll
    for (int j = 0; j < 4; j++) {
        float bl = blin[tx * 4 + j];
#pragma unroll
        for (int i = 0; i < 4; i++) {
            float v = acc[i][j] + bl;
            o64[(ty * 4 + i) * 65 + tx * 4 + j] = fmaxf(v, 0.f);
        }
    }
    __syncthreads();

    // epilogue: [64,64]@[64,128] twice (u2 + shortcut)
    int o0 = (tid & 15) * 8;
    int mm0 = (tid >> 4) * 4;
    float a2acc[4][8];
#pragma unroll
    for (int i = 0; i < 4; i++)
#pragma unroll
        for (int q = 0; q < 8; q++) a2acc[i][q] = 0.f;

    for (int j = 0; j < 64; j++) {
        float4 bA = *(float4*)&su2[j * 128 + o0];
        float4 bB = *(float4*)&su2[j * 128 + o0 + 4];
        float4 cA = *(float4*)&ssc[j * 128 + o0];
        float4 cB = *(float4*)&ssc[j * 128 + o0 + 4];
#pragma unroll
        for (int i = 0; i < 4; i++) {
            float a = o64[(mm0 + i) * 65 + j];
            float c = mfs[(mm0 + i) * 65 + j];
            a2acc[i][0] = fmaf(a, bA.x, fmaf(c, cA.x, a2acc[i][0]));
            a2acc[i][1] = fmaf(a, bA.y, fmaf(c, cA.y, a2acc[i][1]));
            a2acc[i][2] = fmaf(a, bA.z, fmaf(c, cA.z, a2acc[i][2]));
            a2acc[i][3] = fmaf(a, bA.w, fmaf(c, cA.w, a2acc[i][3]));
            a2acc[i][4] = fmaf(a, bB.x, fmaf(c, cB.x, a2acc[i][4]));
            a2acc[i][5] = fmaf(a, bB.y, fmaf(c, cB.y, a2acc[i][5]));
            a2acc[i][6] = fmaf(a, bB.z, fmaf(c, cB.z, a2acc[i][6]));
            a2acc[i][7] = fmaf(a, bB.w, fmaf(c, cB.w, a2acc[i][7]));
        }
    }

#pragma unroll
    for (int i = 0; i < 4; i++) {
        int m = m0 + mm0 + i;
        if (m < M_PTS) {
#pragma unroll
            for (int q = 0; q < 8; q++) {
                float v = a2acc[i][q] + bu2[o0 + q] + bsc[o0 + q];
                out[(size_t)m * 128 + o0 + q] = v > 0.f ? v : 0.1f * v;
            }
        }
    }
}

// =====================================================================
extern "C" void kernel_launch(void* const* d_in, const int* in_sizes, int n_in,
                              void* d_out, int out_size) {
    const float* dense_feats = (const float*)d_in[1];
    const float* vi          = (const float*)d_in[5];
    const int*   nei         = (const int*)d_in[6];
    const float* w_u1  = (const float*)d_in[7];  const float* b_u1  = (const float*)d_in[8];
    const float* w_gu  = (const float*)d_in[9];  const float* b_gu  = (const float*)d_in[10];
    const float* w_pe  = (const float*)d_in[11]; const float* b_pe  = (const float*)d_in[12];
    const float* w_g1  = (const float*)d_in[13]; const float* b_g1  = (const float*)d_in[14];
    const float* w_g2  = (const float*)d_in[15]; const float* b_g2  = (const float*)d_in[16];
    const float* w_wn1 = (const float*)d_in[17]; const float* b_wn1 = (const float*)d_in[18];
    const float* w_wn2 = (const float*)d_in[19]; const float* b_wn2 = (const float*)d_in[20];
    const float* w_wn3 = (const float*)d_in[21]; const float* b_wn3 = (const float*)d_in[22];
    const float* w_lin = (const float*)d_in[23]; const float* b_lin = (const float*)d_in[24];
    const float* w_u2  = (const float*)d_in[25]; const float* b_u2  = (const float*)d_in[26];
    const float* w_sc  = (const float*)d_in[27]; const float* b_sc  = (const float*)d_in[28];
    float* out = (float*)d_out;

    kA<<<(N_PTS + 3) / 4, 128>>>(dense_feats, w_u1, b_u1, w_gu, b_gu);
    kB<<<(M_PTS + 3) / 4, 128>>>(dense_feats, vi, nei,
                                 w_pe, b_pe, w_g1, b_g1, w_g2, b_g2,
                                 w_wn1, b_wn1, w_wn2, b_wn2, w_wn3, b_wn3);

    int smemC = (64 * 16 + 16 * 64 + 64 * 65 * 2 + 64 * 128 * 2) * 4;  // 107008 B
    cudaFuncSetAttribute(kC, cudaFuncAttributeMaxDynamicSharedMemorySize, smemC);
    kC<<<(M_PTS + 63) / 64, 256, smemC>>>(w_lin, b_lin, w_u2, b_u2, w_sc, b_sc, out);
}

// round 4
// speedup vs baseline: 1.3452x; 1.3452x over previous
#include <cuda_runtime.h>
#include <cstdint>

#define N_PTS 200000
#define M_PTS 100000

typedef unsigned long long u64;

// ---- scratch (device-global, no allocation) ----
__device__ float g_feats_x[N_PTS * 32];            // 25.6 MB
__device__ float g_guid_x[N_PTS * 32];             // 25.6 MB
__device__ float g_agg[(size_t)M_PTS * 512];       // 204.8 MB
__device__ float g_maxf[M_PTS * 64];               // 25.6 MB

// ---- packed fp32x2 helpers (Blackwell f32x2 pipe: 2x fp32 FMA throughput) ----
__device__ __forceinline__ u64 pk2(float x, float y) {
    u64 r; asm("mov.b64 %0,{%1,%2};" : "=l"(r) : "f"(x), "f"(y)); return r;
}
__device__ __forceinline__ float2 upk2(u64 v) {
    float2 r; asm("mov.b64 {%0,%1},%2;" : "=f"(r.x), "=f"(r.y) : "l"(v)); return r;
}
__device__ __forceinline__ void fma2(u64& d, u64 a, u64 b) {
    asm("fma.rn.f32x2 %0,%1,%2,%3;" : "=l"(d) : "l"(a), "l"(b), "l"(d));
}
__device__ __forceinline__ float lrelu(float x) { return x > 0.f ? x : 0.1f * x; }

// =====================================================================
// Kernel A: tiled GEMM, 128 points/block, 256 threads.
//   stage1: feats_x = leaky(df[128,64] @ w1[64,32] + b1)
//   stage2: guid_x  = feats_x[128,32] @ wgu[32,32] + bgu
// f32x2 accumulators, transposed A tiles for LDS.64 point-pair loads.
// =====================================================================
__global__ __launch_bounds__(256) void kA(const float* __restrict__ df,
                                          const float* __restrict__ w1,
                                          const float* __restrict__ b1,
                                          const float* __restrict__ wgu,
                                          const float* __restrict__ bgu) {
    extern __shared__ float sm[];
    float* s_dfT = sm;                 // [64][130]
    float* s_w1  = s_dfT + 64 * 130;   // [64][32]
    float* s_wgu = s_w1 + 2048;        // [32][32]
    float* s_fxT = s_wgu + 1024;       // [32][130]
    __shared__ float s_b1[32], s_bgu[32];

    int tid = threadIdx.x;
    int p0 = blockIdx.x * 128;

    for (int i = tid; i < 2048; i += 256) s_w1[i] = w1[i];
    for (int i = tid; i < 1024; i += 256) s_wgu[i] = wgu[i];
    if (tid < 32) { s_b1[tid] = b1[tid]; s_bgu[tid] = bgu[tid]; }

#pragma unroll
    for (int q = 0; q < 8; q++) {
        int f4 = tid + q * 256;
        int pt = f4 >> 4, c4 = (f4 & 15) * 4;
        int p = p0 + pt;
        float4 v = (p < N_PTS) ? *(const float4*)&df[(size_t)p * 64 + c4]
                               : make_float4(0.f, 0.f, 0.f, 0.f);
        s_dfT[(c4 + 0) * 130 + pt] = v.x;
        s_dfT[(c4 + 1) * 130 + pt] = v.y;
        s_dfT[(c4 + 2) * 130 + pt] = v.z;
        s_dfT[(c4 + 3) * 130 + pt] = v.w;
    }
    __syncthreads();

    int tx = tid & 7;    // 8 ch-groups of 4
    int ty = tid >> 3;   // 32 pt-groups of 4

    // ---- stage 1 ----
    u64 acc[2][4];
#pragma unroll
    for (int i = 0; i < 2; i++)
#pragma unroll
        for (int j = 0; j < 4; j++) acc[i][j] = 0ull;

#pragma unroll 8
    for (int kk = 0; kk < 64; kk++) {
        const float* ar = &s_dfT[kk * 130 + ty * 4];
        u64 a01 = *(const u64*)(ar);
        u64 a23 = *(const u64*)(ar + 2);
        float4 bv = *(const float4*)&s_w1[kk * 32 + tx * 4];
        u64 b0 = pk2(bv.x, bv.x), b1p = pk2(bv.y, bv.y);
        u64 b2 = pk2(bv.z, bv.z), b3p = pk2(bv.w, bv.w);
        fma2(acc[0][0], a01, b0); fma2(acc[0][1], a01, b1p);
        fma2(acc[0][2], a01, b2); fma2(acc[0][3], a01, b3p);
        fma2(acc[1][0], a23, b0); fma2(acc[1][1], a23, b1p);
        fma2(acc[1][2], a23, b2); fma2(acc[1][3], a23, b3p);
    }

    float fx[4][4];
#pragma unroll
    for (int pp = 0; pp < 2; pp++)
#pragma unroll
        for (int j = 0; j < 4; j++) {
            float2 v = upk2(acc[pp][j]);
            float bb = s_b1[tx * 4 + j];
            fx[2 * pp][j] = lrelu(v.x + bb);
            fx[2 * pp + 1][j] = lrelu(v.y + bb);
        }
#pragma unroll
    for (int i = 0; i < 4; i++) {
        int pt = ty * 4 + i;
#pragma unroll
        for (int j = 0; j < 4; j++) s_fxT[(tx * 4 + j) * 130 + pt] = fx[i][j];
        int p = p0 + pt;
        if (p < N_PTS) {
            float4 o = make_float4(fx[i][0], fx[i][1], fx[i][2], fx[i][3]);
            *(float4*)&g_feats_x[(size_t)p * 32 + tx * 4] = o;
        }
    }
    __syncthreads();

    // ---- stage 2 ----
    u64 acc2[2][4];
#pragma unroll
    for (int i = 0; i < 2; i++)
#pragma unroll
        for (int j = 0; j < 4; j++) acc2[i][j] = 0ull;

#pragma unroll 8
    for (int kk = 0; kk < 32; kk++) {
        const float* ar = &s_fxT[kk * 130 + ty * 4];
        u64 a01 = *(const u64*)(ar);
        u64 a23 = *(const u64*)(ar + 2);
        float4 bv = *(const float4*)&s_wgu[kk * 32 + tx * 4];
        u64 b0 = pk2(bv.x, bv.x), b1p = pk2(bv.y, bv.y);
        u64 b2 = pk2(bv.z, bv.z), b3p = pk2(bv.w, bv.w);
        fma2(acc2[0][0], a01, b0); fma2(acc2[0][1], a01, b1p);
        fma2(acc2[0][2], a01, b2); fma2(acc2[0][3], a01, b3p);
        fma2(acc2[1][0], a23, b0); fma2(acc2[1][1], a23, b1p);
        fma2(acc2[1][2], a23, b2); fma2(acc2[1][3], a23, b3p);
    }
#pragma unroll
    for (int pp = 0; pp < 2; pp++) {
#pragma unroll
        for (int i = 0; i < 2; i++) {
            int pt = ty * 4 + 2 * pp + i;
            int p = p0 + pt;
            if (p < N_PTS) {
                float4 o;
                float2 v0 = upk2(acc2[pp][0]); float2 v1 = upk2(acc2[pp][1]);
                float2 v2 = upk2(acc2[pp][2]); float2 v3 = upk2(acc2[pp][3]);
                o.x = (i ? v0.y : v0.x) + s_bgu[tx * 4 + 0];
                o.y = (i ? v1.y : v1.x) + s_bgu[tx * 4 + 1];
                o.z = (i ? v2.y : v2.x) + s_bgu[tx * 4 + 2];
                o.w = (i ? v3.y : v3.x) + s_bgu[tx * 4 + 3];
                *(float4*)&g_guid_x[(size_t)p * 32 + tx * 4] = o;
            }
        }
    }
}

// =====================================================================
// Kernel B: per sparse point m (warp-per-point, 4 warps/block).
// Round-3 changes: register-hoisted weights, gmax pre-subtract,
// f32x2 for hid-reduction + einsum.
// =====================================================================
__global__ __launch_bounds__(128) void kB(
    const float* __restrict__ df, const float* __restrict__ vi,
    const int* __restrict__ nei,
    const float* __restrict__ wpe, const float* __restrict__ bpe,
    const float* __restrict__ wg1, const float* __restrict__ bg1,
    const float* __restrict__ wg2, const float* __restrict__ bg2,
    const float* __restrict__ wn1, const float* __restrict__ bn1,
    const float* __restrict__ wn2, const float* __restrict__ bn2,
    const float* __restrict__ wn3, const float* __restrict__ bn3) {
    __shared__ float s_wpe[384], s_bpe[32];
    __shared__ float s_wg1p[544], s_bg1[8], s_wg2[64], s_bg2[8];
    __shared__ float s_w1[96], s_b1[8], s_w2[64], s_b2[8], s_w3[128], s_b3[16];
    __shared__ __align__(16) float s_vi[4][192];
    __shared__ __align__(16) float s_gfeat[4][16 * 64];
    __shared__ __align__(16) float s_gf[4][16 * 32];
    __shared__ __align__(16) float s_wn[4][256];
    __shared__ __align__(16) float s_gmax[4][64];
    __shared__ int s_idx[4][16];

    int tid = threadIdx.x;
    for (int i = tid; i < 384; i += 128) s_wpe[i] = wpe[i];
    for (int i = tid; i < 512; i += 128) {
        int c = i >> 3, h2 = i & 7;
        s_wg1p[(c >> 4) * 136 + (c & 15) * 8 + h2] = wg1[i];
    }
    if (tid < 64)  s_wg2[tid] = wg2[tid];
    if (tid < 96)  s_w1[tid] = wn1[tid];
    if (tid < 64)  s_w2[tid] = wn2[tid];
    if (tid < 128) s_w3[tid] = wn3[tid];
    if (tid < 32)  s_bpe[tid] = bpe[tid];
    if (tid < 8) { s_bg1[tid] = bg1[tid]; s_bg2[tid] = bg2[tid];
                   s_b1[tid] = bn1[tid]; s_b2[tid] = bn2[tid]; }
    if (tid < 16) s_b3[tid] = bn3[tid];
    __syncthreads();

    int lane = tid & 31, w = tid >> 5;
    int m = blockIdx.x * 4 + w;
    if (m >= M_PTS) return;

    for (int i = lane; i < 192; i += 32) s_vi[w][i] = vi[m * 192 + i];
    if (lane < 16) s_idx[w][lane] = nei[m * 16 + lane];
    __syncwarp();

    int h = lane & 7;
    int hw = lane & 15;

    // hoisted phase-1 weights
    float wpe_r[12], w1r[12], w2r[8], w3r[8];
#pragma unroll
    for (int j = 0; j < 12; j++) { wpe_r[j] = s_wpe[j * 32 + lane]; w1r[j] = s_w1[j * 8 + h]; }
#pragma unroll
    for (int j = 0; j < 8; j++) { w2r[j] = s_w2[j * 8 + h]; w3r[j] = s_w3[j * 16 + hw]; }
    float bpe_r = s_bpe[lane], b1r = s_b1[h], b2r = s_b2[h], b3r = s_b3[hw];

    float gmax0 = -1e30f, gmax1 = -1e30f, sc0 = -1e30f, sc1 = -1e30f;

    // ---------- Phase 1 ----------
    for (int k = 0; k < 16; k++) {
        int n = s_idx[w][k];
        const float* vk = &s_vi[w][k * 12];

        float gg = g_guid_x[n * 32 + lane];
        float pe = bpe_r;
#pragma unroll
        for (int j = 0; j < 12; j++) pe = fmaf(vk[j], wpe_r[j], pe);
        pe = fmaxf(pe, 0.f);
        s_gfeat[w][k * 64 + lane] = gg;
        s_gfeat[w][k * 64 + 32 + lane] = pe;
        gmax0 = fmaxf(gmax0, gg);
        gmax1 = fmaxf(gmax1, pe);

        s_gf[w][k * 32 + lane] = g_feats_x[n * 32 + lane];
        sc0 = fmaxf(sc0, df[n * 64 + lane]);
        sc1 = fmaxf(sc1, df[n * 64 + 32 + lane]);

        float h1 = b1r;
#pragma unroll
        for (int j = 0; j < 12; j++) h1 = fmaf(vk[j], w1r[j], h1);
        h1 = fmaxf(h1, 0.f);
        float h2 = b2r;
#pragma unroll
        for (int j = 0; j < 8; j++) h2 = fmaf(__shfl_sync(~0u, h1, j), w2r[j], h2);
        h2 = fmaxf(h2, 0.f);
        float wnv = b3r;
#pragma unroll
        for (int j = 0; j < 8; j++) wnv = fmaf(__shfl_sync(~0u, h2, j), w3r[j], wnv);
        wnv = fmaxf(wnv, 0.f);
        if (lane < 16) s_wn[w][k * 16 + lane] = wnv;
    }
    s_gmax[w][lane] = gmax0;
    s_gmax[w][32 + lane] = gmax1;
    __syncwarp();

    // pre-subtract gmax from gfeat (folds the sub out of the inner loop)
#pragma unroll
    for (int i = lane; i < 1024; i += 32) s_gfeat[w][i] -= s_gmax[w][i & 63];
    __syncwarp();

    // ---------- Phase 2 ----------
    int g = lane >> 3;
    u64 wg1p[8];
    const float* wg1g = &s_wg1p[g * 136];
#pragma unroll
    for (int c2 = 0; c2 < 8; c2++)
        wg1p[c2] = pk2(wg1g[(2 * c2) * 8 + h], wg1g[(2 * c2 + 1) * 8 + h]);
    float wg2r[8];
#pragma unroll
    for (int j = 0; j < 8; j++) wg2r[j] = s_wg2[j * 8 + h];
    float bg1r = s_bg1[h], bg2r = s_bg2[h];

    u64 accp[8];
#pragma unroll
    for (int i = 0; i < 8; i++) accp[i] = 0ull;

    for (int k = 0; k < 16; k++) {
        u64 hp = 0ull;
        const u64* gp = (const u64*)&s_gfeat[w][k * 64 + g * 16];
#pragma unroll
        for (int c2 = 0; c2 < 8; c2++) fma2(hp, gp[c2], wg1p[c2]);
        float2 hv = upk2(hp);
        float hid = hv.x + hv.y;
        hid += __shfl_xor_sync(~0u, hid, 8);
        hid += __shfl_xor_sync(~0u, hid, 16);
        hid = fmaxf(hid + bg1r, 0.f);

        float scz = bg2r;
#pragma unroll
        for (int j = 0; j < 8; j++)
            scz = fmaf(__shfl_sync(~0u, hid, j), wg2r[j], scz);
        float score = 1.f / (1.f + __expf(-scz));

        float sC = __shfl_sync(~0u, score, lane >> 2);
        float nf = s_gf[w][k * 32 + lane] * sC;
        u64 nfp = pk2(nf, nf);
        const u64* wp = (const u64*)&s_wn[w][k * 16];
#pragma unroll
        for (int q2 = 0; q2 < 8; q2++) fma2(accp[q2], nfp, wp[q2]);
    }

    size_t base = (size_t)m * 512 + lane * 16;
#pragma unroll
    for (int q2 = 0; q2 < 4; q2++) {
        float2 v0 = upk2(accp[q2 * 2]);
        float2 v1 = upk2(accp[q2 * 2 + 1]);
        float4 v = make_float4(v0.x, v0.y, v1.x, v1.y);
        *(float4*)&g_agg[base + q2 * 4] = v;
    }
    g_maxf[m * 64 + lane] = sc0;
    g_maxf[m * 64 + 32 + lane] = sc1;
}

// =====================================================================
// Kernel C: BM=128, BN=64, BK=16, 256 threads, f32x2 FMAs.
//   main:    o64 = relu(agg[128,512] @ wlin[512,64] + blin)
//   epilog:  out = leaky(o64 @ wu2 + maxf @ wsc + bu2 + bsc)
// Epilogue weights via __ldg (L1-resident), smem = 79KB -> 2 blocks/SM.
// =====================================================================
__global__ __launch_bounds__(256, 2) void kC(
    const float* __restrict__ wlin, const float* __restrict__ blin,
    const float* __restrict__ wu2, const float* __restrict__ bu2,
    const float* __restrict__ wsc, const float* __restrict__ bsc,
    float* __restrict__ out) {
    extern __shared__ float sm[];
    float* AsT = sm;                 // [16][130] transposed A slice
    float* Bs  = AsT + 16 * 130;     // [16][64]
    float* o64 = Bs + 16 * 64;       // [128][65]
    float* mfs = o64 + 128 * 65;     // [128][65]

    int tid = threadIdx.x;
    int m0 = blockIdx.x * 128;

    // A-load mapping: 2 float4 per thread per BK-slice
    int pt0 = tid >> 2,        c40 = (tid & 3) * 4;
    int pt1 = 64 + (tid >> 2), c41 = c40;
    bool v0 = (m0 + pt0) < M_PTS, v1 = (m0 + pt1) < M_PTS;
    const float* a0p = &g_agg[(size_t)(m0 + (v0 ? pt0 : 0)) * 512 + c40];
    const float* a1p = &g_agg[(size_t)(m0 + (v1 ? pt1 : 0)) * 512 + c41];
    // B-load mapping: 1 float4 per thread
    int rb = tid >> 4, cb = (tid & 15) * 4;
    const float* bp = &wlin[rb * 64 + cb];

    int tx = tid & 15;   // 16 ch-groups of 4
    int ty = tid >> 4;   // 16 pt-groups of 8

    u64 accp[4][4];
#pragma unroll
    for (int i = 0; i < 4; i++)
#pragma unroll
        for (int j = 0; j < 4; j++) accp[i][j] = 0ull;

    float4 ra0 = v0 ? *(const float4*)a0p : make_float4(0.f, 0.f, 0.f, 0.f);
    float4 ra1 = v1 ? *(const float4*)a1p : make_float4(0.f, 0.f, 0.f, 0.f);
    float4 rbv = *(const float4*)bp;

    for (int kb = 0; kb < 32; kb++) {
        AsT[(c40 + 0) * 130 + pt0] = ra0.x; AsT[(c40 + 1) * 130 + pt0] = ra0.y;
        AsT[(c40 + 2) * 130 + pt0] = ra0.z; AsT[(c40 + 3) * 130 + pt0] = ra0.w;
        AsT[(c41 + 0) * 130 + pt1] = ra1.x; AsT[(c41 + 1) * 130 + pt1] = ra1.y;
        AsT[(c41 + 2) * 130 + pt1] = ra1.z; AsT[(c41 + 3) * 130 + pt1] = ra1.w;
        *(float4*)&Bs[rb * 64 + cb] = rbv;
        __syncthreads();

        if (kb < 31) {
            ra0 = v0 ? *(const float4*)(a0p + (kb + 1) * 16) : make_float4(0.f, 0.f, 0.f, 0.f);
            ra1 = v1 ? *(const float4*)(a1p + (kb + 1) * 16) : make_float4(0.f, 0.f, 0.f, 0.f);
            rbv = *(const float4*)(bp + (kb + 1) * 16 * 64);
        }

#pragma unroll
        for (int kk = 0; kk < 16; kk++) {
            const float* ar = &AsT[kk * 130 + ty * 8];
            u64 a01 = *(const u64*)(ar);
            u64 a23 = *(const u64*)(ar + 2);
            u64 a45 = *(const u64*)(ar + 4);
            u64 a67 = *(const u64*)(ar + 6);
            float4 bv = *(const float4*)&Bs[kk * 64 + tx * 4];
            u64 b0 = pk2(bv.x, bv.x), b1p = pk2(bv.y, bv.y);
            u64 b2 = pk2(bv.z, bv.z), b3p = pk2(bv.w, bv.w);
            fma2(accp[0][0], a01, b0); fma2(accp[0][1], a01, b1p);
            fma2(accp[0][2], a01, b2); fma2(accp[0][3], a01, b3p);
            fma2(accp[1][0], a23, b0); fma2(accp[1][1], a23, b1p);
            fma2(accp[1][2], a23, b2); fma2(accp[1][3], a23, b3p);
            fma2(accp[2][0], a45, b0); fma2(accp[2][1], a45, b1p);
            fma2(accp[2][2], a45, b2); fma2(accp[2][3], a45, b3p);
            fma2(accp[3][0], a67, b0); fma2(accp[3][1], a67, b1p);
            fma2(accp[3][2], a67, b2); fma2(accp[3][3], a67, b3p);
        }
        __syncthreads();
    }

    // bias + relu -> o64 smem
    {
        float blr[4];
#pragma unroll
        for (int j = 0; j < 4; j++) blr[j] = __ldg(&blin[tx * 4 + j]);
#pragma unroll
        for (int ip = 0; ip < 4; ip++)
#pragma unroll
            for (int j = 0; j < 4; j++) {
                float2 v = upk2(accp[ip][j]);
                o64[(ty * 8 + 2 * ip) * 65 + tx * 4 + j] = fmaxf(v.x + blr[j], 0.f);
                o64[(ty * 8 + 2 * ip + 1) * 65 + tx * 4 + j] = fmaxf(v.y + blr[j], 0.f);
            }
    }

    // load maxf tile
#pragma unroll
    for (int q = 0; q < 8; q++) {
        int f4 = tid + q * 256;
        int pt = f4 >> 4, c4 = (f4 & 15) * 4;
        int mm = m0 + pt;
        float4 v = (mm < M_PTS) ? *(const float4*)&g_maxf[(size_t)mm * 64 + c4]
                                : make_float4(0.f, 0.f, 0.f, 0.f);
        mfs[pt * 65 + c4 + 0] = v.x; mfs[pt * 65 + c4 + 1] = v.y;
        mfs[pt * 65 + c4 + 2] = v.z; mfs[pt * 65 + c4 + 3] = v.w;
    }
    __syncthreads();

    // epilogue: [128,64]@[64,128] (u2) + [128,64]@[64,128] (sc), shared acc
    int o0 = (tid & 15) * 8;
    int mpt = (tid >> 4) * 8;
    u64 acc2[8][4];
#pragma unroll
    for (int i = 0; i < 8; i++)
#pragma unroll
        for (int c = 0; c < 4; c++) acc2[i][c] = 0ull;

    for (int j = 0; j < 64; j++) {
        const u64* pu = (const u64*)&wu2[j * 128 + o0];
        const u64* ps = (const u64*)&wsc[j * 128 + o0];
        u64 u0 = __ldg(pu), u1 = __ldg(pu + 1), u2v = __ldg(pu + 2), u3 = __ldg(pu + 3);
        u64 s0 = __ldg(ps), s1 = __ldg(ps + 1), s2v = __ldg(ps + 2), s3 = __ldg(ps + 3);
#pragma unroll
        for (int i = 0; i < 8; i++) {
            float a = o64[(mpt + i) * 65 + j];
            float c = mfs[(mpt + i) * 65 + j];
            u64 ap = pk2(a, a), cp = pk2(c, c);
            fma2(acc2[i][0], ap, u0); fma2(acc2[i][0], cp, s0);
            fma2(acc2[i][1], ap, u1); fma2(acc2[i][1], cp, s1);
            fma2(acc2[i][2], ap, u2v); fma2(acc2[i][2], cp, s2v);
            fma2(acc2[i][3], ap, u3); fma2(acc2[i][3], cp, s3);
        }
    }

    float bb[8];
#pragma unroll
    for (int q = 0; q < 8; q++) bb[q] = __ldg(&bu2[o0 + q]) + __ldg(&bsc[o0 + q]);
#pragma unroll
    for (int i = 0; i < 8; i++) {
        int m = m0 + mpt + i;
        if (m < M_PTS) {
            float4 oA, oB;
            float2 v0 = upk2(acc2[i][0]); float2 v1 = upk2(acc2[i][1]);
            float2 v2 = upk2(acc2[i][2]); float2 v3 = upk2(acc2[i][3]);
            oA.x = lrelu(v0.x + bb[0]); oA.y = lrelu(v0.y + bb[1]);
            oA.z = lrelu(v1.x + bb[2]); oA.w = lrelu(v1.y + bb[3]);
            oB.x = lrelu(v2.x + bb[4]); oB.y = lrelu(v2.y + bb[5]);
            oB.z = lrelu(v3.x + bb[6]); oB.w = lrelu(v3.y + bb[7]);
            *(float4*)&out[(size_t)m * 128 + o0] = oA;
            *(float4*)&out[(size_t)m * 128 + o0 + 4] = oB;
        }
    }
}

// =====================================================================
extern "C" void kernel_launch(void* const* d_in, const int* in_sizes, int n_in,
                              void* d_out, int out_size) {
    const float* dense_feats = (const float*)d_in[1];
    const float* vi          = (const float*)d_in[5];
    const int*   nei         = (const int*)d_in[6];
    const float* w_u1  = (const float*)d_in[7];  const float* b_u1  = (const float*)d_in[8];
    const float* w_gu  = (const float*)d_in[9];  const float* b_gu  = (const float*)d_in[10];
    const float* w_pe  = (const float*)d_in[11]; const float* b_pe  = (const float*)d_in[12];
    const float* w_g1  = (const float*)d_in[13]; const float* b_g1  = (const float*)d_in[14];
    const float* w_g2  = (const float*)d_in[15]; const float* b_g2  = (const float*)d_in[16];
    const float* w_wn1 = (const float*)d_in[17]; const float* b_wn1 = (const float*)d_in[18];
    const float* w_wn2 = (const float*)d_in[19]; const float* b_wn2 = (const float*)d_in[20];
    const float* w_wn3 = (const float*)d_in[21]; const float* b_wn3 = (const float*)d_in[22];
    const float* w_lin = (const float*)d_in[23]; const float* b_lin = (const float*)d_in[24];
    const float* w_u2  = (const float*)d_in[25]; const float* b_u2  = (const float*)d_in[26];
    const float* w_sc  = (const float*)d_in[27]; const float* b_sc  = (const float*)d_in[28];
    float* out = (float*)d_out;

    int smemA = (64 * 130 + 64 * 32 + 32 * 32 + 32 * 130) * 4;   // 62208 B
    cudaFuncSetAttribute(kA, cudaFuncAttributeMaxDynamicSharedMemorySize, smemA);
    kA<<<(N_PTS + 127) / 128, 256, smemA>>>(dense_feats, w_u1, b_u1, w_gu, b_gu);

    kB<<<(M_PTS + 3) / 4, 128>>>(dense_feats, vi, nei,
                                 w_pe, b_pe, w_g1, b_g1, w_g2, b_g2,
                                 w_wn1, b_wn1, w_wn2, b_wn2, w_wn3, b_wn3);

    int smemC = (16 * 130 + 16 * 64 + 128 * 65 + 128 * 65) * 4;  // 78976 B
    cudaFuncSetAttribute(kC, cudaFuncAttributeMaxDynamicSharedMemorySize, smemC);
    kC<<<(M_PTS + 127) / 128, 256, smemC>>>(w_lin, b_lin, w_u2, b_u2, w_sc, b_sc, out);
}

// round 6
// speedup vs baseline: 1.3914x; 1.0343x over previous
#include <cuda_runtime.h>
#include <cstdint>

#define N_PTS 200000
#define M_PTS 100000
#define R_ROWS (M_PTS * 16)

typedef unsigned long long u64;

// ---- scratch (device-global, no allocation) ----
__device__ float g_feats_x[N_PTS * 32];            // 25.6 MB
__device__ float g_guid_x[N_PTS * 32];             // 25.6 MB
__device__ float g_agg[(size_t)M_PTS * 512];       // 204.8 MB
__device__ float g_maxf[M_PTS * 64];               // 25.6 MB
__device__ float g_pe[(size_t)R_ROWS * 32];        // 204.8 MB
__device__ float g_w[(size_t)R_ROWS * 16];         // 102.4 MB

// ---- packed fp32x2 helpers ----
__device__ __forceinline__ u64 pk2(float x, float y) {
    u64 r; asm("mov.b64 %0,{%1,%2};" : "=l"(r) : "f"(x), "f"(y)); return r;
}
__device__ __forceinline__ float2 upk2(u64 v) {
    float2 r; asm("mov.b64 {%0,%1},%2;" : "=f"(r.x), "=f"(r.y) : "l"(v)); return r;
}
__device__ __forceinline__ void fma2(u64& d, u64 a, u64 b) {
    asm("fma.rn.f32x2 %0,%1,%2,%3;" : "=l"(d) : "l"(a), "l"(b), "l"(d));
}
__device__ __forceinline__ float lrelu(float x) { return x > 0.f ? x : 0.1f * x; }

// =====================================================================
// Kernel A: tiled GEMM, 128 points/block, 256 threads. (unchanged R3)
// =====================================================================
__global__ __launch_bounds__(256) void kA(const float* __restrict__ df,
                                          const float* __restrict__ w1,
                                          const float* __restrict__ b1,
                                          const float* __restrict__ wgu,
                                          const float* __restrict__ bgu) {
    extern __shared__ float sm[];
    float* s_dfT = sm;                 // [64][130]
    float* s_w1  = s_dfT + 64 * 130;   // [64][32]
    float* s_wgu = s_w1 + 2048;        // [32][32]
    float* s_fxT = s_wgu + 1024;       // [32][130]
    __shared__ float s_b1[32], s_bgu[32];

    int tid = threadIdx.x;
    int p0 = blockIdx.x * 128;

    for (int i = tid; i < 2048; i += 256) s_w1[i] = w1[i];
    for (int i = tid; i < 1024; i += 256) s_wgu[i] = wgu[i];
    if (tid < 32) { s_b1[tid] = b1[tid]; s_bgu[tid] = bgu[tid]; }

#pragma unroll
    for (int q = 0; q < 8; q++) {
        int f4 = tid + q * 256;
        int pt = f4 >> 4, c4 = (f4 & 15) * 4;
        int p = p0 + pt;
        float4 v = (p < N_PTS) ? *(const float4*)&df[(size_t)p * 64 + c4]
                               : make_float4(0.f, 0.f, 0.f, 0.f);
        s_dfT[(c4 + 0) * 130 + pt] = v.x;
        s_dfT[(c4 + 1) * 130 + pt] = v.y;
        s_dfT[(c4 + 2) * 130 + pt] = v.z;
        s_dfT[(c4 + 3) * 130 + pt] = v.w;
    }
    __syncthreads();

    int tx = tid & 7;
    int ty = tid >> 3;

    u64 acc[2][4];
#pragma unroll
    for (int i = 0; i < 2; i++)
#pragma unroll
        for (int j = 0; j < 4; j++) acc[i][j] = 0ull;

#pragma unroll 8
    for (int kk = 0; kk < 64; kk++) {
        const float* ar = &s_dfT[kk * 130 + ty * 4];
        u64 a01 = *(const u64*)(ar);
        u64 a23 = *(const u64*)(ar + 2);
        float4 bv = *(const float4*)&s_w1[kk * 32 + tx * 4];
        u64 b0 = pk2(bv.x, bv.x), b1p = pk2(bv.y, bv.y);
        u64 b2 = pk2(bv.z, bv.z), b3p = pk2(bv.w, bv.w);
        fma2(acc[0][0], a01, b0); fma2(acc[0][1], a01, b1p);
        fma2(acc[0][2], a01, b2); fma2(acc[0][3], a01, b3p);
        fma2(acc[1][0], a23, b0); fma2(acc[1][1], a23, b1p);
        fma2(acc[1][2], a23, b2); fma2(acc[1][3], a23, b3p);
    }

    float fx[4][4];
#pragma unroll
    for (int pp = 0; pp < 2; pp++)
#pragma unroll
        for (int j = 0; j < 4; j++) {
            float2 v = upk2(acc[pp][j]);
            float bb = s_b1[tx * 4 + j];
            fx[2 * pp][j] = lrelu(v.x + bb);
            fx[2 * pp + 1][j] = lrelu(v.y + bb);
        }
#pragma unroll
    for (int i = 0; i < 4; i++) {
        int pt = ty * 4 + i;
#pragma unroll
        for (int j = 0; j < 4; j++) s_fxT[(tx * 4 + j) * 130 + pt] = fx[i][j];
        int p = p0 + pt;
        if (p < N_PTS) {
            float4 o = make_float4(fx[i][0], fx[i][1], fx[i][2], fx[i][3]);
            *(float4*)&g_feats_x[(size_t)p * 32 + tx * 4] = o;
        }
    }
    __syncthreads();

    u64 acc2[2][4];
#pragma unroll
    for (int i = 0; i < 2; i++)
#pragma unroll
        for (int j = 0; j < 4; j++) acc2[i][j] = 0ull;

#pragma unroll 8
    for (int kk = 0; kk < 32; kk++) {
        const float* ar = &s_fxT[kk * 130 + ty * 4];
        u64 a01 = *(const u64*)(ar);
        u64 a23 = *(const u64*)(ar + 2);
        float4 bv = *(const float4*)&s_wgu[kk * 32 + tx * 4];
        u64 b0 = pk2(bv.x, bv.x), b1p = pk2(bv.y, bv.y);
        u64 b2 = pk2(bv.z, bv.z), b3p = pk2(bv.w, bv.w);
        fma2(acc2[0][0], a01, b0); fma2(acc2[0][1], a01, b1p);
        fma2(acc2[0][2], a01, b2); fma2(acc2[0][3], a01, b3p);
        fma2(acc2[1][0], a23, b0); fma2(acc2[1][1], a23, b1p);
        fma2(acc2[1][2], a23, b2); fma2(acc2[1][3], a23, b3p);
    }
#pragma unroll
    for (int pp = 0; pp < 2; pp++) {
#pragma unroll
        for (int i = 0; i < 2; i++) {
            int pt = ty * 4 + 2 * pp + i;
            int p = p0 + pt;
            if (p < N_PTS) {
                float4 o;
                float2 v0 = upk2(acc2[pp][0]); float2 v1 = upk2(acc2[pp][1]);
                float2 v2 = upk2(acc2[pp][2]); float2 v3 = upk2(acc2[pp][3]);
                o.x = (i ? v0.y : v0.x) + s_bgu[tx * 4 + 0];
                o.y = (i ? v1.y : v1.x) + s_bgu[tx * 4 + 1];
                o.z = (i ? v2.y : v2.x) + s_bgu[tx * 4 + 2];
                o.w = (i ? v3.y : v3.x) + s_bgu[tx * 4 + 3];
                *(float4*)&g_guid_x[(size_t)p * 32 + tx * 4] = o;
            }
        }
    }
}

// =====================================================================
// Kernel W (NEW): gatherless per-row MLPs over R = M*K = 1.6M rows.
//   pe  = relu(vi @ wpe + bpe)            [R,32] -> g_pe
//   w16 = relu-chain(vi; 12->8->8->16)    [R,16] -> g_w
// One row per thread, weights as broadcast LDS.64 pairs, f32x2 math.
// =====================================================================
__global__ __launch_bounds__(256) void kW(
    const float* __restrict__ vi,
    const float* __restrict__ wpe, const float* __restrict__ bpe,
    const float* __restrict__ wn1, const float* __restrict__ bn1,
    const float* __restrict__ wn2, const float* __restrict__ bn2,
    const float* __restrict__ wn3, const float* __restrict__ bn3) {
    __shared__ __align__(16) float s_wpe[384];
    __shared__ __align__(16) float s_w1[96];
    __shared__ __align__(16) float s_w2[64];
    __shared__ __align__(16) float s_w3[128];
    __shared__ __align__(16) float s_bpe[32];
    __shared__ __align__(16) float s_b1[8], s_b2[8];
    __shared__ __align__(16) float s_b3[16];

    int tid = threadIdx.x;
    for (int i = tid; i < 384; i += 256) s_wpe[i] = wpe[i];
    if (tid < 96)  s_w1[tid] = wn1[tid];
    if (tid < 64)  s_w2[tid] = wn2[tid];
    if (tid < 128) s_w3[tid] = wn3[tid];
    if (tid < 32)  s_bpe[tid] = bpe[tid];
    if (tid < 8) { s_b1[tid] = bn1[tid]; s_b2[tid] = bn2[tid]; }
    if (tid < 16) s_b3[tid] = bn3[tid];
    __syncthreads();

    size_t r = (size_t)blockIdx.x * 256 + tid;
    if (r >= R_ROWS) return;

    const float4* v4 = (const float4*)(vi + r * 12);
    float4 va = v4[0], vb = v4[1], vc = v4[2];
    float vr[12] = {va.x, va.y, va.z, va.w, vb.x, vb.y, vb.z, vb.w,
                    vc.x, vc.y, vc.z, vc.w};
    u64 vp[12];
#pragma unroll
    for (int j = 0; j < 12; j++) vp[j] = pk2(vr[j], vr[j]);

    // ---- PE: 12 -> 32, relu; compute+store in float4 chunks ----
    float* peo = &g_pe[r * 32];
#pragma unroll
    for (int c4 = 0; c4 < 8; c4++) {
        u64 a0 = *(const u64*)&s_bpe[c4 * 4];
        u64 a1 = *(const u64*)&s_bpe[c4 * 4 + 2];
#pragma unroll
        for (int j = 0; j < 12; j++) {
            fma2(a0, vp[j], *(const u64*)&s_wpe[j * 32 + c4 * 4]);
            fma2(a1, vp[j], *(const u64*)&s_wpe[j * 32 + c4 * 4 + 2]);
        }
        float2 p0 = upk2(a0), p1 = upk2(a1);
        float4 o = make_float4(fmaxf(p0.x, 0.f), fmaxf(p0.y, 0.f),
                               fmaxf(p1.x, 0.f), fmaxf(p1.y, 0.f));
        *(float4*)&peo[c4 * 4] = o;
    }

    // ---- WeightNet: 12 -> 8 -> 8 -> 16, relu each ----
    u64 h1p[8];
#pragma unroll
    for (int c2 = 0; c2 < 4; c2++) {
        u64 a = *(const u64*)&s_b1[c2 * 2];
#pragma unroll
        for (int j = 0; j < 12; j++)
            fma2(a, vp[j], *(const u64*)&s_w1[j * 8 + c2 * 2]);
        float2 v = upk2(a);
        float x = fmaxf(v.x, 0.f), y = fmaxf(v.y, 0.f);
        h1p[2 * c2] = pk2(x, x); h1p[2 * c2 + 1] = pk2(y, y);
    }
    u64 h2p[8];
#pragma unroll
    for (int c2 = 0; c2 < 4; c2++) {
        u64 a = *(const u64*)&s_b2[c2 * 2];
#pragma unroll
        for (int j = 0; j < 8; j++)
            fma2(a, h1p[j], *(const u64*)&s_w2[j * 8 + c2 * 2]);
        float2 v = upk2(a);
        float x = fmaxf(v.x, 0.f), y = fmaxf(v.y, 0.f);
        h2p[2 * c2] = pk2(x, x); h2p[2 * c2 + 1] = pk2(y, y);
    }
    float* wo = &g_w[r * 16];
#pragma unroll
    for (int c4 = 0; c4 < 4; c4++) {
        u64 a0 = *(const u64*)&s_b3[c4 * 4];
        u64 a1 = *(const u64*)&s_b3[c4 * 4 + 2];
#pragma unroll
        for (int j = 0; j < 8; j++) {
            fma2(a0, h2p[j], *(const u64*)&s_w3[j * 16 + c4 * 4]);
            fma2(a1, h2p[j], *(const u64*)&s_w3[j * 16 + c4 * 4 + 2]);
        }
        float2 p0 = upk2(a0), p1 = upk2(a1);
        float4 o = make_float4(fmaxf(p0.x, 0.f), fmaxf(p0.y, 0.f),
                               fmaxf(p1.x, 0.f), fmaxf(p1.y, 0.f));
        *(float4*)&wo[c4 * 4] = o;
    }
}

// =====================================================================
// Kernel B (slimmed): per sparse point m (warp-per-point, 4 warps/block).
// Phase 1 = pure gathers + maxes (PE/WeightNet precomputed by kW).
// Phase 2 = guidance scores + weighted einsum (unchanged R3).
// =====================================================================
__global__ __launch_bounds__(128) void kB(
    const float* __restrict__ df, const int* __restrict__ nei,
    const float* __restrict__ wg1, const float* __restrict__ bg1,
    const float* __restrict__ wg2, const float* __restrict__ bg2) {
    __shared__ float s_wg1p[544], s_bg1[8], s_wg2[64], s_bg2[8];
    __shared__ __align__(16) float s_gfeat[4][1024];
    __shared__ __align__(16) float s_gf[4][512];
    __shared__ __align__(16) float s_wn[4][256];
    __shared__ __align__(16) float s_gmax[4][64];
    __shared__ int s_idx[4][16];

    int tid = threadIdx.x;
    for (int i = tid; i < 512; i += 128) {
        int c = i >> 3, h2 = i & 7;
        s_wg1p[(c >> 4) * 136 + (c & 15) * 8 + h2] = wg1[i];
    }
    if (tid < 64) s_wg2[tid] = wg2[tid];
    if (tid < 8) { s_bg1[tid] = bg1[tid]; s_bg2[tid] = bg2[tid]; }
    __syncthreads();

    int lane = tid & 31, w = tid >> 5;
    int m = blockIdx.x * 4 + w;
    if (m >= M_PTS) return;

    if (lane < 16) s_idx[w][lane] = nei[m * 16 + lane];
    __syncwarp();

    float gmax0 = -1e30f, gmax1 = -1e30f, sc0 = -1e30f, sc1 = -1e30f;
    const float* pebase = &g_pe[(size_t)m * 512 + lane];
    const float* wbase  = &g_w[(size_t)m * 256 + lane];

    // ---------- Phase 1: gathers + streamed pe/w + maxes ----------
#pragma unroll 4
    for (int k = 0; k < 16; k++) {
        int n = s_idx[w][k];
        float gg = g_guid_x[n * 32 + lane];
        float pe = pebase[k * 32];
        float gf = g_feats_x[n * 32 + lane];
        float d0 = df[n * 64 + lane];
        float d1 = df[n * 64 + 32 + lane];
        if ((k & 1) == 0) s_wn[w][k * 16 + lane] = wbase[k * 16];
        s_gfeat[w][k * 64 + lane] = gg;
        s_gfeat[w][k * 64 + 32 + lane] = pe;
        s_gf[w][k * 32 + lane] = gf;
        gmax0 = fmaxf(gmax0, gg);
        gmax1 = fmaxf(gmax1, pe);
        sc0 = fmaxf(sc0, d0);
        sc1 = fmaxf(sc1, d1);
    }
    s_gmax[w][lane] = gmax0;
    s_gmax[w][32 + lane] = gmax1;
    __syncwarp();

    // pre-subtract gmax from gfeat
#pragma unroll
    for (int i = lane; i < 1024; i += 32) s_gfeat[w][i] -= s_gmax[w][i & 63];
    __syncwarp();

    // ---------- Phase 2 ----------
    int h = lane & 7;
    int g = lane >> 3;
    u64 wg1p[8];
    const float* wg1g = &s_wg1p[g * 136];
#pragma unroll
    for (int c2 = 0; c2 < 8; c2++)
        wg1p[c2] = pk2(wg1g[(2 * c2) * 8 + h], wg1g[(2 * c2 + 1) * 8 + h]);
    float wg2r[8];
#pragma unroll
    for (int j = 0; j < 8; j++) wg2r[j] = s_wg2[j * 8 + h];
    float bg1r = s_bg1[h], bg2r = s_bg2[h];

    u64 accp[8];
#pragma unroll
    for (int i = 0; i < 8; i++) accp[i] = 0ull;

    for (int k = 0; k < 16; k++) {
        u64 hp = 0ull;
        const u64* gp = (const u64*)&s_gfeat[w][k * 64 + g * 16];
#pragma unroll
        for (int c2 = 0; c2 < 8; c2++) fma2(hp, gp[c2], wg1p[c2]);
        float2 hv = upk2(hp);
        float hid = hv.x + hv.y;
        hid += __shfl_xor_sync(~0u, hid, 8);
        hid += __shfl_xor_sync(~0u, hid, 16);
        hid = fmaxf(hid + bg1r, 0.f);

        float scz = bg2r;
#pragma unroll
        for (int j = 0; j < 8; j++)
            scz = fmaf(__shfl_sync(~0u, hid, j), wg2r[j], scz);
        float score = 1.f / (1.f + __expf(-scz));

        float sC = __shfl_sync(~0u, score, lane >> 2);
        float nf = s_gf[w][k * 32 + lane] * sC;
        u64 nfp = pk2(nf, nf);
        const u64* wp = (const u64*)&s_wn[w][k * 16];
#pragma unroll
        for (int q2 = 0; q2 < 8; q2++) fma2(accp[q2], nfp, wp[q2]);
    }

    size_t base = (size_t)m * 512 + lane * 16;
#pragma unroll
    for (int q2 = 0; q2 < 4; q2++) {
        float2 v0 = upk2(accp[q2 * 2]);
        float2 v1 = upk2(accp[q2 * 2 + 1]);
        float4 v = make_float4(v0.x, v0.y, v1.x, v1.y);
        *(float4*)&g_agg[base + q2 * 4] = v;
    }
    g_maxf[m * 64 + lane] = sc0;
    g_maxf[m * 64 + 32 + lane] = sc1;
}

// =====================================================================
// Kernel C: BM=128, BN=64, BK=16, 256 threads, f32x2 FMAs. (unchanged R3)
// =====================================================================
__global__ __launch_bounds__(256, 2) void kC(
    const float* __restrict__ wlin, const float* __restrict__ blin,
    const float* __restrict__ wu2, const float* __restrict__ bu2,
    const float* __restrict__ wsc, const float* __restrict__ bsc,
    float* __restrict__ out) {
    extern __shared__ float sm[];
    float* AsT = sm;                 // [16][130]
    float* Bs  = AsT + 16 * 130;     // [16][64]
    float* o64 = Bs + 16 * 64;       // [128][65]
    float* mfs = o64 + 128 * 65;     // [128][65]

    int tid = threadIdx.x;
    int m0 = blockIdx.x * 128;

    int pt0 = tid >> 2,        c40 = (tid & 3) * 4;
    int pt1 = 64 + (tid >> 2), c41 = c40;
    bool v0 = (m0 + pt0) < M_PTS, v1 = (m0 + pt1) < M_PTS;
    const float* a0p = &g_agg[(size_t)(m0 + (v0 ? pt0 : 0)) * 512 + c40];
    const float* a1p = &g_agg[(size_t)(m0 + (v1 ? pt1 : 0)) * 512 + c41];
    int rb = tid >> 4, cb = (tid & 15) * 4;
    const float* bp = &wlin[rb * 64 + cb];

    int tx = tid & 15;
    int ty = tid >> 4;

    u64 accp[4][4];
#pragma unroll
    for (int i = 0; i < 4; i++)
#pragma unroll
        for (int j = 0; j < 4; j++) accp[i][j] = 0ull;

    float4 ra0 = v0 ? *(const float4*)a0p : make_float4(0.f, 0.f, 0.f, 0.f);
    float4 ra1 = v1 ? *(const float4*)a1p : make_float4(0.f, 0.f, 0.f, 0.f);
    float4 rbv = *(const float4*)bp;

    for (int kb = 0; kb < 32; kb++) {
        AsT[(c40 + 0) * 130 + pt0] = ra0.x; AsT[(c40 + 1) * 130 + pt0] = ra0.y;
        AsT[(c40 + 2) * 130 + pt0] = ra0.z; AsT[(c40 + 3) * 130 + pt0] = ra0.w;
        AsT[(c41 + 0) * 130 + pt1] = ra1.x; AsT[(c41 + 1) * 130 + pt1] = ra1.y;
        AsT[(c41 + 2) * 130 + pt1] = ra1.z; AsT[(c41 + 3) * 130 + pt1] = ra1.w;
        *(float4*)&Bs[rb * 64 + cb] = rbv;
        __syncthreads();

        if (kb < 31) {
            ra0 = v0 ? *(const float4*)(a0p + (kb + 1) * 16) : make_float4(0.f, 0.f, 0.f, 0.f);
            ra1 = v1 ? *(const float4*)(a1p + (kb + 1) * 16) : make_float4(0.f, 0.f, 0.f, 0.f);
            rbv = *(const float4*)(bp + (kb + 1) * 16 * 64);
        }

#pragma unroll
        for (int kk = 0; kk < 16; kk++) {
            const float* ar = &AsT[kk * 130 + ty * 8];
            u64 a01 = *(const u64*)(ar);
            u64 a23 = *(const u64*)(ar + 2);
            u64 a45 = *(const u64*)(ar + 4);
            u64 a67 = *(const u64*)(ar + 6);
            float4 bv = *(const float4*)&Bs[kk * 64 + tx * 4];
            u64 b0 = pk2(bv.x, bv.x), b1p = pk2(bv.y, bv.y);
            u64 b2 = pk2(bv.z, bv.z), b3p = pk2(bv.w, bv.w);
            fma2(accp[0][0], a01, b0); fma2(accp[0][1], a01, b1p);
            fma2(accp[0][2], a01, b2); fma2(accp[0][3], a01, b3p);
            fma2(accp[1][0], a23, b0); fma2(accp[1][1], a23, b1p);
            fma2(accp[1][2], a23, b2); fma2(accp[1][3], a23, b3p);
            fma2(accp[2][0], a45, b0); fma2(accp[2][1], a45, b1p);
            fma2(accp[2][2], a45, b2); fma2(accp[2][3], a45, b3p);
            fma2(accp[3][0], a67, b0); fma2(accp[3][1], a67, b1p);
            fma2(accp[3][2], a67, b2); fma2(accp[3][3], a67, b3p);
        }
        __syncthreads();
    }

    {
        float blr[4];
#pragma unroll
        for (int j = 0; j < 4; j++) blr[j] = __ldg(&blin[tx * 4 + j]);
#pragma unroll
        for (int ip = 0; ip < 4; ip++)
#pragma unroll
            for (int j = 0; j < 4; j++) {
                float2 v = upk2(accp[ip][j]);
                o64[(ty * 8 + 2 * ip) * 65 + tx * 4 + j] = fmaxf(v.x + blr[j], 0.f);
                o64[(ty * 8 + 2 * ip + 1) * 65 + tx * 4 + j] = fmaxf(v.y + blr[j], 0.f);
            }
    }

#pragma unroll
    for (int q = 0; q < 8; q++) {
        int f4 = tid + q * 256;
        int pt = f4 >> 4, c4 = (f4 & 15) * 4;
        int mm = m0 + pt;
        float4 v = (mm < M_PTS) ? *(const float4*)&g_maxf[(size_t)mm * 64 + c4]
                                : make_float4(0.f, 0.f, 0.f, 0.f);
        mfs[pt * 65 + c4 + 0] = v.x; mfs[pt * 65 + c4 + 1] = v.y;
        mfs[pt * 65 + c4 + 2] = v.z; mfs[pt * 65 + c4 + 3] = v.w;
    }
    __syncthreads();

    int o0 = (tid & 15) * 8;
    int mpt = (tid >> 4) * 8;
    u64 acc2[8][4];
#pragma unroll
    for (int i = 0; i < 8; i++)
#pragma unroll
        for (int c = 0; c < 4; c++) acc2[i][c] = 0ull;

    for (int j = 0; j < 64; j++) {
        const u64* pu = (const u64*)&wu2[j * 128 + o0];
        const u64* ps = (const u64*)&wsc[j * 128 + o0];
        u64 u0 = __ldg(pu), u1 = __ldg(pu + 1), u2v = __ldg(pu + 2), u3 = __ldg(pu + 3);
        u64 s0 = __ldg(ps), s1 = __ldg(ps + 1), s2v = __ldg(ps + 2), s3 = __ldg(ps + 3);
#pragma unroll
        for (int i = 0; i < 8; i++) {
            float a = o64[(mpt + i) * 65 + j];
            float c = mfs[(mpt + i) * 65 + j];
            u64 ap = pk2(a, a), cp = pk2(c, c);
            fma2(acc2[i][0], ap, u0); fma2(acc2[i][0], cp, s0);
            fma2(acc2[i][1], ap, u1); fma2(acc2[i][1], cp, s1);
            fma2(acc2[i][2], ap, u2v); fma2(acc2[i][2], cp, s2v);
            fma2(acc2[i][3], ap, u3); fma2(acc2[i][3], cp, s3);
        }
    }

    float bb[8];
#pragma unroll
    for (int q = 0; q < 8; q++) bb[q] = __ldg(&bu2[o0 + q]) + __ldg(&bsc[o0 + q]);
#pragma unroll
    for (int i = 0; i < 8; i++) {
        int m = m0 + mpt + i;
        if (m < M_PTS) {
            float4 oA, oB;
            float2 v0 = upk2(acc2[i][0]); float2 v1 = upk2(acc2[i][1]);
            float2 v2 = upk2(acc2[i][2]); float2 v3 = upk2(acc2[i][3]);
            oA.x = lrelu(v0.x + bb[0]); oA.y = lrelu(v0.y + bb[1]);
            oA.z = lrelu(v1.x + bb[2]); oA.w = lrelu(v1.y + bb[3]);
            oB.x = lrelu(v2.x + bb[4]); oB.y = lrelu(v2.y + bb[5]);
            oB.z = lrelu(v3.x + bb[6]); oB.w = lrelu(v3.y + bb[7]);
            *(float4*)&out[(size_t)m * 128 + o0] = oA;
            *(float4*)&out[(size_t)m * 128 + o0 + 4] = oB;
        }
    }
}

// =====================================================================
extern "C" void kernel_launch(void* const* d_in, const int* in_sizes, int n_in,
                              void* d_out, int out_size) {
    const float* dense_feats = (const float*)d_in[1];
    const float* vi          = (const float*)d_in[5];
    const int*   nei         = (const int*)d_in[6];
    const float* w_u1  = (const float*)d_in[7];  const float* b_u1  = (const float*)d_in[8];
    const float* w_gu  = (const float*)d_in[9];  const float* b_gu  = (const float*)d_in[10];
    const float* w_pe  = (const float*)d_in[11]; const float* b_pe  = (const float*)d_in[12];
    const float* w_g1  = (const float*)d_in[13]; const float* b_g1  = (const float*)d_in[14];
    const float* w_g2  = (const float*)d_in[15]; const float* b_g2  = (const float*)d_in[16];
    const float* w_wn1 = (const float*)d_in[17]; const float* b_wn1 = (const float*)d_in[18];
    const float* w_wn2 = (const float*)d_in[19]; const float* b_wn2 = (const float*)d_in[20];
    const float* w_wn3 = (const float*)d_in[21]; const float* b_wn3 = (const float*)d_in[22];
    const float* w_lin = (const float*)d_in[23]; const float* b_lin = (const float*)d_in[24];
    const float* w_u2  = (const float*)d_in[25]; const float* b_u2  = (const float*)d_in[26];
    const float* w_sc  = (const float*)d_in[27]; const float* b_sc  = (const float*)d_in[28];
    float* out = (float*)d_out;

    int smemA = (64 * 130 + 64 * 32 + 32 * 32 + 32 * 130) * 4;   // 62208 B
    cudaFuncSetAttribute(kA, cudaFuncAttributeMaxDynamicSharedMemorySize, smemA);
    kA<<<(N_PTS + 127) / 128, 256, smemA>>>(dense_feats, w_u1, b_u1, w_gu, b_gu);

    kW<<<(R_ROWS + 255) / 256, 256>>>(vi, w_pe, b_pe,
                                      w_wn1, b_wn1, w_wn2, b_wn2, w_wn3, b_wn3);

    kB<<<(M_PTS + 3) / 4, 128>>>(dense_feats, nei, w_g1, b_g1, w_g2, b_g2);

    int smemC = (16 * 130 + 16 * 64 + 128 * 65 + 128 * 65) * 4;  // 78976 B
    cudaFuncSetAttribute(kC, cudaFuncAttributeMaxDynamicSharedMemorySize, smemC);
    kC<<<(M_PTS + 127) / 128, 256, smemC>>>(w_lin, b_lin, w_u2, b_u2, w_sc, b_sc, out);
}

// round 9
// speedup vs baseline: 1.4129x; 1.0155x over previous
#include <cuda_runtime.h>
#include <cuda_fp16.h>
#include <cstdint>

#define N_PTS 200000
#define M_PTS 100000

typedef unsigned long long u64;

// ---- scratch (device-global, no allocation) ----
__device__ __half g_fx_h[N_PTS * 32];                // 12.8 MB
__device__ __half g_gx_h[N_PTS * 32];                // 12.8 MB
__device__ __half g_df_h[(size_t)N_PTS * 64];        // 25.6 MB
__device__ __half g_agg_h[(size_t)M_PTS * 512];      // 102.4 MB
__device__ float  g_maxf[M_PTS * 64];                // 25.6 MB

struct __align__(16) H8 { __half2 a, b, c, d; };

// ---- packed fp32x2 helpers ----
__device__ __forceinline__ u64 pk2(float x, float y) {
    u64 r; asm("mov.b64 %0,{%1,%2};" : "=l"(r) : "f"(x), "f"(y)); return r;
}
__device__ __forceinline__ float2 upk2(u64 v) {
    float2 r; asm("mov.b64 {%0,%1},%2;" : "=f"(r.x), "=f"(r.y) : "l"(v)); return r;
}
__device__ __forceinline__ void fma2(u64& d, u64 a, u64 b) {
    asm("fma.rn.f32x2 %0,%1,%2,%3;" : "=l"(d) : "l"(a), "l"(b), "l"(d));
}
__device__ __forceinline__ float lrelu(float x) { return x > 0.f ? x : 0.1f * x; }

// =====================================================================
// Kernel A: tiled GEMM, 128 points/block, 256 threads.
// Outputs feats_x / guid_x as fp16; also mirrors dense_feats to fp16.
// =====================================================================
__global__ __launch_bounds__(256) void kA(const float* __restrict__ df,
                                          const float* __restrict__ w1,
                                          const float* __restrict__ b1,
                                          const float* __restrict__ wgu,
                                          const float* __restrict__ bgu) {
    extern __shared__ float sm[];
    float* s_dfT = sm;                 // [64][130]
    float* s_w1  = s_dfT + 64 * 130;   // [64][32]
    float* s_wgu = s_w1 + 2048;        // [32][32]
    float* s_fxT = s_wgu + 1024;       // [32][130]
    __shared__ float s_b1[32], s_bgu[32];

    int tid = threadIdx.x;
    int p0 = blockIdx.x * 128;

    for (int i = tid; i < 2048; i += 256) s_w1[i] = w1[i];
    for (int i = tid; i < 1024; i += 256) s_wgu[i] = wgu[i];
    if (tid < 32) { s_b1[tid] = b1[tid]; s_bgu[tid] = bgu[tid]; }

#pragma unroll
    for (int q = 0; q < 8; q++) {
        int f4 = tid + q * 256;
        int pt = f4 >> 4, c4 = (f4 & 15) * 4;
        int p = p0 + pt;
        float4 v = (p < N_PTS) ? *(const float4*)&df[(size_t)p * 64 + c4]
                               : make_float4(0.f, 0.f, 0.f, 0.f);
        s_dfT[(c4 + 0) * 130 + pt] = v.x;
        s_dfT[(c4 + 1) * 130 + pt] = v.y;
        s_dfT[(c4 + 2) * 130 + pt] = v.z;
        s_dfT[(c4 + 3) * 130 + pt] = v.w;
        if (p < N_PTS) {   // fp16 mirror of dense_feats for kB's shortcut gather
            __half2* dst = (__half2*)&g_df_h[(size_t)p * 64 + c4];
            dst[0] = __floats2half2_rn(v.x, v.y);
            dst[1] = __floats2half2_rn(v.z, v.w);
        }
    }
    __syncthreads();

    int tx = tid & 7;
    int ty = tid >> 3;

    // ---- stage 1: feats_x ----
    u64 acc[2][4];
#pragma unroll
    for (int i = 0; i < 2; i++)
#pragma unroll
        for (int j = 0; j < 4; j++) acc[i][j] = 0ull;

#pragma unroll 8
    for (int kk = 0; kk < 64; kk++) {
        const float* ar = &s_dfT[kk * 130 + ty * 4];
        u64 a01 = *(const u64*)(ar);
        u64 a23 = *(const u64*)(ar + 2);
        float4 bv = *(const float4*)&s_w1[kk * 32 + tx * 4];
        u64 b0 = pk2(bv.x, bv.x), b1p = pk2(bv.y, bv.y);
        u64 b2 = pk2(bv.z, bv.z), b3p = pk2(bv.w, bv.w);
        fma2(acc[0][0], a01, b0); fma2(acc[0][1], a01, b1p);
        fma2(acc[0][2], a01, b2); fma2(acc[0][3], a01, b3p);
        fma2(acc[1][0], a23, b0); fma2(acc[1][1], a23, b1p);
        fma2(acc[1][2], a23, b2); fma2(acc[1][3], a23, b3p);
    }

    float fx[4][4];
#pragma unroll
    for (int pp = 0; pp < 2; pp++)
#pragma unroll
        for (int j = 0; j < 4; j++) {
            float2 v = upk2(acc[pp][j]);
            float bb = s_b1[tx * 4 + j];
            fx[2 * pp][j] = lrelu(v.x + bb);
            fx[2 * pp + 1][j] = lrelu(v.y + bb);
        }
#pragma unroll
    for (int i = 0; i < 4; i++) {
        int pt = ty * 4 + i;
#pragma unroll
        for (int j = 0; j < 4; j++) s_fxT[(tx * 4 + j) * 130 + pt] = fx[i][j];
        int p = p0 + pt;
        if (p < N_PTS) {
            __half2* dst = (__half2*)&g_fx_h[(size_t)p * 32 + tx * 4];
            dst[0] = __floats2half2_rn(fx[i][0], fx[i][1]);
            dst[1] = __floats2half2_rn(fx[i][2], fx[i][3]);
        }
    }
    __syncthreads();

    // ---- stage 2: guid_x ----
    u64 acc2[2][4];
#pragma unroll
    for (int i = 0; i < 2; i++)
#pragma unroll
        for (int j = 0; j < 4; j++) acc2[i][j] = 0ull;

#pragma unroll 8
    for (int kk = 0; kk < 32; kk++) {
        const float* ar = &s_fxT[kk * 130 + ty * 4];
        u64 a01 = *(const u64*)(ar);
        u64 a23 = *(const u64*)(ar + 2);
        float4 bv = *(const float4*)&s_wgu[kk * 32 + tx * 4];
        u64 b0 = pk2(bv.x, bv.x), b1p = pk2(bv.y, bv.y);
        u64 b2 = pk2(bv.z, bv.z), b3p = pk2(bv.w, bv.w);
        fma2(acc2[0][0], a01, b0); fma2(acc2[0][1], a01, b1p);
        fma2(acc2[0][2], a01, b2); fma2(acc2[0][3], a01, b3p);
        fma2(acc2[1][0], a23, b0); fma2(acc2[1][1], a23, b1p);
        fma2(acc2[1][2], a23, b2); fma2(acc2[1][3], a23, b3p);
    }
#pragma unroll
    for (int pp = 0; pp < 2; pp++) {
#pragma unroll
        for (int i = 0; i < 2; i++) {
            int pt = ty * 4 + 2 * pp + i;
            int p = p0 + pt;
            if (p < N_PTS) {
                float2 v0 = upk2(acc2[pp][0]); float2 v1 = upk2(acc2[pp][1]);
                float2 v2 = upk2(acc2[pp][2]); float2 v3 = upk2(acc2[pp][3]);
                float o0 = (i ? v0.y : v0.x) + s_bgu[tx * 4 + 0];
                float o1 = (i ? v1.y : v1.x) + s_bgu[tx * 4 + 1];
                float o2 = (i ? v2.y : v2.x) + s_bgu[tx * 4 + 2];
                float o3 = (i ? v3.y : v3.x) + s_bgu[tx * 4 + 3];
                __half2* dst = (__half2*)&g_gx_h[(size_t)p * 32 + tx * 4];
                dst[0] = __floats2half2_rn(o0, o1);
                dst[1] = __floats2half2_rn(o2, o3);
            }
        }
    }
}

// =====================================================================
// Kernel B: warp-per-point. PE + WeightNet computed in-kernel (no HBM
// round-trips); fp16 gathers (L2-resident tables); fp16 agg output.
// =====================================================================
__global__ __launch_bounds__(128) void kB(
    const float* __restrict__ vi, const int* __restrict__ nei,
    const float* __restrict__ wpe, const float* __restrict__ bpe,
    const float* __restrict__ wg1, const float* __restrict__ bg1,
    const float* __restrict__ wg2, const float* __restrict__ bg2,
    const float* __restrict__ wn1, const float* __restrict__ bn1,
    const float* __restrict__ wn2, const float* __restrict__ bn2,
    const float* __restrict__ wn3, const float* __restrict__ bn3) {
    __shared__ float s_wpe[384], s_bpe[32];
    __shared__ float s_wg1p[544], s_bg1[8], s_wg2[64], s_bg2[8];
    __shared__ float s_w1[96], s_b1[8], s_w2[64], s_b2[8], s_w3[128], s_b3[16];
    __shared__ __align__(16) float s_vi[4][192];
    __shared__ __align__(16) float s_gfeat[4][1024];
    __shared__ __align__(16) float s_gf[4][512];
    __shared__ __align__(16) float s_wn[4][256];
    __shared__ __align__(16) float s_gmax[4][64];
    __shared__ int s_idx[4][16];

    int tid = threadIdx.x;
    for (int i = tid; i < 384; i += 128) s_wpe[i] = wpe[i];
    for (int i = tid; i < 512; i += 128) {
        int c = i >> 3, h2 = i & 7;
        s_wg1p[(c >> 4) * 136 + (c & 15) * 8 + h2] = wg1[i];
    }
    if (tid < 64)  s_wg2[tid] = wg2[tid];
    if (tid < 96)  s_w1[tid] = wn1[tid];
    if (tid < 64)  s_w2[tid] = wn2[tid];
    if (tid < 128) s_w3[tid] = wn3[tid];
    if (tid < 32)  s_bpe[tid] = bpe[tid];
    if (tid < 8) { s_bg1[tid] = bg1[tid]; s_bg2[tid] = bg2[tid];
                   s_b1[tid] = bn1[tid]; s_b2[tid] = bn2[tid]; }
    if (tid < 16) s_b3[tid] = bn3[tid];
    __syncthreads();

    int lane = tid & 31, w = tid >> 5;
    int m = blockIdx.x * 4 + w;
    if (m >= M_PTS) return;

    for (int i = lane; i < 48; i += 32)
        *(float4*)&s_vi[w][i * 4] = *(const float4*)&vi[(size_t)m * 192 + i * 4];
    if (lane < 16) s_idx[w][lane] = nei[m * 16 + lane];
    __syncwarp();

    // ---------- WeightNet, vectorized over k: 2 lanes per neighbor ----------
    {
        int kk = lane >> 1, half = lane & 1;
        const float* vk = &s_vi[w][kk * 12];
        float4 va = *(const float4*)vk;
        float4 vb = *(const float4*)(vk + 4);
        float4 vc = *(const float4*)(vk + 8);
        float vr[12] = {va.x, va.y, va.z, va.w, vb.x, vb.y, vb.z, vb.w,
                        vc.x, vc.y, vc.z, vc.w};
        float h1[4];
#pragma unroll
        for (int i = 0; i < 4; i++) {
            int o = half * 4 + i;
            float a = s_b1[o];
#pragma unroll
            for (int j = 0; j < 12; j++) a = fmaf(vr[j], s_w1[j * 8 + o], a);
            h1[i] = fmaxf(a, 0.f);
        }
        float oth[4];
#pragma unroll
        for (int i = 0; i < 4; i++) oth[i] = __shfl_xor_sync(~0u, h1[i], 1);
        float h1a[8];
#pragma unroll
        for (int j = 0; j < 8; j++)
            h1a[j] = ((j >> 2) == half) ? h1[j & 3] : oth[j & 3];

        float h2[4];
#pragma unroll
        for (int i = 0; i < 4; i++) {
            int o = half * 4 + i;
            float a = s_b2[o];
#pragma unroll
            for (int j = 0; j < 8; j++) a = fmaf(h1a[j], s_w2[j * 8 + o], a);
            h2[i] = fmaxf(a, 0.f);
        }
#pragma unroll
        for (int i = 0; i < 4; i++) oth[i] = __shfl_xor_sync(~0u, h2[i], 1);
        float h2a[8];
#pragma unroll
        for (int j = 0; j < 8; j++)
            h2a[j] = ((j >> 2) == half) ? h2[j & 3] : oth[j & 3];

        float w16[8];
#pragma unroll
        for (int q = 0; q < 8; q++) {
            int o = half * 8 + q;
            float a = s_b3[o];
#pragma unroll
            for (int j = 0; j < 8; j++) a = fmaf(h2a[j], s_w3[j * 16 + o], a);
            w16[q] = fmaxf(a, 0.f);
        }
        float* dst = &s_wn[w][kk * 16 + half * 8];
        *(float4*)dst = make_float4(w16[0], w16[1], w16[2], w16[3]);
        *(float4*)(dst + 4) = make_float4(w16[4], w16[5], w16[6], w16[7]);
    }

    // hoisted PE weights (per-lane column)
    float wpe_r[12];
#pragma unroll
    for (int j = 0; j < 12; j++) wpe_r[j] = s_wpe[j * 32 + lane];
    float bpe_r = s_bpe[lane];

    float gmax0 = -1e30f, gmax1 = -1e30f, sc0 = -1e30f, sc1 = -1e30f;

    // ---------- Phase 1: fp16 gathers + PE + maxes ----------
#pragma unroll 4
    for (int k = 0; k < 16; k++) {
        int n = s_idx[w][k];
        float gg = __half2float(g_gx_h[(size_t)n * 32 + lane]);
        float gf = __half2float(g_fx_h[(size_t)n * 32 + lane]);
        float d0 = __half2float(g_df_h[(size_t)n * 64 + lane]);
        float d1 = __half2float(g_df_h[(size_t)n * 64 + 32 + lane]);
        const float* vk = &s_vi[w][k * 12];
        float pe = bpe_r;
#pragma unroll
        for (int j = 0; j < 12; j++) pe = fmaf(vk[j], wpe_r[j], pe);
        pe = fmaxf(pe, 0.f);
        s_gfeat[w][k * 64 + lane] = gg;
        s_gfeat[w][k * 64 + 32 + lane] = pe;
        s_gf[w][k * 32 + lane] = gf;
        gmax0 = fmaxf(gmax0, gg);
        gmax1 = fmaxf(gmax1, pe);
        sc0 = fmaxf(sc0, d0);
        sc1 = fmaxf(sc1, d1);
    }
    s_gmax[w][lane] = gmax0;
    s_gmax[w][32 + lane] = gmax1;
    __syncwarp();

#pragma unroll
    for (int i = lane; i < 1024; i += 32) s_gfeat[w][i] -= s_gmax[w][i & 63];
    __syncwarp();

    // ---------- Phase 2: scores + weighted einsum ----------
    int h = lane & 7;
    int g = lane >> 3;
    u64 wg1p[8];
    const float* wg1g = &s_wg1p[g * 136];
#pragma unroll
    for (int c2 = 0; c2 < 8; c2++)
        wg1p[c2] = pk2(wg1g[(2 * c2) * 8 + h], wg1g[(2 * c2 + 1) * 8 + h]);
    float wg2r[8];
#pragma unroll
    for (int j = 0; j < 8; j++) wg2r[j] = s_wg2[j * 8 + h];
    float bg1r = s_bg1[h], bg2r = s_bg2[h];

    u64 accp[8];
#pragma unroll
    for (int i = 0; i < 8; i++) accp[i] = 0ull;

    for (int k = 0; k < 16; k++) {
        u64 hp = 0ull;
        const u64* gp = (const u64*)&s_gfeat[w][k * 64 + g * 16];
#pragma unroll
        for (int c2 = 0; c2 < 8; c2++) fma2(hp, gp[c2], wg1p[c2]);
        float2 hv = upk2(hp);
        float hid = hv.x + hv.y;
        hid += __shfl_xor_sync(~0u, hid, 8);
        hid += __shfl_xor_sync(~0u, hid, 16);
        hid = fmaxf(hid + bg1r, 0.f);

        float scz = bg2r;
#pragma unroll
        for (int j = 0; j < 8; j++)
            scz = fmaf(__shfl_sync(~0u, hid, j), wg2r[j], scz);
        float score = 1.f / (1.f + __expf(-scz));

        float sC = __shfl_sync(~0u, score, lane >> 2);
        float nf = s_gf[w][k * 32 + lane] * sC;
        u64 nfp = pk2(nf, nf);
        const u64* wp = (const u64*)&s_wn[w][k * 16];
#pragma unroll
        for (int q2 = 0; q2 < 8; q2++) fma2(accp[q2], nfp, wp[q2]);
    }

    // fp16 agg: lane writes 16 halves = 32B (2x STG.128)
    {
        size_t base = (size_t)m * 512 + lane * 16;
        float2 v0 = upk2(accp[0]), v1 = upk2(accp[1]);
        float2 v2 = upk2(accp[2]), v3 = upk2(accp[3]);
        H8 o0;
        o0.a = __floats2half2_rn(v0.x, v0.y); o0.b = __floats2half2_rn(v1.x, v1.y);
        o0.c = __floats2half2_rn(v2.x, v2.y); o0.d = __floats2half2_rn(v3.x, v3.y);
        *(H8*)&g_agg_h[base] = o0;
        float2 v4 = upk2(accp[4]), v5 = upk2(accp[5]);
        float2 v6 = upk2(accp[6]), v7 = upk2(accp[7]);
        H8 o1;
        o1.a = __floats2half2_rn(v4.x, v4.y); o1.b = __floats2half2_rn(v5.x, v5.y);
        o1.c = __floats2half2_rn(v6.x, v6.y); o1.d = __floats2half2_rn(v7.x, v7.y);
        *(H8*)&g_agg_h[base + 8] = o1;
    }
    g_maxf[m * 64 + lane] = sc0;
    g_maxf[m * 64 + 32 + lane] = sc1;
}

// =====================================================================
// Kernel C: BM=128, BN=64, BK=16, 256 threads, fp16 A-loads, f32x2 FMAs.
// smem union (AsT/Bs <-> mfs) = 65KB, 3 blocks/SM, two-pass epilogue.
// =====================================================================
__global__ __launch_bounds__(256, 3) void kC(
    const float* __restrict__ wlin, const float* __restrict__ blin,
    const float* __restrict__ wu2, const float* __restrict__ bu2,
    const float* __restrict__ wsc, const float* __restrict__ bsc,
    float* __restrict__ out) {
    extern __shared__ float sm[];
    float* o64 = sm;                 // [128][65]
    float* AsT = sm + 128 * 65;      // [16][130]  (aliases mfs)
    float* Bs  = AsT + 16 * 130;     // [16][64]
    float* mfs = sm + 128 * 65;      // [128][65]  (epilogue only)

    int tid = threadIdx.x;
    int m0 = blockIdx.x * 128;

    // A-load: one uint4 (8 halves) per thread per BK-slice
    int pt = tid >> 1, c8 = (tid & 1) * 8;
    bool av = (m0 + pt) < M_PTS;
    const __half* ap = &g_agg_h[(size_t)(m0 + (av ? pt : 0)) * 512 + c8];
    int rb = tid >> 4, cb = (tid & 15) * 4;
    const float* bp = &wlin[rb * 64 + cb];

    int tx = tid & 15;
    int ty = tid >> 4;

    u64 accp[4][4];
#pragma unroll
    for (int i = 0; i < 4; i++)
#pragma unroll
        for (int j = 0; j < 4; j++) accp[i][j] = 0ull;

    uint4 ra = av ? *(const uint4*)ap : make_uint4(0, 0, 0, 0);
    float4 rbv = *(const float4*)bp;

    for (int kb = 0; kb < 32; kb++) {
        {
            __half2* hp = (__half2*)&ra;
            float2 f0 = __half22float2(hp[0]); float2 f1 = __half22float2(hp[1]);
            float2 f2 = __half22float2(hp[2]); float2 f3 = __half22float2(hp[3]);
            AsT[(c8 + 0) * 130 + pt] = f0.x; AsT[(c8 + 1) * 130 + pt] = f0.y;
            AsT[(c8 + 2) * 130 + pt] = f1.x; AsT[(c8 + 3) * 130 + pt] = f1.y;
            AsT[(c8 + 4) * 130 + pt] = f2.x; AsT[(c8 + 5) * 130 + pt] = f2.y;
            AsT[(c8 + 6) * 130 + pt] = f3.x; AsT[(c8 + 7) * 130 + pt] = f3.y;
        }
        *(float4*)&Bs[rb * 64 + cb] = rbv;
        __syncthreads();

        if (kb < 31) {
            ra = av ? *(const uint4*)(ap + (kb + 1) * 16) : make_uint4(0, 0, 0, 0);
            rbv = *(const float4*)(bp + (kb + 1) * 16 * 64);
        }

#pragma unroll
        for (int kk = 0; kk < 16; kk++) {
            const float* ar = &AsT[kk * 130 + ty * 8];
            u64 a01 = *(const u64*)(ar);
            u64 a23 = *(const u64*)(ar + 2);
            u64 a45 = *(const u64*)(ar + 4);
            u64 a67 = *(const u64*)(ar + 6);
            float4 bv = *(const float4*)&Bs[kk * 64 + tx * 4];
            u64 b0 = pk2(bv.x, bv.x), b1p = pk2(bv.y, bv.y);
            u64 b2 = pk2(bv.z, bv.z), b3p = pk2(bv.w, bv.w);
            fma2(accp[0][0], a01, b0); fma2(accp[0][1], a01, b1p);
            fma2(accp[0][2], a01, b2); fma2(accp[0][3], a01, b3p);
            fma2(accp[1][0], a23, b0); fma2(accp[1][1], a23, b1p);
            fma2(accp[1][2], a23, b2); fma2(accp[1][3], a23, b3p);
            fma2(accp[2][0], a45, b0); fma2(accp[2][1], a45, b1p);
            fma2(accp[2][2], a45, b2); fma2(accp[2][3], a45, b3p);
            fma2(accp[3][0], a67, b0); fma2(accp[3][1], a67, b1p);
            fma2(accp[3][2], a67, b2); fma2(accp[3][3], a67, b3p);
        }
        __syncthreads();
    }

    // bias + relu -> o64 smem
    {
        float blr[4];
#pragma unroll
        for (int j = 0; j < 4; j++) blr[j] = __ldg(&blin[tx * 4 + j]);
#pragma unroll
        for (int ip = 0; ip < 4; ip++)
#pragma unroll
            for (int j = 0; j < 4; j++) {
                float2 v = upk2(accp[ip][j]);
                o64[(ty * 8 + 2 * ip) * 65 + tx * 4 + j] = fmaxf(v.x + blr[j], 0.f);
                o64[(ty * 8 + 2 * ip + 1) * 65 + tx * 4 + j] = fmaxf(v.y + blr[j], 0.f);
            }
    }

    // load maxf tile into the (now free) AsT/Bs region
#pragma unroll
    for (int q = 0; q < 8; q++) {
        int f4 = tid + q * 256;
        int ptq = f4 >> 4, c4 = (f4 & 15) * 4;
        int mm = m0 + ptq;
        float4 v = (mm < M_PTS) ? *(const float4*)&g_maxf[(size_t)mm * 64 + c4]
                                : make_float4(0.f, 0.f, 0.f, 0.f);
        mfs[ptq * 65 + c4 + 0] = v.x; mfs[ptq * 65 + c4 + 1] = v.y;
        mfs[ptq * 65 + c4 + 2] = v.z; mfs[ptq * 65 + c4 + 3] = v.w;
    }
    __syncthreads();

    // epilogue: two passes of 4 rows x 8 cols per thread
    int o0 = (tid & 15) * 8;
#pragma unroll
    for (int pass = 0; pass < 2; pass++) {
        int mpt = (tid >> 4) * 8 + pass * 4;
        u64 acc2[4][4];
#pragma unroll
        for (int i = 0; i < 4; i++)
#pragma unroll
            for (int c = 0; c < 4; c++) acc2[i][c] = 0ull;

        for (int j = 0; j < 64; j++) {
            const u64* pu = (const u64*)&wu2[j * 128 + o0];
            const u64* ps = (const u64*)&wsc[j * 128 + o0];
            u64 u0 = __ldg(pu), u1 = __ldg(pu + 1), u2v = __ldg(pu + 2), u3 = __ldg(pu + 3);
            u64 s0 = __ldg(ps), s1 = __ldg(ps + 1), s2v = __ldg(ps + 2), s3 = __ldg(ps + 3);
#pragma unroll
            for (int i = 0; i < 4; i++) {
                float a = o64[(mpt + i) * 65 + j];
                float c = mfs[(mpt + i) * 65 + j];
                u64 apk = pk2(a, a), cpk = pk2(c, c);
                fma2(acc2[i][0], apk, u0); fma2(acc2[i][0], cpk, s0);
                fma2(acc2[i][1], apk, u1); fma2(acc2[i][1], cpk, s1);
                fma2(acc2[i][2], apk, u2v); fma2(acc2[i][2], cpk, s2v);
                fma2(acc2[i][3], apk, u3); fma2(acc2[i][3], cpk, s3);
            }
        }

        float bb[8];
#pragma unroll
        for (int q = 0; q < 8; q++) bb[q] = __ldg(&bu2[o0 + q]) + __ldg(&bsc[o0 + q]);
#pragma unroll
        for (int i = 0; i < 4; i++) {
            int m = m0 + mpt + i;
            if (m < M_PTS) {
                float4 oA, oB;
                float2 v0 = upk2(acc2[i][0]); float2 v1 = upk2(acc2[i][1]);
                float2 v2 = upk2(acc2[i][2]); float2 v3 = upk2(acc2[i][3]);
                oA.x = lrelu(v0.x + bb[0]); oA.y = lrelu(v0.y + bb[1]);
                oA.z = lrelu(v1.x + bb[2]); oA.w = lrelu(v1.y + bb[3]);
                oB.x = lrelu(v2.x + bb[4]); oB.y = lrelu(v2.y + bb[5]);
                oB.z = lrelu(v3.x + bb[6]); oB.w = lrelu(v3.y + bb[7]);
                *(float4*)&out[(size_t)m * 128 + o0] = oA;
                *(float4*)&out[(size_t)m * 128 + o0 + 4] = oB;
            }
        }
    }
}

// =====================================================================
extern "C" void kernel_launch(void* const* d_in, const int* in_sizes, int n_in,
                              void* d_out, int out_size) {
    const float* dense_feats = (const float*)d_in[1];
    const float* vi          = (const float*)d_in[5];
    const int*   nei         = (const int*)d_in[6];
    const float* w_u1  = (const float*)d_in[7];  const float* b_u1  = (const float*)d_in[8];
    const float* w_gu  = (const float*)d_in[9];  const float* b_gu  = (const float*)d_in[10];
    const float* w_pe  = (const float*)d_in[11]; const float* b_pe  = (const float*)d_in[12];
    const float* w_g1  = (const float*)d_in[13]; const float* b_g1  = (const float*)d_in[14];
    const float* w_g2  = (const float*)d_in[15]; const float* b_g2  = (const float*)d_in[16];
    const float* w_wn1 = (const float*)d_in[17]; const float* b_wn1 = (const float*)d_in[18];
    const float* w_wn2 = (const float*)d_in[19]; const float* b_wn2 = (const float*)d_in[20];
    const float* w_wn3 = (const float*)d_in[21]; const float* b_wn3 = (const float*)d_in[22];
    const float* w_lin = (const float*)d_in[23]; const float* b_lin = (const float*)d_in[24];
    const float* w_u2  = (const float*)d_in[25]; const float* b_u2  = (const float*)d_in[26];
    const float* w_sc  = (const float*)d_in[27]; const float* b_sc  = (const float*)d_in[28];
    float* out = (float*)d_out;

    int smemA = (64 * 130 + 64 * 32 + 32 * 32 + 32 * 130) * 4;   // 62208 B
    cudaFuncSetAttribute(kA, cudaFuncAttributeMaxDynamicSharedMemorySize, smemA);
    kA<<<(N_PTS + 127) / 128, 256, smemA>>>(dense_feats, w_u1, b_u1, w_gu, b_gu);

    kB<<<(M_PTS + 3) / 4, 128>>>(vi, nei,
                                 w_pe, b_pe, w_g1, b_g1, w_g2, b_g2,
                                 w_wn1, b_wn1, w_wn2, b_wn2, w_wn3, b_wn3);

    int smemC = (128 * 65 + 16 * 130 + 16 * 64) * 4 > (128 * 65 * 2) * 4
                    ? (128 * 65 + 16 * 130 + 16 * 64) * 4
                    : (128 * 65 * 2) * 4;                        // 66560 B
    cudaFuncSetAttribute(kC, cudaFuncAttributeMaxDynamicSharedMemorySize, smemC);
    kC<<<(M_PTS + 127) / 128, 256, smemC>>>(w_lin, b_lin, w_u2, b_u2, w_sc, b_sc, out);
}

// round 13
// speedup vs baseline: 1.5031x; 1.0639x over previous
#include <cuda_runtime.h>
#include <cuda_fp16.h>
#include <cstdint>

#define N_PTS 200000
#define M_PTS 100000

typedef unsigned long long u64;

// ---- scratch (device-global, no allocation) ----
__device__ __half g_fx_h[N_PTS * 32];                // 12.8 MB
__device__ __half g_gx_h[N_PTS * 32];                // 12.8 MB
__device__ __half g_df_h[(size_t)N_PTS * 64];        // 25.6 MB
__device__ __half g_agg_h[(size_t)M_PTS * 512];      // 102.4 MB
__device__ float  g_maxf[M_PTS * 64];                // 25.6 MB

struct __align__(16) H8 { __half2 a, b, c, d; };

// ---- packed fp32x2 helpers ----
__device__ __forceinline__ u64 pk2(float x, float y) {
    u64 r; asm("mov.b64 %0,{%1,%2};" : "=l"(r) : "f"(x), "f"(y)); return r;
}
__device__ __forceinline__ float2 upk2(u64 v) {
    float2 r; asm("mov.b64 {%0,%1},%2;" : "=f"(r.x), "=f"(r.y) : "l"(v)); return r;
}
__device__ __forceinline__ void fma2(u64& d, u64 a, u64 b) {
    asm("fma.rn.f32x2 %0,%1,%2,%3;" : "=l"(d) : "l"(a), "l"(b), "l"(d));
}
__device__ __forceinline__ float lrelu(float x) { return x > 0.f ? x : 0.1f * x; }

// =====================================================================
// Kernel A: tiled GEMM, 128 points/block, 256 threads. (unchanged R6)
// =====================================================================
__global__ __launch_bounds__(256) void kA(const float* __restrict__ df,
                                          const float* __restrict__ w1,
                                          const float* __restrict__ b1,
                                          const float* __restrict__ wgu,
                                          const float* __restrict__ bgu) {
    extern __shared__ float sm[];
    float* s_dfT = sm;                 // [64][130]
    float* s_w1  = s_dfT + 64 * 130;   // [64][32]
    float* s_wgu = s_w1 + 2048;        // [32][32]
    float* s_fxT = s_wgu + 1024;       // [32][130]
    __shared__ float s_b1[32], s_bgu[32];

    int tid = threadIdx.x;
    int p0 = blockIdx.x * 128;

    for (int i = tid; i < 2048; i += 256) s_w1[i] = w1[i];
    for (int i = tid; i < 1024; i += 256) s_wgu[i] = wgu[i];
    if (tid < 32) { s_b1[tid] = b1[tid]; s_bgu[tid] = bgu[tid]; }

#pragma unroll
    for (int q = 0; q < 8; q++) {
        int f4 = tid + q * 256;
        int pt = f4 >> 4, c4 = (f4 & 15) * 4;
        int p = p0 + pt;
        float4 v = (p < N_PTS) ? *(const float4*)&df[(size_t)p * 64 + c4]
                               : make_float4(0.f, 0.f, 0.f, 0.f);
        s_dfT[(c4 + 0) * 130 + pt] = v.x;
        s_dfT[(c4 + 1) * 130 + pt] = v.y;
        s_dfT[(c4 + 2) * 130 + pt] = v.z;
        s_dfT[(c4 + 3) * 130 + pt] = v.w;
        if (p < N_PTS) {
            __half2* dst = (__half2*)&g_df_h[(size_t)p * 64 + c4];
            dst[0] = __floats2half2_rn(v.x, v.y);
            dst[1] = __floats2half2_rn(v.z, v.w);
        }
    }
    __syncthreads();

    int tx = tid & 7;
    int ty = tid >> 3;

    u64 acc[2][4];
#pragma unroll
    for (int i = 0; i < 2; i++)
#pragma unroll
        for (int j = 0; j < 4; j++) acc[i][j] = 0ull;

#pragma unroll 8
    for (int kk = 0; kk < 64; kk++) {
        const float* ar = &s_dfT[kk * 130 + ty * 4];
        u64 a01 = *(const u64*)(ar);
        u64 a23 = *(const u64*)(ar + 2);
        float4 bv = *(const float4*)&s_w1[kk * 32 + tx * 4];
        u64 b0 = pk2(bv.x, bv.x), b1p = pk2(bv.y, bv.y);
        u64 b2 = pk2(bv.z, bv.z), b3p = pk2(bv.w, bv.w);
        fma2(acc[0][0], a01, b0); fma2(acc[0][1], a01, b1p);
        fma2(acc[0][2], a01, b2); fma2(acc[0][3], a01, b3p);
        fma2(acc[1][0], a23, b0); fma2(acc[1][1], a23, b1p);
        fma2(acc[1][2], a23, b2); fma2(acc[1][3], a23, b3p);
    }

    float fx[4][4];
#pragma unroll
    for (int pp = 0; pp < 2; pp++)
#pragma unroll
        for (int j = 0; j < 4; j++) {
            float2 v = upk2(acc[pp][j]);
            float bb = s_b1[tx * 4 + j];
            fx[2 * pp][j] = lrelu(v.x + bb);
            fx[2 * pp + 1][j] = lrelu(v.y + bb);
        }
#pragma unroll
    for (int i = 0; i < 4; i++) {
        int pt = ty * 4 + i;
#pragma unroll
        for (int j = 0; j < 4; j++) s_fxT[(tx * 4 + j) * 130 + pt] = fx[i][j];
        int p = p0 + pt;
        if (p < N_PTS) {
            __half2* dst = (__half2*)&g_fx_h[(size_t)p * 32 + tx * 4];
            dst[0] = __floats2half2_rn(fx[i][0], fx[i][1]);
            dst[1] = __floats2half2_rn(fx[i][2], fx[i][3]);
        }
    }
    __syncthreads();

    u64 acc2[2][4];
#pragma unroll
    for (int i = 0; i < 2; i++)
#pragma unroll
        for (int j = 0; j < 4; j++) acc2[i][j] = 0ull;

#pragma unroll 8
    for (int kk = 0; kk < 32; kk++) {
        const float* ar = &s_fxT[kk * 130 + ty * 4];
        u64 a01 = *(const u64*)(ar);
        u64 a23 = *(const u64*)(ar + 2);
        float4 bv = *(const float4*)&s_wgu[kk * 32 + tx * 4];
        u64 b0 = pk2(bv.x, bv.x), b1p = pk2(bv.y, bv.y);
        u64 b2 = pk2(bv.z, bv.z), b3p = pk2(bv.w, bv.w);
        fma2(acc2[0][0], a01, b0); fma2(acc2[0][1], a01, b1p);
        fma2(acc2[0][2], a01, b2); fma2(acc2[0][3], a01, b3p);
        fma2(acc2[1][0], a23, b0); fma2(acc2[1][1], a23, b1p);
        fma2(acc2[1][2], a23, b2); fma2(acc2[1][3], a23, b3p);
    }
#pragma unroll
    for (int pp = 0; pp < 2; pp++) {
#pragma unroll
        for (int i = 0; i < 2; i++) {
            int pt = ty * 4 + 2 * pp + i;
            int p = p0 + pt;
            if (p < N_PTS) {
                float2 v0 = upk2(acc2[pp][0]); float2 v1 = upk2(acc2[pp][1]);
                float2 v2 = upk2(acc2[pp][2]); float2 v3 = upk2(acc2[pp][3]);
                float o0 = (i ? v0.y : v0.x) + s_bgu[tx * 4 + 0];
                float o1 = (i ? v1.y : v1.x) + s_bgu[tx * 4 + 1];
                float o2 = (i ? v2.y : v2.x) + s_bgu[tx * 4 + 2];
                float o3 = (i ? v3.y : v3.x) + s_bgu[tx * 4 + 3];
                __half2* dst = (__half2*)&g_gx_h[(size_t)p * 32 + tx * 4];
                dst[0] = __floats2half2_rn(o0, o1);
                dst[1] = __floats2half2_rn(o2, o3);
            }
        }
    }
}

// =====================================================================
// Kernel B v3: warp-per-point, latency-restructured.
//  - phase 1: 2 batches of 8 k's, all 32 gathers front-issued (MLP=32)
//  - gmax handled algebraically via hmax fold into bias (no subtract pass)
//  - phase 2: unroll 4 to overlap the serial shfl/sigmoid chains
// =====================================================================
__global__ __launch_bounds__(128) void kB(
    const float* __restrict__ vi, const int* __restrict__ nei,
    const float* __restrict__ wpe, const float* __restrict__ bpe,
    const float* __restrict__ wg1, const float* __restrict__ bg1,
    const float* __restrict__ wg2, const float* __restrict__ bg2,
    const float* __restrict__ wn1, const float* __restrict__ bn1,
    const float* __restrict__ wn2, const float* __restrict__ bn2,
    const float* __restrict__ wn3, const float* __restrict__ bn3) {
    __shared__ float s_wpe[384], s_bpe[32];
    __shared__ float s_wg1p[544], s_bg1[8], s_wg2[64], s_bg2[8];
    __shared__ float s_w1[96], s_b1[8], s_w2[64], s_b2[8], s_w3[128], s_b3[16];
    __shared__ __align__(16) float s_vi[4][192];
    __shared__ __align__(16) float s_gfeat[4][1024];
    __shared__ __align__(16) float s_gf[4][512];
    __shared__ __align__(16) float s_wn[4][256];
    __shared__ __align__(16) float s_gmax[4][64];
    __shared__ int s_idx[4][16];

    int tid = threadIdx.x;
    for (int i = tid; i < 384; i += 128) s_wpe[i] = wpe[i];
    for (int i = tid; i < 512; i += 128) {
        int c = i >> 3, h2 = i & 7;
        s_wg1p[(c >> 4) * 136 + (c & 15) * 8 + h2] = wg1[i];
    }
    if (tid < 64)  s_wg2[tid] = wg2[tid];
    if (tid < 96)  s_w1[tid] = wn1[tid];
    if (tid < 64)  s_w2[tid] = wn2[tid];
    if (tid < 128) s_w3[tid] = wn3[tid];
    if (tid < 32)  s_bpe[tid] = bpe[tid];
    if (tid < 8) { s_bg1[tid] = bg1[tid]; s_bg2[tid] = bg2[tid];
                   s_b1[tid] = bn1[tid]; s_b2[tid] = bn2[tid]; }
    if (tid < 16) s_b3[tid] = bn3[tid];
    __syncthreads();

    int lane = tid & 31, w = tid >> 5;
    int m = blockIdx.x * 4 + w;
    if (m >= M_PTS) return;

    for (int i = lane; i < 48; i += 32)
        *(float4*)&s_vi[w][i * 4] = *(const float4*)&vi[(size_t)m * 192 + i * 4];
    if (lane < 16) s_idx[w][lane] = nei[m * 16 + lane];
    __syncwarp();

    // ---------- WeightNet, vectorized over k: 2 lanes per neighbor ----------
    {
        int kk = lane >> 1, half = lane & 1;
        const float* vk = &s_vi[w][kk * 12];
        float4 va = *(const float4*)vk;
        float4 vb = *(const float4*)(vk + 4);
        float4 vc = *(const float4*)(vk + 8);
        float vr[12] = {va.x, va.y, va.z, va.w, vb.x, vb.y, vb.z, vb.w,
                        vc.x, vc.y, vc.z, vc.w};
        float h1[4];
#pragma unroll
        for (int i = 0; i < 4; i++) {
            int o = half * 4 + i;
            float a = s_b1[o];
#pragma unroll
            for (int j = 0; j < 12; j++) a = fmaf(vr[j], s_w1[j * 8 + o], a);
            h1[i] = fmaxf(a, 0.f);
        }
        float oth[4];
#pragma unroll
        for (int i = 0; i < 4; i++) oth[i] = __shfl_xor_sync(~0u, h1[i], 1);
        float h1a[8];
#pragma unroll
        for (int j = 0; j < 8; j++)
            h1a[j] = ((j >> 2) == half) ? h1[j & 3] : oth[j & 3];

        float h2[4];
#pragma unroll
        for (int i = 0; i < 4; i++) {
            int o = half * 4 + i;
            float a = s_b2[o];
#pragma unroll
            for (int j = 0; j < 8; j++) a = fmaf(h1a[j], s_w2[j * 8 + o], a);
            h2[i] = fmaxf(a, 0.f);
        }
#pragma unroll
        for (int i = 0; i < 4; i++) oth[i] = __shfl_xor_sync(~0u, h2[i], 1);
        float h2a[8];
#pragma unroll
        for (int j = 0; j < 8; j++)
            h2a[j] = ((j >> 2) == half) ? h2[j & 3] : oth[j & 3];

        float w16[8];
#pragma unroll
        for (int q = 0; q < 8; q++) {
            int o = half * 8 + q;
            float a = s_b3[o];
#pragma unroll
            for (int j = 0; j < 8; j++) a = fmaf(h2a[j], s_w3[j * 16 + o], a);
            w16[q] = fmaxf(a, 0.f);
        }
        float* dst = &s_wn[w][kk * 16 + half * 8];
        *(float4*)dst = make_float4(w16[0], w16[1], w16[2], w16[3]);
        *(float4*)(dst + 4) = make_float4(w16[4], w16[5], w16[6], w16[7]);
    }

    // hoisted PE weights (per-lane column)
    float wpe_r[12];
#pragma unroll
    for (int j = 0; j < 12; j++) wpe_r[j] = s_wpe[j * 32 + lane];
    float bpe_r = s_bpe[lane];

    float gmax0 = -1e30f, gmax1 = -1e30f, sc0 = -1e30f, sc1 = -1e30f;

    // ---------- Phase 1: front-batched gathers (MLP=32), 2 batches of 8 ----------
#pragma unroll
    for (int b = 0; b < 2; b++) {
        float gg[8], gf[8], d0[8], d1[8];
#pragma unroll
        for (int kk = 0; kk < 8; kk++) {
            int n = s_idx[w][b * 8 + kk];
            gg[kk] = __half2float(g_gx_h[(size_t)n * 32 + lane]);
            gf[kk] = __half2float(g_fx_h[(size_t)n * 32 + lane]);
            d0[kk] = __half2float(g_df_h[(size_t)n * 64 + lane]);
            d1[kk] = __half2float(g_df_h[(size_t)n * 64 + 32 + lane]);
        }
#pragma unroll
        for (int kk = 0; kk < 8; kk++) {
            int k = b * 8 + kk;
            const float* vk = &s_vi[w][k * 12];
            float pe = bpe_r;
#pragma unroll
            for (int j = 0; j < 12; j++) pe = fmaf(vk[j], wpe_r[j], pe);
            pe = fmaxf(pe, 0.f);
            s_gfeat[w][k * 64 + lane] = gg[kk];
            s_gfeat[w][k * 64 + 32 + lane] = pe;
            s_gf[w][k * 32 + lane] = gf[kk];
            gmax0 = fmaxf(gmax0, gg[kk]);
            gmax1 = fmaxf(gmax1, pe);
            sc0 = fmaxf(sc0, d0[kk]);
            sc1 = fmaxf(sc1, d1[kk]);
        }
    }
    s_gmax[w][lane] = gmax0;
    s_gmax[w][32 + lane] = gmax1;
    __syncwarp();

    // ---------- Phase 2: scores + weighted einsum ----------
    int h = lane & 7;
    int g = lane >> 3;
    u64 wg1p[8];
    const float* wg1g = &s_wg1p[g * 136];
#pragma unroll
    for (int c2 = 0; c2 < 8; c2++)
        wg1p[c2] = pk2(wg1g[(2 * c2) * 8 + h], wg1g[(2 * c2 + 1) * 8 + h]);
    float wg2r[8];
#pragma unroll
    for (int j = 0; j < 8; j++) wg2r[j] = s_wg2[j * 8 + h];
    float bg1r = s_bg1[h], bg2r = s_bg2[h];

    // hmax[h] = dot(gmax, wg1[:,h]); fold into bias (exact algebra:
    // dot(gfeat - gmax, w) = dot(gfeat, w) - dot(gmax, w))
    {
        u64 hmp = 0ull;
        const u64* gmp = (const u64*)&s_gmax[w][g * 16];
#pragma unroll
        for (int c2 = 0; c2 < 8; c2++) fma2(hmp, gmp[c2], wg1p[c2]);
        float2 hmv = upk2(hmp);
        float hmax = hmv.x + hmv.y;
        hmax += __shfl_xor_sync(~0u, hmax, 8);
        hmax += __shfl_xor_sync(~0u, hmax, 16);
        bg1r -= hmax;
    }

    u64 accp[8];
#pragma unroll
    for (int i = 0; i < 8; i++) accp[i] = 0ull;

#pragma unroll 4
    for (int k = 0; k < 16; k++) {
        u64 hp = 0ull;
        const u64* gp = (const u64*)&s_gfeat[w][k * 64 + g * 16];
#pragma unroll
        for (int c2 = 0; c2 < 8; c2++) fma2(hp, gp[c2], wg1p[c2]);
        float2 hv = upk2(hp);
        float hid = hv.x + hv.y;
        hid += __shfl_xor_sync(~0u, hid, 8);
        hid += __shfl_xor_sync(~0u, hid, 16);
        hid = fmaxf(hid + bg1r, 0.f);

        float scz = bg2r;
#pragma unroll
        for (int j = 0; j < 8; j++)
            scz = fmaf(__shfl_sync(~0u, hid, j), wg2r[j], scz);
        float score = 1.f / (1.f + __expf(-scz));

        float sC = __shfl_sync(~0u, score, lane >> 2);
        float nf = s_gf[w][k * 32 + lane] * sC;
        u64 nfp = pk2(nf, nf);
        const u64* wp = (const u64*)&s_wn[w][k * 16];
#pragma unroll
        for (int q2 = 0; q2 < 8; q2++) fma2(accp[q2], nfp, wp[q2]);
    }

    // fp16 agg: lane writes 16 halves = 32B (2x STG.128)
    {
        size_t base = (size_t)m * 512 + lane * 16;
        float2 v0 = upk2(accp[0]), v1 = upk2(accp[1]);
        float2 v2 = upk2(accp[2]), v3 = upk2(accp[3]);
        H8 o0;
        o0.a = __floats2half2_rn(v0.x, v0.y); o0.b = __floats2half2_rn(v1.x, v1.y);
        o0.c = __floats2half2_rn(v2.x, v2.y); o0.d = __floats2half2_rn(v3.x, v3.y);
        *(H8*)&g_agg_h[base] = o0;
        float2 v4 = upk2(accp[4]), v5 = upk2(accp[5]);
        float2 v6 = upk2(accp[6]), v7 = upk2(accp[7]);
        H8 o1;
        o1.a = __floats2half2_rn(v4.x, v4.y); o1.b = __floats2half2_rn(v5.x, v5.y);
        o1.c = __floats2half2_rn(v6.x, v6.y); o1.d = __floats2half2_rn(v7.x, v7.y);
        *(H8*)&g_agg_h[base + 8] = o1;
    }
    g_maxf[m * 64 + lane] = sc0;
    g_maxf[m * 64 + 32 + lane] = sc1;
}

// =====================================================================
// Kernel C: BM=128, BN=64, BK=16, 256 threads, fp16 A-loads, f32x2 FMAs.
// smem union, 3 blocks/SM, two-pass epilogue. (unchanged R9)
// =====================================================================
__global__ __launch_bounds__(256, 3) void kC(
    const float* __restrict__ wlin, const float* __restrict__ blin,
    const float* __restrict__ wu2, const float* __restrict__ bu2,
    const float* __restrict__ wsc, const float* __restrict__ bsc,
    float* __restrict__ out) {
    extern __shared__ float sm[];
    float* o64 = sm;                 // [128][65]
    float* AsT = sm + 128 * 65;      // [16][130]  (aliases mfs)
    float* Bs  = AsT + 16 * 130;     // [16][64]
    float* mfs = sm + 128 * 65;      // [128][65]  (epilogue only)

    int tid = threadIdx.x;
    int m0 = blockIdx.x * 128;

    int pt = tid >> 1, c8 = (tid & 1) * 8;
    bool av = (m0 + pt) < M_PTS;
    const __half* ap = &g_agg_h[(size_t)(m0 + (av ? pt : 0)) * 512 + c8];
    int rb = tid >> 4, cb = (tid & 15) * 4;
    const float* bp = &wlin[rb * 64 + cb];

    int tx = tid & 15;
    int ty = tid >> 4;

    u64 accp[4][4];
#pragma unroll
    for (int i = 0; i < 4; i++)
#pragma unroll
        for (int j = 0; j < 4; j++) accp[i][j] = 0ull;

    uint4 ra = av ? *(const uint4*)ap : make_uint4(0, 0, 0, 0);
    float4 rbv = *(const float4*)bp;

    for (int kb = 0; kb < 32; kb++) {
        {
            __half2* hp = (__half2*)&ra;
            float2 f0 = __half22float2(hp[0]); float2 f1 = __half22float2(hp[1]);
            float2 f2 = __half22float2(hp[2]); float2 f3 = __half22float2(hp[3]);
            AsT[(c8 + 0) * 130 + pt] = f0.x; AsT[(c8 + 1) * 130 + pt] = f0.y;
            AsT[(c8 + 2) * 130 + pt] = f1.x; AsT[(c8 + 3) * 130 + pt] = f1.y;
            AsT[(c8 + 4) * 130 + pt] = f2.x; AsT[(c8 + 5) * 130 + pt] = f2.y;
            AsT[(c8 + 6) * 130 + pt] = f3.x; AsT[(c8 + 7) * 130 + pt] = f3.y;
        }
        *(float4*)&Bs[rb * 64 + cb] = rbv;
        __syncthreads();

        if (kb < 31) {
            ra = av ? *(const uint4*)(ap + (kb + 1) * 16) : make_uint4(0, 0, 0, 0);
            rbv = *(const float4*)(bp + (kb + 1) * 16 * 64);
        }

#pragma unroll
        for (int kk = 0; kk < 16; kk++) {
            const float* ar = &AsT[kk * 130 + ty * 8];
            u64 a01 = *(const u64*)(ar);
            u64 a23 = *(const u64*)(ar + 2);
            u64 a45 = *(const u64*)(ar + 4);
            u64 a67 = *(const u64*)(ar + 6);
            float4 bv = *(const float4*)&Bs[kk * 64 + tx * 4];
            u64 b0 = pk2(bv.x, bv.x), b1p = pk2(bv.y, bv.y);
            u64 b2 = pk2(bv.z, bv.z), b3p = pk2(bv.w, bv.w);
            fma2(accp[0][0], a01, b0); fma2(accp[0][1], a01, b1p);
            fma2(accp[0][2], a01, b2); fma2(accp[0][3], a01, b3p);
            fma2(accp[1][0], a23, b0); fma2(accp[1][1], a23, b1p);
            fma2(accp[1][2], a23, b2); fma2(accp[1][3], a23, b3p);
            fma2(accp[2][0], a45, b0); fma2(accp[2][1], a45, b1p);
            fma2(accp[2][2], a45, b2); fma2(accp[2][3], a45, b3p);
            fma2(accp[3][0], a67, b0); fma2(accp[3][1], a67, b1p);
            fma2(accp[3][2], a67, b2); fma2(accp[3][3], a67, b3p);
        }
        __syncthreads();
    }

    {
        float blr[4];
#pragma unroll
        for (int j = 0; j < 4; j++) blr[j] = __ldg(&blin[tx * 4 + j]);
#pragma unroll
        for (int ip = 0; ip < 4; ip++)
#pragma unroll
            for (int j = 0; j < 4; j++) {
                float2 v = upk2(accp[ip][j]);
                o64[(ty * 8 + 2 * ip) * 65 + tx * 4 + j] = fmaxf(v.x + blr[j], 0.f);
                o64[(ty * 8 + 2 * ip + 1) * 65 + tx * 4 + j] = fmaxf(v.y + blr[j], 0.f);
            }
    }

#pragma unroll
    for (int q = 0; q < 8; q++) {
        int f4 = tid + q * 256;
        int ptq = f4 >> 4, c4 = (f4 & 15) * 4;
        int mm = m0 + ptq;
        float4 v = (mm < M_PTS) ? *(const float4*)&g_maxf[(size_t)mm * 64 + c4]
                                : make_float4(0.f, 0.f, 0.f, 0.f);
        mfs[ptq * 65 + c4 + 0] = v.x; mfs[ptq * 65 + c4 + 1] = v.y;
        mfs[ptq * 65 + c4 + 2] = v.z; mfs[ptq * 65 + c4 + 3] = v.w;
    }
    __syncthreads();

    int o0 = (tid & 15) * 8;
#pragma unroll
    for (int pass = 0; pass < 2; pass++) {
        int mpt = (tid >> 4) * 8 + pass * 4;
        u64 acc2[4][4];
#pragma unroll
        for (int i = 0; i < 4; i++)
#pragma unroll
            for (int c = 0; c < 4; c++) acc2[i][c] = 0ull;

        for (int j = 0; j < 64; j++) {
            const u64* pu = (const u64*)&wu2[j * 128 + o0];
            const u64* ps = (const u64*)&wsc[j * 128 + o0];
            u64 u0 = __ldg(pu), u1 = __ldg(pu + 1), u2v = __ldg(pu + 2), u3 = __ldg(pu + 3);
            u64 s0 = __ldg(ps), s1 = __ldg(ps + 1), s2v = __ldg(ps + 2), s3 = __ldg(ps + 3);
#pragma unroll
            for (int i = 0; i < 4; i++) {
                float a = o64[(mpt + i) * 65 + j];
                float c = mfs[(mpt + i) * 65 + j];
                u64 apk = pk2(a, a), cpk = pk2(c, c);
                fma2(acc2[i][0], apk, u0); fma2(acc2[i][0], cpk, s0);
                fma2(acc2[i][1], apk, u1); fma2(acc2[i][1], cpk, s1);
                fma2(acc2[i][2], apk, u2v); fma2(acc2[i][2], cpk, s2v);
                fma2(acc2[i][3], apk, u3); fma2(acc2[i][3], cpk, s3);
            }
        }

        float bb[8];
#pragma unroll
        for (int q = 0; q < 8; q++) bb[q] = __ldg(&bu2[o0 + q]) + __ldg(&bsc[o0 + q]);
#pragma unroll
        for (int i = 0; i < 4; i++) {
            int m = m0 + mpt + i;
            if (m < M_PTS) {
                float4 oA, oB;
                float2 v0 = upk2(acc2[i][0]); float2 v1 = upk2(acc2[i][1]);
                float2 v2 = upk2(acc2[i][2]); float2 v3 = upk2(acc2[i][3]);
                oA.x = lrelu(v0.x + bb[0]); oA.y = lrelu(v0.y + bb[1]);
                oA.z = lrelu(v1.x + bb[2]); oA.w = lrelu(v1.y + bb[3]);
                oB.x = lrelu(v2.x + bb[4]); oB.y = lrelu(v2.y + bb[5]);
                oB.z = lrelu(v3.x + bb[6]); oB.w = lrelu(v3.y + bb[7]);
                *(float4*)&out[(size_t)m * 128 + o0] = oA;
                *(float4*)&out[(size_t)m * 128 + o0 + 4] = oB;
            }
        }
    }
}

// =====================================================================
extern "C" void kernel_launch(void* const* d_in, const int* in_sizes, int n_in,
                              void* d_out, int out_size) {
    const float* dense_feats = (const float*)d_in[1];
    const float* vi          = (const float*)d_in[5];
    const int*   nei         = (const int*)d_in[6];
    const float* w_u1  = (const float*)d_in[7];  const float* b_u1  = (const float*)d_in[8];
    const float* w_gu  = (const float*)d_in[9];  const float* b_gu  = (const float*)d_in[10];
    const float* w_pe  = (const float*)d_in[11]; const float* b_pe  = (const float*)d_in[12];
    const float* w_g1  = (const float*)d_in[13]; const float* b_g1  = (const float*)d_in[14];
    const float* w_g2  = (const float*)d_in[15]; const float* b_g2  = (const float*)d_in[16];
    const float* w_wn1 = (const float*)d_in[17]; const float* b_wn1 = (const float*)d_in[18];
    const float* w_wn2 = (const float*)d_in[19]; const float* b_wn2 = (const float*)d_in[20];
    const float* w_wn3 = (const float*)d_in[21]; const float* b_wn3 = (const float*)d_in[22];
    const float* w_lin = (const float*)d_in[23]; const float* b_lin = (const float*)d_in[24];
    const float* w_u2  = (const float*)d_in[25]; const float* b_u2  = (const float*)d_in[26];
    const float* w_sc  = (const float*)d_in[27]; const float* b_sc  = (const float*)d_in[28];
    float* out = (float*)d_out;

    int smemA = (64 * 130 + 64 * 32 + 32 * 32 + 32 * 130) * 4;   // 62208 B
    cudaFuncSetAttribute(kA, cudaFuncAttributeMaxDynamicSharedMemorySize, smemA);
    kA<<<(N_PTS + 127) / 128, 256, smemA>>>(dense_feats, w_u1, b_u1, w_gu, b_gu);

    kB<<<(M_PTS + 3) / 4, 128>>>(vi, nei,
                                 w_pe, b_pe, w_g1, b_g1, w_g2, b_g2,
                                 w_wn1, b_wn1, w_wn2, b_wn2, w_wn3, b_wn3);

    int smemC = (128 * 65 + 16 * 130 + 16 * 64) * 4 > (128 * 65 * 2) * 4
                    ? (128 * 65 + 16 * 130 + 16 * 64) * 4
                    : (128 * 65 * 2) * 4;                        // 66560 B
    cudaFuncSetAttribute(kC, cudaFuncAttributeMaxDynamicSharedMemorySize, smemC);
    kC<<<(M_PTS + 127) / 128, 256, smemC>>>(w_lin, b_lin, w_u2, b_u2, w_sc, b_sc, out);
}

// round 15
// speedup vs baseline: 1.6189x; 1.0771x over previous
#include <cuda_runtime.h>
#include <cuda_fp16.h>
#include <cstdint>

#define N_PTS 200000
#define M_PTS 100000

typedef unsigned long long u64;
typedef unsigned int u32;

// ---- scratch (device-global, no allocation) ----
__device__ __half g_cat[(size_t)N_PTS * 64];         // 25.6 MB: fx[0:32] | gx[32:64]
__device__ __half g_df_h[(size_t)N_PTS * 64];        // 25.6 MB
__device__ __half g_agg_h[(size_t)M_PTS * 512];      // 102.4 MB
__device__ float  g_maxf[M_PTS * 64];                // 25.6 MB

struct __align__(16) H8 { __half2 a, b, c, d; };

// ---- packed fp32x2 helpers ----
__device__ __forceinline__ u64 pk2(float x, float y) {
    u64 r; asm("mov.b64 %0,{%1,%2};" : "=l"(r) : "f"(x), "f"(y)); return r;
}
__device__ __forceinline__ float2 upk2(u64 v) {
    float2 r; asm("mov.b64 {%0,%1},%2;" : "=f"(r.x), "=f"(r.y) : "l"(v)); return r;
}
__device__ __forceinline__ void fma2(u64& d, u64 a, u64 b) {
    asm("fma.rn.f32x2 %0,%1,%2,%3;" : "=l"(d) : "l"(a), "l"(b), "l"(d));
}
__device__ __forceinline__ float lrelu(float x) { return x > 0.f ? x : 0.1f * x; }

// =====================================================================
// Kernel A: tiled GEMM, 128 points/block, 256 threads.
// Writes fused fp16 table g_cat = [fx | gx] and fp16 df mirror.
// =====================================================================
__global__ __launch_bounds__(256) void kA(const float* __restrict__ df,
                                          const float* __restrict__ w1,
                                          const float* __restrict__ b1,
                                          const float* __restrict__ wgu,
                                          const float* __restrict__ bgu) {
    extern __shared__ float sm[];
    float* s_dfT = sm;                 // [64][130]
    float* s_w1  = s_dfT + 64 * 130;   // [64][32]
    float* s_wgu = s_w1 + 2048;        // [32][32]
    float* s_fxT = s_wgu + 1024;       // [32][130]
    __shared__ float s_b1[32], s_bgu[32];

    int tid = threadIdx.x;
    int p0 = blockIdx.x * 128;

    for (int i = tid; i < 2048; i += 256) s_w1[i] = w1[i];
    for (int i = tid; i < 1024; i += 256) s_wgu[i] = wgu[i];
    if (tid < 32) { s_b1[tid] = b1[tid]; s_bgu[tid] = bgu[tid]; }

#pragma unroll
    for (int q = 0; q < 8; q++) {
        int f4 = tid + q * 256;
        int pt = f4 >> 4, c4 = (f4 & 15) * 4;
        int p = p0 + pt;
        float4 v = (p < N_PTS) ? *(const float4*)&df[(size_t)p * 64 + c4]
                               : make_float4(0.f, 0.f, 0.f, 0.f);
        s_dfT[(c4 + 0) * 130 + pt] = v.x;
        s_dfT[(c4 + 1) * 130 + pt] = v.y;
        s_dfT[(c4 + 2) * 130 + pt] = v.z;
        s_dfT[(c4 + 3) * 130 + pt] = v.w;
        if (p < N_PTS) {
            __half2* dst = (__half2*)&g_df_h[(size_t)p * 64 + c4];
            dst[0] = __floats2half2_rn(v.x, v.y);
            dst[1] = __floats2half2_rn(v.z, v.w);
        }
    }
    __syncthreads();

    int tx = tid & 7;
    int ty = tid >> 3;

    // ---- stage 1: feats_x ----
    u64 acc[2][4];
#pragma unroll
    for (int i = 0; i < 2; i++)
#pragma unroll
        for (int j = 0; j < 4; j++) acc[i][j] = 0ull;

#pragma unroll 8
    for (int kk = 0; kk < 64; kk++) {
        const float* ar = &s_dfT[kk * 130 + ty * 4];
        u64 a01 = *(const u64*)(ar);
        u64 a23 = *(const u64*)(ar + 2);
        float4 bv = *(const float4*)&s_w1[kk * 32 + tx * 4];
        u64 b0 = pk2(bv.x, bv.x), b1p = pk2(bv.y, bv.y);
        u64 b2 = pk2(bv.z, bv.z), b3p = pk2(bv.w, bv.w);
        fma2(acc[0][0], a01, b0); fma2(acc[0][1], a01, b1p);
        fma2(acc[0][2], a01, b2); fma2(acc[0][3], a01, b3p);
        fma2(acc[1][0], a23, b0); fma2(acc[1][1], a23, b1p);
        fma2(acc[1][2], a23, b2); fma2(acc[1][3], a23, b3p);
    }

    float fx[4][4];
#pragma unroll
    for (int pp = 0; pp < 2; pp++)
#pragma unroll
        for (int j = 0; j < 4; j++) {
            float2 v = upk2(acc[pp][j]);
            float bb = s_b1[tx * 4 + j];
            fx[2 * pp][j] = lrelu(v.x + bb);
            fx[2 * pp + 1][j] = lrelu(v.y + bb);
        }
#pragma unroll
    for (int i = 0; i < 4; i++) {
        int pt = ty * 4 + i;
#pragma unroll
        for (int j = 0; j < 4; j++) s_fxT[(tx * 4 + j) * 130 + pt] = fx[i][j];
        int p = p0 + pt;
        if (p < N_PTS) {      // fx -> g_cat[p][tx*4 .. +4)
            __half2* dst = (__half2*)&g_cat[(size_t)p * 64 + tx * 4];
            dst[0] = __floats2half2_rn(fx[i][0], fx[i][1]);
            dst[1] = __floats2half2_rn(fx[i][2], fx[i][3]);
        }
    }
    __syncthreads();

    // ---- stage 2: guid_x ----
    u64 acc2[2][4];
#pragma unroll
    for (int i = 0; i < 2; i++)
#pragma unroll
        for (int j = 0; j < 4; j++) acc2[i][j] = 0ull;

#pragma unroll 8
    for (int kk = 0; kk < 32; kk++) {
        const float* ar = &s_fxT[kk * 130 + ty * 4];
        u64 a01 = *(const u64*)(ar);
        u64 a23 = *(const u64*)(ar + 2);
        float4 bv = *(const float4*)&s_wgu[kk * 32 + tx * 4];
        u64 b0 = pk2(bv.x, bv.x), b1p = pk2(bv.y, bv.y);
        u64 b2 = pk2(bv.z, bv.z), b3p = pk2(bv.w, bv.w);
        fma2(acc2[0][0], a01, b0); fma2(acc2[0][1], a01, b1p);
        fma2(acc2[0][2], a01, b2); fma2(acc2[0][3], a01, b3p);
        fma2(acc2[1][0], a23, b0); fma2(acc2[1][1], a23, b1p);
        fma2(acc2[1][2], a23, b2); fma2(acc2[1][3], a23, b3p);
    }
#pragma unroll
    for (int pp = 0; pp < 2; pp++) {
#pragma unroll
        for (int i = 0; i < 2; i++) {
            int pt = ty * 4 + 2 * pp + i;
            int p = p0 + pt;
            if (p < N_PTS) {   // gx -> g_cat[p][32 + tx*4 .. +4)
                float2 v0 = upk2(acc2[pp][0]); float2 v1 = upk2(acc2[pp][1]);
                float2 v2 = upk2(acc2[pp][2]); float2 v3 = upk2(acc2[pp][3]);
                float o0 = (i ? v0.y : v0.x) + s_bgu[tx * 4 + 0];
                float o1 = (i ? v1.y : v1.x) + s_bgu[tx * 4 + 1];
                float o2 = (i ? v2.y : v2.x) + s_bgu[tx * 4 + 2];
                float o3 = (i ? v3.y : v3.x) + s_bgu[tx * 4 + 3];
                __half2* dst = (__half2*)&g_cat[(size_t)p * 64 + 32 + tx * 4];
                dst[0] = __floats2half2_rn(o0, o1);
                dst[1] = __floats2half2_rn(o2, o3);
            }
        }
    }
}

// =====================================================================
// Kernel B v4: warp-per-point.
//  - ALL 32 gather loads (16 k x 2 fused tables) front-issued: MLP=32,
//    each load = 1 uint/lane = one full 128B line per warp.
//  - lane<16 redistributes fx pairs, lane>=16 gg pairs; maxes in regs.
//  - phase 2 unchanged (hmax bias fold, unroll 4).
// =====================================================================
__global__ __launch_bounds__(128) void kB(
    const float* __restrict__ vi, const int* __restrict__ nei,
    const float* __restrict__ wpe, const float* __restrict__ bpe,
    const float* __restrict__ wg1, const float* __restrict__ bg1,
    const float* __restrict__ wg2, const float* __restrict__ bg2,
    const float* __restrict__ wn1, const float* __restrict__ bn1,
    const float* __restrict__ wn2, const float* __restrict__ bn2,
    const float* __restrict__ wn3, const float* __restrict__ bn3) {
    __shared__ float s_wpe[384], s_bpe[32];
    __shared__ float s_wg1p[544], s_bg1[8], s_wg2[64], s_bg2[8];
    __shared__ float s_w1[96], s_b1[8], s_w2[64], s_b2[8], s_w3[128], s_b3[16];
    __shared__ __align__(16) float s_vi[4][192];
    __shared__ __align__(16) float s_gfeat[4][1024];
    __shared__ __align__(16) float s_gf[4][512];
    __shared__ __align__(16) float s_wn[4][256];
    __shared__ __align__(16) float s_gmax[4][64];
    __shared__ int s_idx[4][16];

    int tid = threadIdx.x;
    for (int i = tid; i < 384; i += 128) s_wpe[i] = wpe[i];
    for (int i = tid; i < 512; i += 128) {
        int c = i >> 3, h2 = i & 7;
        s_wg1p[(c >> 4) * 136 + (c & 15) * 8 + h2] = wg1[i];
    }
    if (tid < 64)  s_wg2[tid] = wg2[tid];
    if (tid < 96)  s_w1[tid] = wn1[tid];
    if (tid < 64)  s_w2[tid] = wn2[tid];
    if (tid < 128) s_w3[tid] = wn3[tid];
    if (tid < 32)  s_bpe[tid] = bpe[tid];
    if (tid < 8) { s_bg1[tid] = bg1[tid]; s_bg2[tid] = bg2[tid];
                   s_b1[tid] = bn1[tid]; s_b2[tid] = bn2[tid]; }
    if (tid < 16) s_b3[tid] = bn3[tid];
    __syncthreads();

    int lane = tid & 31, w = tid >> 5;
    int m = blockIdx.x * 4 + w;
    if (m >= M_PTS) return;

    for (int i = lane; i < 48; i += 32)
        *(float4*)&s_vi[w][i * 4] = *(const float4*)&vi[(size_t)m * 192 + i * 4];
    if (lane < 16) s_idx[w][lane] = nei[m * 16 + lane];
    __syncwarp();

    // ---------- front-issue ALL 32 gather loads (full 128B lines) ----------
    u32 t1[16], td[16];
    {
        const u32* catp = (const u32*)g_cat;
        const u32* dfp  = (const u32*)g_df_h;
#pragma unroll
        for (int k = 0; k < 16; k++) {
            size_t n32 = (size_t)s_idx[w][k] * 32 + lane;
            t1[k] = __ldg(&catp[n32]);
            td[k] = __ldg(&dfp[n32]);
        }
    }

    // ---------- WeightNet, vectorized over k (overlaps gather latency) ----------
    {
        int kk = lane >> 1, half = lane & 1;
        const float* vk = &s_vi[w][kk * 12];
        float4 va = *(const float4*)vk;
        float4 vb = *(const float4*)(vk + 4);
        float4 vc = *(const float4*)(vk + 8);
        float vr[12] = {va.x, va.y, va.z, va.w, vb.x, vb.y, vb.z, vb.w,
                        vc.x, vc.y, vc.z, vc.w};
        float h1[4];
#pragma unroll
        for (int i = 0; i < 4; i++) {
            int o = half * 4 + i;
            float a = s_b1[o];
#pragma unroll
            for (int j = 0; j < 12; j++) a = fmaf(vr[j], s_w1[j * 8 + o], a);
            h1[i] = fmaxf(a, 0.f);
        }
        float oth[4];
#pragma unroll
        for (int i = 0; i < 4; i++) oth[i] = __shfl_xor_sync(~0u, h1[i], 1);
        float h1a[8];
#pragma unroll
        for (int j = 0; j < 8; j++)
            h1a[j] = ((j >> 2) == half) ? h1[j & 3] : oth[j & 3];

        float h2[4];
#pragma unroll
        for (int i = 0; i < 4; i++) {
            int o = half * 4 + i;
            float a = s_b2[o];
#pragma unroll
            for (int j = 0; j < 8; j++) a = fmaf(h1a[j], s_w2[j * 8 + o], a);
            h2[i] = fmaxf(a, 0.f);
        }
#pragma unroll
        for (int i = 0; i < 4; i++) oth[i] = __shfl_xor_sync(~0u, h2[i], 1);
        float h2a[8];
#pragma unroll
        for (int j = 0; j < 8; j++)
            h2a[j] = ((j >> 2) == half) ? h2[j & 3] : oth[j & 3];

        float w16[8];
#pragma unroll
        for (int q = 0; q < 8; q++) {
            int o = half * 8 + q;
            float a = s_b3[o];
#pragma unroll
            for (int j = 0; j < 8; j++) a = fmaf(h2a[j], s_w3[j * 16 + o], a);
            w16[q] = fmaxf(a, 0.f);
        }
        float* dst = &s_wn[w][kk * 16 + half * 8];
        *(float4*)dst = make_float4(w16[0], w16[1], w16[2], w16[3]);
        *(float4*)(dst + 4) = make_float4(w16[4], w16[5], w16[6], w16[7]);
    }

    // hoisted PE weights (per-lane column)
    float wpe_r[12];
#pragma unroll
    for (int j = 0; j < 12; j++) wpe_r[j] = s_wpe[j * 32 + lane];
    float bpe_r = s_bpe[lane];

    // ---------- consume gathers: redistribute + maxes + PE ----------
    float2 msc = make_float2(-1e30f, -1e30f);   // df shortcut max (2 ch/lane)
    float2 mgg = make_float2(-1e30f, -1e30f);   // gg max (lanes>=16, 2 ch/lane)
    float gmax1 = -1e30f;                        // pe max (1 ch/lane)
    bool hi = lane >= 16;
    int c2i = 2 * (lane & 15);

#pragma unroll
    for (int k = 0; k < 16; k++) {
        float2 fd = __half22float2(*(__half2*)&td[k]);
        msc.x = fmaxf(msc.x, fd.x); msc.y = fmaxf(msc.y, fd.y);

        float2 f1 = __half22float2(*(__half2*)&t1[k]);
        if (hi) {
            *(float2*)&s_gfeat[w][k * 64 + c2i] = f1;   // gg pair
            mgg.x = fmaxf(mgg.x, f1.x); mgg.y = fmaxf(mgg.y, f1.y);
        } else {
            *(float2*)&s_gf[w][k * 32 + c2i] = f1;      // fx pair
        }

        const float* vk = &s_vi[w][k * 12];
        float pe = bpe_r;
#pragma unroll
        for (int j = 0; j < 12; j++) pe = fmaf(vk[j], wpe_r[j], pe);
        pe = fmaxf(pe, 0.f);
        s_gfeat[w][k * 64 + 32 + lane] = pe;
        gmax1 = fmaxf(gmax1, pe);
    }
    if (hi) *(float2*)&s_gmax[w][c2i] = mgg;
    s_gmax[w][32 + lane] = gmax1;
    *(float2*)&g_maxf[(size_t)m * 64 + 2 * lane] = msc;
    __syncwarp();

    // ---------- Phase 2: scores + weighted einsum ----------
    int h = lane & 7;
    int g = lane >> 3;
    u64 wg1p[8];
    const float* wg1g = &s_wg1p[g * 136];
#pragma unroll
    for (int c2 = 0; c2 < 8; c2++)
        wg1p[c2] = pk2(wg1g[(2 * c2) * 8 + h], wg1g[(2 * c2 + 1) * 8 + h]);
    float wg2r[8];
#pragma unroll
    for (int j = 0; j < 8; j++) wg2r[j] = s_wg2[j * 8 + h];
    float bg1r = s_bg1[h], bg2r = s_bg2[h];

    // hmax fold: dot(gfeat - gmax, w) = dot(gfeat, w) - dot(gmax, w)
    {
        u64 hmp = 0ull;
        const u64* gmp = (const u64*)&s_gmax[w][g * 16];
#pragma unroll
        for (int c2 = 0; c2 < 8; c2++) fma2(hmp, gmp[c2], wg1p[c2]);
        float2 hmv = upk2(hmp);
        float hmax = hmv.x + hmv.y;
        hmax += __shfl_xor_sync(~0u, hmax, 8);
        hmax += __shfl_xor_sync(~0u, hmax, 16);
        bg1r -= hmax;
    }

    u64 accp[8];
#pragma unroll
    for (int i = 0; i < 8; i++) accp[i] = 0ull;

#pragma unroll 4
    for (int k = 0; k < 16; k++) {
        u64 hp = 0ull;
        const u64* gp = (const u64*)&s_gfeat[w][k * 64 + g * 16];
#pragma unroll
        for (int c2 = 0; c2 < 8; c2++) fma2(hp, gp[c2], wg1p[c2]);
        float2 hv = upk2(hp);
        float hid = hv.x + hv.y;
        hid += __shfl_xor_sync(~0u, hid, 8);
        hid += __shfl_xor_sync(~0u, hid, 16);
        hid = fmaxf(hid + bg1r, 0.f);

        float scz = bg2r;
#pragma unroll
        for (int j = 0; j < 8; j++)
            scz = fmaf(__shfl_sync(~0u, hid, j), wg2r[j], scz);
        float score = 1.f / (1.f + __expf(-scz));

        float sC = __shfl_sync(~0u, score, lane >> 2);
        float nf = s_gf[w][k * 32 + lane] * sC;
        u64 nfp = pk2(nf, nf);
        const u64* wp = (const u64*)&s_wn[w][k * 16];
#pragma unroll
        for (int q2 = 0; q2 < 8; q2++) fma2(accp[q2], nfp, wp[q2]);
    }

    // fp16 agg: lane writes 16 halves = 32B (2x STG.128)
    {
        size_t base = (size_t)m * 512 + lane * 16;
        float2 v0 = upk2(accp[0]), v1 = upk2(accp[1]);
        float2 v2 = upk2(accp[2]), v3 = upk2(accp[3]);
        H8 o0;
        o0.a = __floats2half2_rn(v0.x, v0.y); o0.b = __floats2half2_rn(v1.x, v1.y);
        o0.c = __floats2half2_rn(v2.x, v2.y); o0.d = __floats2half2_rn(v3.x, v3.y);
        *(H8*)&g_agg_h[base] = o0;
        float2 v4 = upk2(accp[4]), v5 = upk2(accp[5]);
        float2 v6 = upk2(accp[6]), v7 = upk2(accp[7]);
        H8 o1;
        o1.a = __floats2half2_rn(v4.x, v4.y); o1.b = __floats2half2_rn(v5.x, v5.y);
        o1.c = __floats2half2_rn(v6.x, v6.y); o1.d = __floats2half2_rn(v7.x, v7.y);
        *(H8*)&g_agg_h[base + 8] = o1;
    }
}

// =====================================================================
// Kernel C: BM=128, BN=64, BK=16, 256 threads, fp16 A-loads, f32x2 FMAs.
// smem union, 3 blocks/SM, two-pass epilogue. (unchanged)
// =====================================================================
__global__ __launch_bounds__(256, 3) void kC(
    const float* __restrict__ wlin, const float* __restrict__ blin,
    const float* __restrict__ wu2, const float* __restrict__ bu2,
    const float* __restrict__ wsc, const float* __restrict__ bsc,
    float* __restrict__ out) {
    extern __shared__ float sm[];
    float* o64 = sm;                 // [128][65]
    float* AsT = sm + 128 * 65;      // [16][130]  (aliases mfs)
    float* Bs  = AsT + 16 * 130;     // [16][64]
    float* mfs = sm + 128 * 65;      // [128][65]  (epilogue only)

    int tid = threadIdx.x;
    int m0 = blockIdx.x * 128;

    int pt = tid >> 1, c8 = (tid & 1) * 8;
    bool av = (m0 + pt) < M_PTS;
    const __half* ap = &g_agg_h[(size_t)(m0 + (av ? pt : 0)) * 512 + c8];
    int rb = tid >> 4, cb = (tid & 15) * 4;
    const float* bp = &wlin[rb * 64 + cb];

    int tx = tid & 15;
    int ty = tid >> 4;

    u64 accp[4][4];
#pragma unroll
    for (int i = 0; i < 4; i++)
#pragma unroll
        for (int j = 0; j < 4; j++) accp[i][j] = 0ull;

    uint4 ra = av ? *(const uint4*)ap : make_uint4(0, 0, 0, 0);
    float4 rbv = *(const float4*)bp;

    for (int kb = 0; kb < 32; kb++) {
        {
            __half2* hp = (__half2*)&ra;
            float2 f0 = __half22float2(hp[0]); float2 f1 = __half22float2(hp[1]);
            float2 f2 = __half22float2(hp[2]); float2 f3 = __half22float2(hp[3]);
            AsT[(c8 + 0) * 130 + pt] = f0.x; AsT[(c8 + 1) * 130 + pt] = f0.y;
            AsT[(c8 + 2) * 130 + pt] = f1.x; AsT[(c8 + 3) * 130 + pt] = f1.y;
            AsT[(c8 + 4) * 130 + pt] = f2.x; AsT[(c8 + 5) * 130 + pt] = f2.y;
            AsT[(c8 + 6) * 130 + pt] = f3.x; AsT[(c8 + 7) * 130 + pt] = f3.y;
        }
        *(float4*)&Bs[rb * 64 + cb] = rbv;
        __syncthreads();

        if (kb < 31) {
            ra = av ? *(const uint4*)(ap + (kb + 1) * 16) : make_uint4(0, 0, 0, 0);
            rbv = *(const float4*)(bp + (kb + 1) * 16 * 64);
        }

#pragma unroll
        for (int kk = 0; kk < 16; kk++) {
            const float* ar = &AsT[kk * 130 + ty * 8];
            u64 a01 = *(const u64*)(ar);
            u64 a23 = *(const u64*)(ar + 2);
            u64 a45 = *(const u64*)(ar + 4);
            u64 a67 = *(const u64*)(ar + 6);
            float4 bv = *(const float4*)&Bs[kk * 64 + tx * 4];
            u64 b0 = pk2(bv.x, bv.x), b1p = pk2(bv.y, bv.y);
            u64 b2 = pk2(bv.z, bv.z), b3p = pk2(bv.w, bv.w);
            fma2(accp[0][0], a01, b0); fma2(accp[0][1], a01, b1p);
            fma2(accp[0][2], a01, b2); fma2(accp[0][3], a01, b3p);
            fma2(accp[1][0], a23, b0); fma2(accp[1][1], a23, b1p);
            fma2(accp[1][2], a23, b2); fma2(accp[1][3], a23, b3p);
            fma2(accp[2][0], a45, b0); fma2(accp[2][1], a45, b1p);
            fma2(accp[2][2], a45, b2); fma2(accp[2][3], a45, b3p);
            fma2(accp[3][0], a67, b0); fma2(accp[3][1], a67, b1p);
            fma2(accp[3][2], a67, b2); fma2(accp[3][3], a67, b3p);
        }
        __syncthreads();
    }

    {
        float blr[4];
#pragma unroll
        for (int j = 0; j < 4; j++) blr[j] = __ldg(&blin[tx * 4 + j]);
#pragma unroll
        for (int ip = 0; ip < 4; ip++)
#pragma unroll
            for (int j = 0; j < 4; j++) {
                float2 v = upk2(accp[ip][j]);
                o64[(ty * 8 + 2 * ip) * 65 + tx * 4 + j] = fmaxf(v.x + blr[j], 0.f);
                o64[(ty * 8 + 2 * ip + 1) * 65 + tx * 4 + j] = fmaxf(v.y + blr[j], 0.f);
            }
    }

#pragma unroll
    for (int q = 0; q < 8; q++) {
        int f4 = tid + q * 256;
        int ptq = f4 >> 4, c4 = (f4 & 15) * 4;
        int mm = m0 + ptq;
        float4 v = (mm < M_PTS) ? *(const float4*)&g_maxf[(size_t)mm * 64 + c4]
                                : make_float4(0.f, 0.f, 0.f, 0.f);
        mfs[ptq * 65 + c4 + 0] = v.x; mfs[ptq * 65 + c4 + 1] = v.y;
        mfs[ptq * 65 + c4 + 2] = v.z; mfs[ptq * 65 + c4 + 3] = v.w;
    }
    __syncthreads();

    int o0 = (tid & 15) * 8;
#pragma unroll
    for (int pass = 0; pass < 2; pass++) {
        int mpt = (tid >> 4) * 8 + pass * 4;
        u64 acc2[4][4];
#pragma unroll
        for (int i = 0; i < 4; i++)
#pragma unroll
            for (int c = 0; c < 4; c++) acc2[i][c] = 0ull;

        for (int j = 0; j < 64; j++) {
            const u64* pu = (const u64*)&wu2[j * 128 + o0];
            const u64* ps = (const u64*)&wsc[j * 128 + o0];
            u64 u0 = __ldg(pu), u1 = __ldg(pu + 1), u2v = __ldg(pu + 2), u3 = __ldg(pu + 3);
            u64 s0 = __ldg(ps), s1 = __ldg(ps + 1), s2v = __ldg(ps + 2), s3 = __ldg(ps + 3);
#pragma unroll
            for (int i = 0; i < 4; i++) {
                float a = o64[(mpt + i) * 65 + j];
                float c = mfs[(mpt + i) * 65 + j];
                u64 apk = pk2(a, a), cpk = pk2(c, c);
                fma2(acc2[i][0], apk, u0); fma2(acc2[i][0], cpk, s0);
                fma2(acc2[i][1], apk, u1); fma2(acc2[i][1], cpk, s1);
                fma2(acc2[i][2], apk, u2v); fma2(acc2[i][2], cpk, s2v);
                fma2(acc2[i][3], apk, u3); fma2(acc2[i][3], cpk, s3);
            }
        }

        float bb[8];
#pragma unroll
        for (int q = 0; q < 8; q++) bb[q] = __ldg(&bu2[o0 + q]) + __ldg(&bsc[o0 + q]);
#pragma unroll
        for (int i = 0; i < 4; i++) {
            int m = m0 + mpt + i;
            if (m < M_PTS) {
                float4 oA, oB;
                float2 v0 = upk2(acc2[i][0]); float2 v1 = upk2(acc2[i][1]);
                float2 v2 = upk2(acc2[i][2]); float2 v3 = upk2(acc2[i][3]);
                oA.x = lrelu(v0.x + bb[0]); oA.y = lrelu(v0.y + bb[1]);
                oA.z = lrelu(v1.x + bb[2]); oA.w = lrelu(v1.y + bb[3]);
                oB.x = lrelu(v2.x + bb[4]); oB.y = lrelu(v2.y + bb[5]);
                oB.z = lrelu(v3.x + bb[6]); oB.w = lrelu(v3.y + bb[7]);
                *(float4*)&out[(size_t)m * 128 + o0] = oA;
                *(float4*)&out[(size_t)m * 128 + o0 + 4] = oB;
            }
        }
    }
}

// =====================================================================
extern "C" void kernel_launch(void* const* d_in, const int* in_sizes, int n_in,
                              void* d_out, int out_size) {
    const float* dense_feats = (const float*)d_in[1];
    const float* vi          = (const float*)d_in[5];
    const int*   nei         = (const int*)d_in[6];
    const float* w_u1  = (const float*)d_in[7];  const float* b_u1  = (const float*)d_in[8];
    const float* w_gu  = (const float*)d_in[9];  const float* b_gu  = (const float*)d_in[10];
    const float* w_pe  = (const float*)d_in[11]; const float* b_pe  = (const float*)d_in[12];
    const float* w_g1  = (const float*)d_in[13]; const float* b_g1  = (const float*)d_in[14];
    const float* w_g2  = (const float*)d_in[15]; const float* b_g2  = (const float*)d_in[16];
    const float* w_wn1 = (const float*)d_in[17]; const float* b_wn1 = (const float*)d_in[18];
    const float* w_wn2 = (const float*)d_in[19]; const float* b_wn2 = (const float*)d_in[20];
    const float* w_wn3 = (const float*)d_in[21]; const float* b_wn3 = (const float*)d_in[22];
    const float* w_lin = (const float*)d_in[23]; const float* b_lin = (const float*)d_in[24];
    const float* w_u2  = (const float*)d_in[25]; const float* b_u2  = (const float*)d_in[26];
    const float* w_sc  = (const float*)d_in[27]; const float* b_sc  = (const float*)d_in[28];
    float* out = (float*)d_out;

    int smemA = (64 * 130 + 64 * 32 + 32 * 32 + 32 * 130) * 4;   // 62208 B
    cudaFuncSetAttribute(kA, cudaFuncAttributeMaxDynamicSharedMemorySize, smemA);
    kA<<<(N_PTS + 127) / 128, 256, smemA>>>(dense_feats, w_u1, b_u1, w_gu, b_gu);

    kB<<<(M_PTS + 3) / 4, 128>>>(vi, nei,
                                 w_pe, b_pe, w_g1, b_g1, w_g2, b_g2,
                                 w_wn1, b_wn1, w_wn2, b_wn2, w_wn3, b_wn3);

    int smemC = (128 * 65 + 16 * 130 + 16 * 64) * 4 > (128 * 65 * 2) * 4
                    ? (128 * 65 + 16 * 130 + 16 * 64) * 4
                    : (128 * 65 * 2) * 4;                        // 66560 B
    cudaFuncSetAttribute(kC, cudaFuncAttributeMaxDynamicSharedMemorySize, smemC);
    kC<<<(M_PTS + 127) / 128, 256, smemC>>>(w_lin, b_lin, w_u2, b_u2, w_sc, b_sc, out);
}

// round 16
// speedup vs baseline: 2.3290x; 1.4386x over previous
#include <cuda_runtime.h>
#include <cuda_fp16.h>
#include <cstdint>

#define N_PTS 200000
#define M_PTS 100000

typedef unsigned long long u64;
typedef unsigned int u32;

// ---- scratch (device-global, no allocation) ----
__device__ __half g_cat[(size_t)N_PTS * 64];         // 25.6 MB: fx[0:32] | gx[32:64]
__device__ __half g_df_h[(size_t)N_PTS * 64];        // 25.6 MB
__device__ __half g_agg_h[(size_t)M_PTS * 512];      // 102.4 MB
__device__ float  g_maxf[M_PTS * 64];                // 25.6 MB

struct __align__(16) H8 { __half2 a, b, c, d; };

// ---- packed fp32x2 helpers ----
__device__ __forceinline__ u64 pk2(float x, float y) {
    u64 r; asm("mov.b64 %0,{%1,%2};" : "=l"(r) : "f"(x), "f"(y)); return r;
}
__device__ __forceinline__ float2 upk2(u64 v) {
    float2 r; asm("mov.b64 {%0,%1},%2;" : "=f"(r.x), "=f"(r.y) : "l"(v)); return r;
}
__device__ __forceinline__ void fma2(u64& d, u64 a, u64 b) {
    asm("fma.rn.f32x2 %0,%1,%2,%3;" : "=l"(d) : "l"(a), "l"(b), "l"(d));
}
__device__ __forceinline__ float lrelu(float x) { return x > 0.f ? x : 0.1f * x; }

// ---- tensor core mma m16n8k16 fp16 -> fp32 ----
__device__ __forceinline__ void mma16816(float* c, u32 a0, u32 a1, u32 a2, u32 a3,
                                         u32 b0, u32 b1) {
    asm volatile(
        "mma.sync.aligned.m16n8k16.row.col.f32.f16.f16.f32 "
        "{%0,%1,%2,%3}, {%4,%5,%6,%7}, {%8,%9}, {%0,%1,%2,%3};"
        : "+f"(c[0]), "+f"(c[1]), "+f"(c[2]), "+f"(c[3])
        : "r"(a0), "r"(a1), "r"(a2), "r"(a3), "r"(b0), "r"(b1));
}

// =====================================================================
// Kernel A: tiled GEMM, 128 points/block, 256 threads. (unchanged)
// =====================================================================
__global__ __launch_bounds__(256) void kA(const float* __restrict__ df,
                                          const float* __restrict__ w1,
                                          const float* __restrict__ b1,
                                          const float* __restrict__ wgu,
                                          const float* __restrict__ bgu) {
    extern __shared__ float sm[];
    float* s_dfT = sm;                 // [64][130]
    float* s_w1  = s_dfT + 64 * 130;   // [64][32]
    float* s_wgu = s_w1 + 2048;        // [32][32]
    float* s_fxT = s_wgu + 1024;       // [32][130]
    __shared__ float s_b1[32], s_bgu[32];

    int tid = threadIdx.x;
    int p0 = blockIdx.x * 128;

    for (int i = tid; i < 2048; i += 256) s_w1[i] = w1[i];
    for (int i = tid; i < 1024; i += 256) s_wgu[i] = wgu[i];
    if (tid < 32) { s_b1[tid] = b1[tid]; s_bgu[tid] = bgu[tid]; }

#pragma unroll
    for (int q = 0; q < 8; q++) {
        int f4 = tid + q * 256;
        int pt = f4 >> 4, c4 = (f4 & 15) * 4;
        int p = p0 + pt;
        float4 v = (p < N_PTS) ? *(const float4*)&df[(size_t)p * 64 + c4]
                               : make_float4(0.f, 0.f, 0.f, 0.f);
        s_dfT[(c4 + 0) * 130 + pt] = v.x;
        s_dfT[(c4 + 1) * 130 + pt] = v.y;
        s_dfT[(c4 + 2) * 130 + pt] = v.z;
        s_dfT[(c4 + 3) * 130 + pt] = v.w;
        if (p < N_PTS) {
            __half2* dst = (__half2*)&g_df_h[(size_t)p * 64 + c4];
            dst[0] = __floats2half2_rn(v.x, v.y);
            dst[1] = __floats2half2_rn(v.z, v.w);
        }
    }
    __syncthreads();

    int tx = tid & 7;
    int ty = tid >> 3;

    u64 acc[2][4];
#pragma unroll
    for (int i = 0; i < 2; i++)
#pragma unroll
        for (int j = 0; j < 4; j++) acc[i][j] = 0ull;

#pragma unroll 8
    for (int kk = 0; kk < 64; kk++) {
        const float* ar = &s_dfT[kk * 130 + ty * 4];
        u64 a01 = *(const u64*)(ar);
        u64 a23 = *(const u64*)(ar + 2);
        float4 bv = *(const float4*)&s_w1[kk * 32 + tx * 4];
        u64 b0 = pk2(bv.x, bv.x), b1p = pk2(bv.y, bv.y);
        u64 b2 = pk2(bv.z, bv.z), b3p = pk2(bv.w, bv.w);
        fma2(acc[0][0], a01, b0); fma2(acc[0][1], a01, b1p);
        fma2(acc[0][2], a01, b2); fma2(acc[0][3], a01, b3p);
        fma2(acc[1][0], a23, b0); fma2(acc[1][1], a23, b1p);
        fma2(acc[1][2], a23, b2); fma2(acc[1][3], a23, b3p);
    }

    float fx[4][4];
#pragma unroll
    for (int pp = 0; pp < 2; pp++)
#pragma unroll
        for (int j = 0; j < 4; j++) {
            float2 v = upk2(acc[pp][j]);
            float bb = s_b1[tx * 4 + j];
            fx[2 * pp][j] = lrelu(v.x + bb);
            fx[2 * pp + 1][j] = lrelu(v.y + bb);
        }
#pragma unroll
    for (int i = 0; i < 4; i++) {
        int pt = ty * 4 + i;
#pragma unroll
        for (int j = 0; j < 4; j++) s_fxT[(tx * 4 + j) * 130 + pt] = fx[i][j];
        int p = p0 + pt;
        if (p < N_PTS) {
            __half2* dst = (__half2*)&g_cat[(size_t)p * 64 + tx * 4];
            dst[0] = __floats2half2_rn(fx[i][0], fx[i][1]);
            dst[1] = __floats2half2_rn(fx[i][2], fx[i][3]);
        }
    }
    __syncthreads();

    u64 acc2[2][4];
#pragma unroll
    for (int i = 0; i < 2; i++)
#pragma unroll
        for (int j = 0; j < 4; j++) acc2[i][j] = 0ull;

#pragma unroll 8
    for (int kk = 0; kk < 32; kk++) {
        const float* ar = &s_fxT[kk * 130 + ty * 4];
        u64 a01 = *(const u64*)(ar);
        u64 a23 = *(const u64*)(ar + 2);
        float4 bv = *(const float4*)&s_wgu[kk * 32 + tx * 4];
        u64 b0 = pk2(bv.x, bv.x), b1p = pk2(bv.y, bv.y);
        u64 b2 = pk2(bv.z, bv.z), b3p = pk2(bv.w, bv.w);
        fma2(acc2[0][0], a01, b0); fma2(acc2[0][1], a01, b1p);
        fma2(acc2[0][2], a01, b2); fma2(acc2[0][3], a01, b3p);
        fma2(acc2[1][0], a23, b0); fma2(acc2[1][1], a23, b1p);
        fma2(acc2[1][2], a23, b2); fma2(acc2[1][3], a23, b3p);
    }
#pragma unroll
    for (int pp = 0; pp < 2; pp++) {
#pragma unroll
        for (int i = 0; i < 2; i++) {
            int pt = ty * 4 + 2 * pp + i;
            int p = p0 + pt;
            if (p < N_PTS) {
                float2 v0 = upk2(acc2[pp][0]); float2 v1 = upk2(acc2[pp][1]);
                float2 v2 = upk2(acc2[pp][2]); float2 v3 = upk2(acc2[pp][3]);
                float o0 = (i ? v0.y : v0.x) + s_bgu[tx * 4 + 0];
                float o1 = (i ? v1.y : v1.x) + s_bgu[tx * 4 + 1];
                float o2 = (i ? v2.y : v2.x) + s_bgu[tx * 4 + 2];
                float o3 = (i ? v3.y : v3.x) + s_bgu[tx * 4 + 3];
                __half2* dst = (__half2*)&g_cat[(size_t)p * 64 + 32 + tx * 4];
                dst[0] = __floats2half2_rn(o0, o1);
                dst[1] = __floats2half2_rn(o2, o3);
            }
        }
    }
}

// =====================================================================
// Kernel B v5: warp-per-point; phase 2 de-serialized via smem hid/score.
// =====================================================================
__global__ __launch_bounds__(128) void kB(
    const float* __restrict__ vi, const int* __restrict__ nei,
    const float* __restrict__ wpe, const float* __restrict__ bpe,
    const float* __restrict__ wg1, const float* __restrict__ bg1,
    const float* __restrict__ wg2, const float* __restrict__ bg2,
    const float* __restrict__ wn1, const float* __restrict__ bn1,
    const float* __restrict__ wn2, const float* __restrict__ bn2,
    const float* __restrict__ wn3, const float* __restrict__ bn3) {
    __shared__ float s_wpe[384], s_bpe[32];
    __shared__ float s_wg1p[544], s_bg1[8], s_wg2[64], s_bg2[8];
    __shared__ float s_w1[96], s_b1[8], s_w2[64], s_b2[8], s_w3[128], s_b3[16];
    __shared__ __align__(16) float s_vi[4][192];
    __shared__ __align__(16) float s_gfeat[4][1024];
    __shared__ __align__(16) float s_gf[4][512];
    __shared__ __align__(16) float s_wn[4][256];
    __shared__ __align__(16) float s_gmax[4][64];
    __shared__ __align__(8)  float s_hid[4][128];
    __shared__ __align__(8)  float s_sc[4][128];
    __shared__ int s_idx[4][16];

    int tid = threadIdx.x;
    for (int i = tid; i < 384; i += 128) s_wpe[i] = wpe[i];
    for (int i = tid; i < 512; i += 128) {
        int c = i >> 3, h2 = i & 7;
        s_wg1p[(c >> 4) * 136 + (c & 15) * 8 + h2] = wg1[i];
    }
    if (tid < 64)  s_wg2[tid] = wg2[tid];
    if (tid < 96)  s_w1[tid] = wn1[tid];
    if (tid < 64)  s_w2[tid] = wn2[tid];
    if (tid < 128) s_w3[tid] = wn3[tid];
    if (tid < 32)  s_bpe[tid] = bpe[tid];
    if (tid < 8) { s_bg1[tid] = bg1[tid]; s_bg2[tid] = bg2[tid];
                   s_b1[tid] = bn1[tid]; s_b2[tid] = bn2[tid]; }
    if (tid < 16) s_b3[tid] = bn3[tid];
    __syncthreads();

    int lane = tid & 31, w = tid >> 5;
    int m = blockIdx.x * 4 + w;
    if (m >= M_PTS) return;

    for (int i = lane; i < 48; i += 32)
        *(float4*)&s_vi[w][i * 4] = *(const float4*)&vi[(size_t)m * 192 + i * 4];
    if (lane < 16) s_idx[w][lane] = nei[m * 16 + lane];
    __syncwarp();

    // ---------- front-issue ALL 32 gather loads (full 128B lines) ----------
    u32 t1[16], td[16];
    {
        const u32* catp = (const u32*)g_cat;
        const u32* dfp  = (const u32*)g_df_h;
#pragma unroll
        for (int k = 0; k < 16; k++) {
            size_t n32 = (size_t)s_idx[w][k] * 32 + lane;
            t1[k] = __ldg(&catp[n32]);
            td[k] = __ldg(&dfp[n32]);
        }
    }

    // ---------- WeightNet, vectorized over k (overlaps gather latency) ----------
    {
        int kk = lane >> 1, half = lane & 1;
        const float* vk = &s_vi[w][kk * 12];
        float4 va = *(const float4*)vk;
        float4 vb = *(const float4*)(vk + 4);
        float4 vc = *(const float4*)(vk + 8);
        float vr[12] = {va.x, va.y, va.z, va.w, vb.x, vb.y, vb.z, vb.w,
                        vc.x, vc.y, vc.z, vc.w};
        float h1[4];
#pragma unroll
        for (int i = 0; i < 4; i++) {
            int o = half * 4 + i;
            float a = s_b1[o];
#pragma unroll
            for (int j = 0; j < 12; j++) a = fmaf(vr[j], s_w1[j * 8 + o], a);
            h1[i] = fmaxf(a, 0.f);
        }
        float oth[4];
#pragma unroll
        for (int i = 0; i < 4; i++) oth[i] = __shfl_xor_sync(~0u, h1[i], 1);
        float h1a[8];
#pragma unroll
        for (int j = 0; j < 8; j++)
            h1a[j] = ((j >> 2) == half) ? h1[j & 3] : oth[j & 3];

        float h2[4];
#pragma unroll
        for (int i = 0; i < 4; i++) {
            int o = half * 4 + i;
            float a = s_b2[o];
#pragma unroll
            for (int j = 0; j < 8; j++) a = fmaf(h1a[j], s_w2[j * 8 + o], a);
            h2[i] = fmaxf(a, 0.f);
        }
#pragma unroll
        for (int i = 0; i < 4; i++) oth[i] = __shfl_xor_sync(~0u, h2[i], 1);
        float h2a[8];
#pragma unroll
        for (int j = 0; j < 8; j++)
            h2a[j] = ((j >> 2) == half) ? h2[j & 3] : oth[j & 3];

        float w16[8];
#pragma unroll
        for (int q = 0; q < 8; q++) {
            int o = half * 8 + q;
            float a = s_b3[o];
#pragma unroll
            for (int j = 0; j < 8; j++) a = fmaf(h2a[j], s_w3[j * 16 + o], a);
            w16[q] = fmaxf(a, 0.f);
        }
        float* dst = &s_wn[w][kk * 16 + half * 8];
        *(float4*)dst = make_float4(w16[0], w16[1], w16[2], w16[3]);
        *(float4*)(dst + 4) = make_float4(w16[4], w16[5], w16[6], w16[7]);
    }

    // hoisted PE weights (per-lane column)
    float wpe_r[12];
#pragma unroll
    for (int j = 0; j < 12; j++) wpe_r[j] = s_wpe[j * 32 + lane];
    float bpe_r = s_bpe[lane];

    // ---------- consume gathers: redistribute + maxes + PE ----------
    float2 msc = make_float2(-1e30f, -1e30f);
    float2 mgg = make_float2(-1e30f, -1e30f);
    float gmax1 = -1e30f;
    bool hi = lane >= 16;
    int c2i = 2 * (lane & 15);

#pragma unroll
    for (int k = 0; k < 16; k++) {
        float2 fd = __half22float2(*(__half2*)&td[k]);
        msc.x = fmaxf(msc.x, fd.x); msc.y = fmaxf(msc.y, fd.y);

        float2 f1 = __half22float2(*(__half2*)&t1[k]);
        if (hi) {
            *(float2*)&s_gfeat[w][k * 64 + c2i] = f1;
            mgg.x = fmaxf(mgg.x, f1.x); mgg.y = fmaxf(mgg.y, f1.y);
        } else {
            *(float2*)&s_gf[w][k * 32 + c2i] = f1;
        }

        const float* vk = &s_vi[w][k * 12];
        float pe = bpe_r;
#pragma unroll
        for (int j = 0; j < 12; j++) pe = fmaf(vk[j], wpe_r[j], pe);
        pe = fmaxf(pe, 0.f);
        s_gfeat[w][k * 64 + 32 + lane] = pe;
        gmax1 = fmaxf(gmax1, pe);
    }
    if (hi) *(float2*)&s_gmax[w][c2i] = mgg;
    s_gmax[w][32 + lane] = gmax1;
    *(float2*)&g_maxf[(size_t)m * 64 + 2 * lane] = msc;
    __syncwarp();

    // ---------- Phase 2 ----------
    int h = lane & 7;
    int g = lane >> 3;
    u64 wg1p[8];
    const float* wg1g = &s_wg1p[g * 136];
#pragma unroll
    for (int c2 = 0; c2 < 8; c2++)
        wg1p[c2] = pk2(wg1g[(2 * c2) * 8 + h], wg1g[(2 * c2 + 1) * 8 + h]);
    float wg2r[8];
#pragma unroll
    for (int j = 0; j < 8; j++) wg2r[j] = s_wg2[j * 8 + h];
    float bg1r = s_bg1[h], bg2r = s_bg2[h];

    // hmax fold: dot(gfeat - gmax, w) = dot(gfeat, w) - dot(gmax, w)
    {
        u64 hmp = 0ull;
        const u64* gmp = (const u64*)&s_gmax[w][g * 16];
#pragma unroll
        for (int c2 = 0; c2 < 8; c2++) fma2(hmp, gmp[c2], wg1p[c2]);
        float2 hmv = upk2(hmp);
        float hmax = hmv.x + hmv.y;
        hmax += __shfl_xor_sync(~0u, hmax, 8);
        hmax += __shfl_xor_sync(~0u, hmax, 16);
        bg1r -= hmax;
    }

    // Pass A: hid[k][h] -> smem (independent chains, unroll 4)
#pragma unroll 4
    for (int k = 0; k < 16; k++) {
        u64 hp = 0ull;
        const u64* gp = (const u64*)&s_gfeat[w][k * 64 + g * 16];
#pragma unroll
        for (int c2 = 0; c2 < 8; c2++) fma2(hp, gp[c2], wg1p[c2]);
        float2 hv = upk2(hp);
        float hid = hv.x + hv.y;
        hid += __shfl_xor_sync(~0u, hid, 8);
        hid += __shfl_xor_sync(~0u, hid, 16);
        hid = fmaxf(hid + bg1r, 0.f);
        if (lane < 8) s_hid[w][k * 8 + lane] = hid;
    }
    __syncwarp();

    // Pass B: scores via parallel broadcast-LDS dots (no serial shfl chain)
    {
        int kset = lane >> 3;   // 0..3
#pragma unroll
        for (int q = 0; q < 4; q++) {
            int k = kset + q * 4;
            const float* hv = &s_hid[w][k * 8];
            float scz = bg2r;
#pragma unroll
            for (int j = 0; j < 8; j++) scz = fmaf(hv[j], wg2r[j], scz);
            s_sc[w][k * 8 + h] = 1.f / (1.f + __expf(-scz));
        }
    }
    __syncwarp();

    // Pass C: weighted einsum
    u64 accp[8];
#pragma unroll
    for (int i = 0; i < 8; i++) accp[i] = 0ull;

#pragma unroll 4
    for (int k = 0; k < 16; k++) {
        float sC = s_sc[w][k * 8 + (lane >> 2)];
        float nf = s_gf[w][k * 32 + lane] * sC;
        u64 nfp = pk2(nf, nf);
        const u64* wp = (const u64*)&s_wn[w][k * 16];
#pragma unroll
        for (int q2 = 0; q2 < 8; q2++) fma2(accp[q2], nfp, wp[q2]);
    }

    // fp16 agg: lane writes 16 halves = 32B (2x STG.128)
    {
        size_t base = (size_t)m * 512 + lane * 16;
        float2 v0 = upk2(accp[0]), v1 = upk2(accp[1]);
        float2 v2 = upk2(accp[2]), v3 = upk2(accp[3]);
        H8 o0;
        o0.a = __floats2half2_rn(v0.x, v0.y); o0.b = __floats2half2_rn(v1.x, v1.y);
        o0.c = __floats2half2_rn(v2.x, v2.y); o0.d = __floats2half2_rn(v3.x, v3.y);
        *(H8*)&g_agg_h[base] = o0;
        float2 v4 = upk2(accp[4]), v5 = upk2(accp[5]);
        float2 v6 = upk2(accp[6]), v7 = upk2(accp[7]);
        H8 o1;
        o1.a = __floats2half2_rn(v4.x, v4.y); o1.b = __floats2half2_rn(v5.x, v5.y);
        o1.c = __floats2half2_rn(v6.x, v6.y); o1.d = __floats2half2_rn(v7.x, v7.y);
        *(H8*)&g_agg_h[base + 8] = o1;
    }
}

// =====================================================================
// Kernel C v2: tensor-core (mma.sync m16n8k16 fp16->fp32).
// 256 threads = 8 warps; warp w owns rows m0 + w*16 .. +16.
// main:    o64 = relu(agg_h[128,512] @ wlin_h[512,64] + blin)
// epilog:  out = leaky(o64_h @ wu2_h + mfs_h @ wsc_h + biases)
// smem: Bs[64][520]h (66560B, aliased by wu2h/wsch[128][72]h after main),
//       o64h[128][72]h, mfsh[128][72]h  -> total 103424B, 2 blocks/SM.
// =====================================================================
__global__ __launch_bounds__(256) void kC(
    const float* __restrict__ wlin, const float* __restrict__ blin,
    const float* __restrict__ wu2, const float* __restrict__ bu2,
    const float* __restrict__ wsc, const float* __restrict__ bsc,
    float* __restrict__ out) {
    extern __shared__ char smc[];
    __half* Bs   = (__half*)smc;                    // [64][520]
    __half* wu2h = (__half*)smc;                    // [128][72] (alias)
    __half* wsch = (__half*)(smc + 18432);          // [128][72] (alias)
    __half* o64h = (__half*)(smc + 66560);          // [128][72]
    __half* mfsh = (__half*)(smc + 66560 + 18432);  // [128][72]

    int tid = threadIdx.x;
    int lane = tid & 31, w = tid >> 5;
    int g = lane >> 2, t = lane & 3;
    int m0 = blockIdx.x * 128;

    // 1) wlin [512][64] f32 -> Bs[n][k] fp16 (stride 520)
    for (int i = tid; i < 512 * 16; i += 256) {
        int k = i >> 4, n4 = (i & 15) * 4;
        float4 v = *(const float4*)&wlin[k * 64 + n4];
        Bs[(n4 + 0) * 520 + k] = __float2half_rn(v.x);
        Bs[(n4 + 1) * 520 + k] = __float2half_rn(v.y);
        Bs[(n4 + 2) * 520 + k] = __float2half_rn(v.z);
        Bs[(n4 + 3) * 520 + k] = __float2half_rn(v.w);
    }
    // mfs tile: g_maxf f32 -> mfsh fp16 (stride 72)
    for (int i = tid; i < 128 * 16; i += 256) {
        int r = i >> 4, c4 = (i & 15) * 4;
        int mm = m0 + r;
        float4 v = (mm < M_PTS) ? *(const float4*)&g_maxf[(size_t)mm * 64 + c4]
                                : make_float4(0.f, 0.f, 0.f, 0.f);
        mfsh[r * 72 + c4 + 0] = __float2half_rn(v.x);
        mfsh[r * 72 + c4 + 1] = __float2half_rn(v.y);
        mfsh[r * 72 + c4 + 2] = __float2half_rn(v.z);
        mfsh[r * 72 + c4 + 3] = __float2half_rn(v.w);
    }
    __syncthreads();

    // 2) main GEMM
    int mrA = m0 + w * 16 + g;
    int mrB = mrA + 8;
    int mrAc = mrA < M_PTS ? mrA : M_PTS - 1;
    int mrBc = mrB < M_PTS ? mrB : M_PTS - 1;
    const __half* arow0 = &g_agg_h[(size_t)mrAc * 512];
    const __half* arow1 = &g_agg_h[(size_t)mrBc * 512];
    const __half* brow  = &Bs[(size_t)g * 520 + t * 2];

    float acc[8][4];
#pragma unroll
    for (int i = 0; i < 8; i++)
#pragma unroll
        for (int j = 0; j < 4; j++) acc[i][j] = 0.f;

#pragma unroll 2
    for (int ks = 0; ks < 32; ks++) {
        int kb = ks * 16 + t * 2;
        u32 a0 = *(const u32*)&arow0[kb];
        u32 a1 = *(const u32*)&arow1[kb];
        u32 a2 = *(const u32*)&arow0[kb + 8];
        u32 a3 = *(const u32*)&arow1[kb + 8];
#pragma unroll
        for (int nf = 0; nf < 8; nf++) {
            u32 b0 = *(const u32*)&brow[nf * 8 * 520 + ks * 16];
            u32 b1 = *(const u32*)&brow[nf * 8 * 520 + ks * 16 + 8];
            mma16816(acc[nf], a0, a1, a2, a3, b0, b1);
        }
    }

    // bias + relu -> o64h fp16
    {
        int r = w * 16 + g;
#pragma unroll
        for (int nf = 0; nf < 8; nf++) {
            int c = nf * 8 + t * 2;
            float b0v = __ldg(&blin[c]), b1v = __ldg(&blin[c + 1]);
            *(__half2*)&o64h[r * 72 + c] =
                __floats2half2_rn(fmaxf(acc[nf][0] + b0v, 0.f),
                                  fmaxf(acc[nf][1] + b1v, 0.f));
            *(__half2*)&o64h[(r + 8) * 72 + c] =
                __floats2half2_rn(fmaxf(acc[nf][2] + b0v, 0.f),
                                  fmaxf(acc[nf][3] + b1v, 0.f));
        }
    }
    __syncthreads();   // Bs reads done; safe to overwrite with wu2h/wsch

    // 3) wu2/wsc [64][128] f32 -> [n][k] fp16 (stride 72)
    for (int i = tid; i < 64 * 32; i += 256) {
        int k = i >> 5, n4 = (i & 31) * 4;
        float4 u = *(const float4*)&wu2[k * 128 + n4];
        float4 s = *(const float4*)&wsc[k * 128 + n4];
        wu2h[(n4 + 0) * 72 + k] = __float2half_rn(u.x);
        wu2h[(n4 + 1) * 72 + k] = __float2half_rn(u.y);
        wu2h[(n4 + 2) * 72 + k] = __float2half_rn(u.z);
        wu2h[(n4 + 3) * 72 + k] = __float2half_rn(u.w);
        wsch[(n4 + 0) * 72 + k] = __float2half_rn(s.x);
        wsch[(n4 + 1) * 72 + k] = __float2half_rn(s.y);
        wsch[(n4 + 2) * 72 + k] = __float2half_rn(s.z);
        wsch[(n4 + 3) * 72 + k] = __float2half_rn(s.w);
    }
    __syncthreads();

    // 4) epilogue GEMM: 16 n-frags over 128 cols, k=64 (4 k-steps)
    float acc2[16][4];
#pragma unroll
    for (int i = 0; i < 16; i++)
#pragma unroll
        for (int j = 0; j < 4; j++) acc2[i][j] = 0.f;

    const __half* orow0 = &o64h[(size_t)(w * 16 + g) * 72];
    const __half* orow1 = orow0 + 8 * 72;
    const __half* mrow0 = &mfsh[(size_t)(w * 16 + g) * 72];
    const __half* mrow1 = mrow0 + 8 * 72;
    const __half* urow  = &wu2h[(size_t)g * 72 + t * 2];
    const __half* srow  = &wsch[(size_t)g * 72 + t * 2];

#pragma unroll
    for (int ks = 0; ks < 4; ks++) {
        int kb = ks * 16 + t * 2;
        u32 ao0 = *(const u32*)&orow0[kb];
        u32 ao1 = *(const u32*)&orow1[kb];
        u32 ao2 = *(const u32*)&orow0[kb + 8];
        u32 ao3 = *(const u32*)&orow1[kb + 8];
        u32 am0 = *(const u32*)&mrow0[kb];
        u32 am1 = *(const u32*)&mrow1[kb];
        u32 am2 = *(const u32*)&mrow0[kb + 8];
        u32 am3 = *(const u32*)&mrow1[kb + 8];
#pragma unroll
        for (int nf = 0; nf < 16; nf++) {
            u32 bu0 = *(const u32*)&urow[nf * 8 * 72 + ks * 16];
            u32 bu1 = *(const u32*)&urow[nf * 8 * 72 + ks * 16 + 8];
            mma16816(acc2[nf], ao0, ao1, ao2, ao3, bu0, bu1);
            u32 bs0 = *(const u32*)&srow[nf * 8 * 72 + ks * 16];
            u32 bs1 = *(const u32*)&srow[nf * 8 * 72 + ks * 16 + 8];
            mma16816(acc2[nf], am0, am1, am2, am3, bs0, bs1);
        }
    }

    // 5) bias + leaky-relu + store (f32)
    {
        int r0 = m0 + w * 16 + g;
        int r1 = r0 + 8;
#pragma unroll
        for (int nf = 0; nf < 16; nf++) {
            int c = nf * 8 + t * 2;
            float bb0 = __ldg(&bu2[c]) + __ldg(&bsc[c]);
            float bb1 = __ldg(&bu2[c + 1]) + __ldg(&bsc[c + 1]);
            if (r0 < M_PTS) {
                float2 o = make_float2(lrelu(acc2[nf][0] + bb0),
                                       lrelu(acc2[nf][1] + bb1));
                *(float2*)&out[(size_t)r0 * 128 + c] = o;
            }
            if (r1 < M_PTS) {
                float2 o = make_float2(lrelu(acc2[nf][2] + bb0),
                                       lrelu(acc2[nf][3] + bb1));
                *(float2*)&out[(size_t)r1 * 128 + c] = o;
            }
        }
    }
}

// =====================================================================
extern "C" void kernel_launch(void* const* d_in, const int* in_sizes, int n_in,
                              void* d_out, int out_size) {
    const float* dense_feats = (const float*)d_in[1];
    const float* vi          = (const float*)d_in[5];
    const int*   nei         = (const int*)d_in[6];
    const float* w_u1  = (const float*)d_in[7];  const float* b_u1  = (const float*)d_in[8];
    const float* w_gu  = (const float*)d_in[9];  const float* b_gu  = (const float*)d_in[10];
    const float* w_pe  = (const float*)d_in[11]; const float* b_pe  = (const float*)d_in[12];
    const float* w_g1  = (const float*)d_in[13]; const float* b_g1  = (const float*)d_in[14];
    const float* w_g2  = (const float*)d_in[15]; const float* b_g2  = (const float*)d_in[16];
    const float* w_wn1 = (const float*)d_in[17]; const float* b_wn1 = (const float*)d_in[18];
    const float* w_wn2 = (const float*)d_in[19]; const float* b_wn2 = (const float*)d_in[20];
    const float* w_wn3 = (const float*)d_in[21]; const float* b_wn3 = (const float*)d_in[22];
    const float* w_lin = (const float*)d_in[23]; const float* b_lin = (const float*)d_in[24];
    const float* w_u2  = (const float*)d_in[25]; const float* b_u2  = (const float*)d_in[26];
    const float* w_sc  = (const float*)d_in[27]; const float* b_sc  = (const float*)d_in[28];
    float* out = (float*)d_out;

    int smemA = (64 * 130 + 64 * 32 + 32 * 32 + 32 * 130) * 4;   // 62208 B
    cudaFuncSetAttribute(kA, cudaFuncAttributeMaxDynamicSharedMemorySize, smemA);
    kA<<<(N_PTS + 127) / 128, 256, smemA>>>(dense_feats, w_u1, b_u1, w_gu, b_gu);

    kB<<<(M_PTS + 3) / 4, 128>>>(vi, nei,
                                 w_pe, b_pe, w_g1, b_g1, w_g2, b_g2,
                                 w_wn1, b_wn1, w_wn2, b_wn2, w_wn3, b_wn3);

    int smemC = 66560 + 18432 + 18432;                           // 103424 B
    cudaFuncSetAttribute(kC, cudaFuncAttributeMaxDynamicSharedMemorySize, smemC);
    kC<<<(M_PTS + 127) / 128, 256, smemC>>>(w_lin, b_lin, w_u2, b_u2, w_sc, b_sc, out);
}

// round 17
// speedup vs baseline: 2.4748x; 1.0626x over previous
#include <cuda_runtime.h>
#include <cuda_fp16.h>
#include <cstdint>

#define N_PTS 200000
#define M_PTS 100000

typedef unsigned long long u64;
typedef unsigned int u32;

// ---- scratch (device-global, no allocation) ----
__device__ __half g_cat[(size_t)N_PTS * 64];         // 25.6 MB: fx[0:32] | gx[32:64]
__device__ __half g_df_h[(size_t)N_PTS * 64];        // 25.6 MB
__device__ __half g_agg_h[(size_t)M_PTS * 512];      // 102.4 MB
__device__ float  g_maxf[M_PTS * 64];                // 25.6 MB

struct __align__(16) H8 { __half2 a, b, c, d; };

// ---- packed fp32x2 helpers ----
__device__ __forceinline__ u64 pk2(float x, float y) {
    u64 r; asm("mov.b64 %0,{%1,%2};" : "=l"(r) : "f"(x), "f"(y)); return r;
}
__device__ __forceinline__ float2 upk2(u64 v) {
    float2 r; asm("mov.b64 {%0,%1},%2;" : "=f"(r.x), "=f"(r.y) : "l"(v)); return r;
}
__device__ __forceinline__ void fma2(u64& d, u64 a, u64 b) {
    asm("fma.rn.f32x2 %0,%1,%2,%3;" : "=l"(d) : "l"(a), "l"(b), "l"(d));
}
__device__ __forceinline__ float lrelu(float x) { return x > 0.f ? x : 0.1f * x; }

// ---- tensor core mma m16n8k16 fp16 -> fp32 ----
__device__ __forceinline__ void mma16816(float* c, u32 a0, u32 a1, u32 a2, u32 a3,
                                         u32 b0, u32 b1) {
    asm volatile(
        "mma.sync.aligned.m16n8k16.row.col.f32.f16.f16.f32 "
        "{%0,%1,%2,%3}, {%4,%5,%6,%7}, {%8,%9}, {%0,%1,%2,%3};"
        : "+f"(c[0]), "+f"(c[1]), "+f"(c[2]), "+f"(c[3])
        : "r"(a0), "r"(a1), "r"(a2), "r"(a3), "r"(b0), "r"(b1));
}

// =====================================================================
// Kernel A: tiled GEMM, 128 points/block, 256 threads. (unchanged)
// =====================================================================
__global__ __launch_bounds__(256) void kA(const float* __restrict__ df,
                                          const float* __restrict__ w1,
                                          const float* __restrict__ b1,
                                          const float* __restrict__ wgu,
                                          const float* __restrict__ bgu) {
    extern __shared__ float sm[];
    float* s_dfT = sm;                 // [64][130]
    float* s_w1  = s_dfT + 64 * 130;   // [64][32]
    float* s_wgu = s_w1 + 2048;        // [32][32]
    float* s_fxT = s_wgu + 1024;       // [32][130]
    __shared__ float s_b1[32], s_bgu[32];

    int tid = threadIdx.x;
    int p0 = blockIdx.x * 128;

    for (int i = tid; i < 2048; i += 256) s_w1[i] = w1[i];
    for (int i = tid; i < 1024; i += 256) s_wgu[i] = wgu[i];
    if (tid < 32) { s_b1[tid] = b1[tid]; s_bgu[tid] = bgu[tid]; }

#pragma unroll
    for (int q = 0; q < 8; q++) {
        int f4 = tid + q * 256;
        int pt = f4 >> 4, c4 = (f4 & 15) * 4;
        int p = p0 + pt;
        float4 v = (p < N_PTS) ? *(const float4*)&df[(size_t)p * 64 + c4]
                               : make_float4(0.f, 0.f, 0.f, 0.f);
        s_dfT[(c4 + 0) * 130 + pt] = v.x;
        s_dfT[(c4 + 1) * 130 + pt] = v.y;
        s_dfT[(c4 + 2) * 130 + pt] = v.z;
        s_dfT[(c4 + 3) * 130 + pt] = v.w;
        if (p < N_PTS) {
            __half2* dst = (__half2*)&g_df_h[(size_t)p * 64 + c4];
            dst[0] = __floats2half2_rn(v.x, v.y);
            dst[1] = __floats2half2_rn(v.z, v.w);
        }
    }
    __syncthreads();

    int tx = tid & 7;
    int ty = tid >> 3;

    u64 acc[2][4];
#pragma unroll
    for (int i = 0; i < 2; i++)
#pragma unroll
        for (int j = 0; j < 4; j++) acc[i][j] = 0ull;

#pragma unroll 8
    for (int kk = 0; kk < 64; kk++) {
        const float* ar = &s_dfT[kk * 130 + ty * 4];
        u64 a01 = *(const u64*)(ar);
        u64 a23 = *(const u64*)(ar + 2);
        float4 bv = *(const float4*)&s_w1[kk * 32 + tx * 4];
        u64 b0 = pk2(bv.x, bv.x), b1p = pk2(bv.y, bv.y);
        u64 b2 = pk2(bv.z, bv.z), b3p = pk2(bv.w, bv.w);
        fma2(acc[0][0], a01, b0); fma2(acc[0][1], a01, b1p);
        fma2(acc[0][2], a01, b2); fma2(acc[0][3], a01, b3p);
        fma2(acc[1][0], a23, b0); fma2(acc[1][1], a23, b1p);
        fma2(acc[1][2], a23, b2); fma2(acc[1][3], a23, b3p);
    }

    float fx[4][4];
#pragma unroll
    for (int pp = 0; pp < 2; pp++)
#pragma unroll
        for (int j = 0; j < 4; j++) {
            float2 v = upk2(acc[pp][j]);
            float bb = s_b1[tx * 4 + j];
            fx[2 * pp][j] = lrelu(v.x + bb);
            fx[2 * pp + 1][j] = lrelu(v.y + bb);
        }
#pragma unroll
    for (int i = 0; i < 4; i++) {
        int pt = ty * 4 + i;
#pragma unroll
        for (int j = 0; j < 4; j++) s_fxT[(tx * 4 + j) * 130 + pt] = fx[i][j];
        int p = p0 + pt;
        if (p < N_PTS) {
            __half2* dst = (__half2*)&g_cat[(size_t)p * 64 + tx * 4];
            dst[0] = __floats2half2_rn(fx[i][0], fx[i][1]);
            dst[1] = __floats2half2_rn(fx[i][2], fx[i][3]);
        }
    }
    __syncthreads();

    u64 acc2[2][4];
#pragma unroll
    for (int i = 0; i < 2; i++)
#pragma unroll
        for (int j = 0; j < 4; j++) acc2[i][j] = 0ull;

#pragma unroll 8
    for (int kk = 0; kk < 32; kk++) {
        const float* ar = &s_fxT[kk * 130 + ty * 4];
        u64 a01 = *(const u64*)(ar);
        u64 a23 = *(const u64*)(ar + 2);
        float4 bv = *(const float4*)&s_wgu[kk * 32 + tx * 4];
        u64 b0 = pk2(bv.x, bv.x), b1p = pk2(bv.y, bv.y);
        u64 b2 = pk2(bv.z, bv.z), b3p = pk2(bv.w, bv.w);
        fma2(acc2[0][0], a01, b0); fma2(acc2[0][1], a01, b1p);
        fma2(acc2[0][2], a01, b2); fma2(acc2[0][3], a01, b3p);
        fma2(acc2[1][0], a23, b0); fma2(acc2[1][1], a23, b1p);
        fma2(acc2[1][2], a23, b2); fma2(acc2[1][3], a23, b3p);
    }
#pragma unroll
    for (int pp = 0; pp < 2; pp++) {
#pragma unroll
        for (int i = 0; i < 2; i++) {
            int pt = ty * 4 + 2 * pp + i;
            int p = p0 + pt;
            if (p < N_PTS) {
                float2 v0 = upk2(acc2[pp][0]); float2 v1 = upk2(acc2[pp][1]);
                float2 v2 = upk2(acc2[pp][2]); float2 v3 = upk2(acc2[pp][3]);
                float o0 = (i ? v0.y : v0.x) + s_bgu[tx * 4 + 0];
                float o1 = (i ? v1.y : v1.x) + s_bgu[tx * 4 + 1];
                float o2 = (i ? v2.y : v2.x) + s_bgu[tx * 4 + 2];
                float o3 = (i ? v3.y : v3.x) + s_bgu[tx * 4 + 3];
                __half2* dst = (__half2*)&g_cat[(size_t)p * 64 + 32 + tx * 4];
                dst[0] = __floats2half2_rn(o0, o1);
                dst[1] = __floats2half2_rn(o2, o3);
            }
        }
    }
}

// =====================================================================
// Kernel D (NEW): shortcut max-pool. Warp-per-point, zero smem,
// 16 front-batched half2-line gathers + hmax2 reduce.
// =====================================================================
__global__ __launch_bounds__(256) void kD(const int* __restrict__ nei) {
    int tid = threadIdx.x;
    int lane = tid & 31, w = tid >> 5;
    int m = blockIdx.x * 8 + w;
    if (m >= M_PTS) return;

    int myidx = 0;
    if (lane < 16) myidx = nei[m * 16 + lane];

    const u32* dfp = (const u32*)g_df_h;
    u32 v[16];
#pragma unroll
    for (int k = 0; k < 16; k++) {
        int n = __shfl_sync(~0u, myidx, k);
        v[k] = __ldg(&dfp[(size_t)n * 32 + lane]);
    }
    __half2 mx = __floats2half2_rn(-65504.f, -65504.f);
#pragma unroll
    for (int k = 0; k < 16; k++) mx = __hmax2(mx, *(__half2*)&v[k]);
    float2 f = __half22float2(mx);
    *(float2*)&g_maxf[(size_t)m * 64 + 2 * lane] = f;
}

// =====================================================================
// Kernel B v6: warp-per-point, occupancy-dieted (fp16 smem staging).
// smem ~27.5KB/block -> 8 blocks/SM (launch_bounds(128,8)).
// df/shortcut work moved to kD.
// =====================================================================
__global__ __launch_bounds__(128, 8) void kB(
    const float* __restrict__ vi, const int* __restrict__ nei,
    const float* __restrict__ wpe, const float* __restrict__ bpe,
    const float* __restrict__ wg1, const float* __restrict__ bg1,
    const float* __restrict__ wg2, const float* __restrict__ bg2,
    const float* __restrict__ wn1, const float* __restrict__ bn1,
    const float* __restrict__ wn2, const float* __restrict__ bn2,
    const float* __restrict__ wn3, const float* __restrict__ bn3) {
    __shared__ float s_wpe[384], s_bpe[32];
    __shared__ float s_wg1p[544], s_bg1[8], s_wg2[64], s_bg2[8];
    __shared__ float s_w1[96], s_b1[8], s_w2[64], s_b2[8], s_w3[128], s_b3[16];
    __shared__ __align__(16) float s_vi[4][192];
    __shared__ __align__(16) __half s_gfeat[4][1024];   // 8KB: gg|pe per k
    __shared__ __align__(16) u32 s_gf[4][256];          // 4KB: raw fx half2
    __shared__ __align__(16) u32 s_wn[4][128];          // 2KB: wn half2
    __shared__ __align__(16) float s_gmax[4][64];
    __shared__ float s_hid[4][128], s_sc[4][128];
    __shared__ int s_idx[4][16];

    int tid = threadIdx.x;
    for (int i = tid; i < 384; i += 128) s_wpe[i] = wpe[i];
    for (int i = tid; i < 512; i += 128) {
        int c = i >> 3, h2 = i & 7;
        s_wg1p[(c >> 4) * 136 + (c & 15) * 8 + h2] = wg1[i];
    }
    if (tid < 64)  s_wg2[tid] = wg2[tid];
    if (tid < 96)  s_w1[tid] = wn1[tid];
    if (tid < 64)  s_w2[tid] = wn2[tid];
    if (tid < 128) s_w3[tid] = wn3[tid];
    if (tid < 32)  s_bpe[tid] = bpe[tid];
    if (tid < 8) { s_bg1[tid] = bg1[tid]; s_bg2[tid] = bg2[tid];
                   s_b1[tid] = bn1[tid]; s_b2[tid] = bn2[tid]; }
    if (tid < 16) s_b3[tid] = bn3[tid];
    __syncthreads();

    int lane = tid & 31, w = tid >> 5;
    int m = blockIdx.x * 4 + w;
    if (m >= M_PTS) return;

    for (int i = lane; i < 48; i += 32)
        *(float4*)&s_vi[w][i * 4] = *(const float4*)&vi[(size_t)m * 192 + i * 4];
    if (lane < 16) s_idx[w][lane] = nei[m * 16 + lane];
    __syncwarp();

    // ---------- WeightNet, vectorized over k: 2 lanes per neighbor ----------
    {
        int kk = lane >> 1, half = lane & 1;
        const float* vk = &s_vi[w][kk * 12];
        float4 va = *(const float4*)vk;
        float4 vb = *(const float4*)(vk + 4);
        float4 vc = *(const float4*)(vk + 8);
        float vr[12] = {va.x, va.y, va.z, va.w, vb.x, vb.y, vb.z, vb.w,
                        vc.x, vc.y, vc.z, vc.w};
        float h1[4];
#pragma unroll
        for (int i = 0; i < 4; i++) {
            int o = half * 4 + i;
            float a = s_b1[o];
#pragma unroll
            for (int j = 0; j < 12; j++) a = fmaf(vr[j], s_w1[j * 8 + o], a);
            h1[i] = fmaxf(a, 0.f);
        }
        float oth[4];
#pragma unroll
        for (int i = 0; i < 4; i++) oth[i] = __shfl_xor_sync(~0u, h1[i], 1);
        float h1a[8];
#pragma unroll
        for (int j = 0; j < 8; j++)
            h1a[j] = ((j >> 2) == half) ? h1[j & 3] : oth[j & 3];

        float h2[4];
#pragma unroll
        for (int i = 0; i < 4; i++) {
            int o = half * 4 + i;
            float a = s_b2[o];
#pragma unroll
            for (int j = 0; j < 8; j++) a = fmaf(h1a[j], s_w2[j * 8 + o], a);
            h2[i] = fmaxf(a, 0.f);
        }
#pragma unroll
        for (int i = 0; i < 4; i++) oth[i] = __shfl_xor_sync(~0u, h2[i], 1);
        float h2a[8];
#pragma unroll
        for (int j = 0; j < 8; j++)
            h2a[j] = ((j >> 2) == half) ? h2[j & 3] : oth[j & 3];

        // pack to half2 and store (wn output is used at fp16 precision)
        u32* dst = &s_wn[w][kk * 8 + half * 4];
#pragma unroll
        for (int q = 0; q < 4; q++) {
            int o0 = half * 8 + 2 * q;
            float a0 = s_b3[o0], a1 = s_b3[o0 + 1];
#pragma unroll
            for (int j = 0; j < 8; j++) {
                a0 = fmaf(h2a[j], s_w3[j * 16 + o0], a0);
                a1 = fmaf(h2a[j], s_w3[j * 16 + o0 + 1], a1);
            }
            __half2 hv = __floats2half2_rn(fmaxf(a0, 0.f), fmaxf(a1, 0.f));
            dst[q] = *(u32*)&hv;
        }
    }

    // ---------- Phase 1: gathers (2 batches of 8) + PE + maxes ----------
    float2 mgg = make_float2(-1e30f, -1e30f);
    float gmax1 = -1e30f;
    bool hi = lane >= 16;
    int p16 = lane & 15;
    const u32* catp = (const u32*)g_cat;

#pragma unroll
    for (int b = 0; b < 2; b++) {
        u32 t1[8];
#pragma unroll
        for (int kk = 0; kk < 8; kk++) {
            size_t n32 = (size_t)s_idx[w][b * 8 + kk] * 32 + lane;
            t1[kk] = __ldg(&catp[n32]);
        }
#pragma unroll
        for (int kk = 0; kk < 8; kk++) {
            int k = b * 8 + kk;
            if (hi) {   // gg pair for channels 2*p16, 2*p16+1 -> gfeat[0:32]
                ((u32*)&s_gfeat[w][k * 64])[p16] = t1[kk];
                float2 f1 = __half22float2(*(__half2*)&t1[kk]);
                mgg.x = fmaxf(mgg.x, f1.x); mgg.y = fmaxf(mgg.y, f1.y);
            } else {    // fx pair (raw half2)
                s_gf[w][k * 16 + p16] = t1[kk];
            }
            const float* vk = &s_vi[w][k * 12];
            float pe = s_bpe[lane];
#pragma unroll
            for (int j = 0; j < 12; j++) pe = fmaf(vk[j], s_wpe[j * 32 + lane], pe);
            pe = fmaxf(pe, 0.f);
            s_gfeat[w][k * 64 + 32 + lane] = __float2half_rn(pe);
            gmax1 = fmaxf(gmax1, pe);
        }
    }
    if (hi) *(float2*)&s_gmax[w][2 * p16] = mgg;
    s_gmax[w][32 + lane] = gmax1;
    __syncwarp();

    // ---------- Phase 2 ----------
    int h = lane & 7;
    int g = lane >> 3;
    u64 wg1p[8];
    const float* wg1g = &s_wg1p[g * 136];
#pragma unroll
    for (int c2 = 0; c2 < 8; c2++)
        wg1p[c2] = pk2(wg1g[(2 * c2) * 8 + h], wg1g[(2 * c2 + 1) * 8 + h]);
    float wg2r[8];
#pragma unroll
    for (int j = 0; j < 8; j++) wg2r[j] = s_wg2[j * 8 + h];
    float bg1r = s_bg1[h], bg2r = s_bg2[h];

    // hmax fold: dot(gfeat - gmax, w) = dot(gfeat, w) - dot(gmax, w)
    {
        u64 hmp = 0ull;
        const u64* gmp = (const u64*)&s_gmax[w][g * 16];
#pragma unroll
        for (int c2 = 0; c2 < 8; c2++) fma2(hmp, gmp[c2], wg1p[c2]);
        float2 hmv = upk2(hmp);
        float hmax = hmv.x + hmv.y;
        hmax += __shfl_xor_sync(~0u, hmax, 8);
        hmax += __shfl_xor_sync(~0u, hmax, 16);
        bg1r -= hmax;
    }

    // Pass A: hid[k][h] -> smem (gfeat read as half2, converted)
#pragma unroll 4
    for (int k = 0; k < 16; k++) {
        u64 hp = 0ull;
        const u32* gp = (const u32*)&s_gfeat[w][k * 64 + g * 16];
#pragma unroll
        for (int c2 = 0; c2 < 8; c2++) {
            u32 v = gp[c2];
            float2 f = __half22float2(*(__half2*)&v);
            fma2(hp, pk2(f.x, f.y), wg1p[c2]);
        }
        float2 hv = upk2(hp);
        float hid = hv.x + hv.y;
        hid += __shfl_xor_sync(~0u, hid, 8);
        hid += __shfl_xor_sync(~0u, hid, 16);
        hid = fmaxf(hid + bg1r, 0.f);
        if (lane < 8) s_hid[w][k * 8 + lane] = hid;
    }
    __syncwarp();

    // Pass B: scores via parallel broadcast-LDS dots
    {
        int kset = lane >> 3;
#pragma unroll
        for (int q = 0; q < 4; q++) {
            int k = kset + q * 4;
            const float* hv = &s_hid[w][k * 8];
            float scz = bg2r;
#pragma unroll
            for (int j = 0; j < 8; j++) scz = fmaf(hv[j], wg2r[j], scz);
            s_sc[w][k * 8 + h] = 1.f / (1.f + __expf(-scz));
        }
    }
    __syncwarp();

    // Pass C: weighted einsum (gf/wn from raw half2)
    u64 accp[8];
#pragma unroll
    for (int i = 0; i < 8; i++) accp[i] = 0ull;

#pragma unroll 4
    for (int k = 0; k < 16; k++) {
        float sC = s_sc[w][k * 8 + (lane >> 2)];
        u32 gfv = s_gf[w][k * 16 + (lane >> 1)];
        float nf = __half2float(((__half*)&gfv)[lane & 1]) * sC;
        u64 nfp = pk2(nf, nf);
        const u32* wp = &s_wn[w][k * 8];
#pragma unroll
        for (int q2 = 0; q2 < 8; q2++) {
            u32 wv = wp[q2];
            float2 wf = __half22float2(*(__half2*)&wv);
            fma2(accp[q2], nfp, pk2(wf.x, wf.y));
        }
    }

    // fp16 agg: lane writes 16 halves = 32B (2x STG.128)
    {
        size_t base = (size_t)m * 512 + lane * 16;
        float2 v0 = upk2(accp[0]), v1 = upk2(accp[1]);
        float2 v2 = upk2(accp[2]), v3 = upk2(accp[3]);
        H8 o0;
        o0.a = __floats2half2_rn(v0.x, v0.y); o0.b = __floats2half2_rn(v1.x, v1.y);
        o0.c = __floats2half2_rn(v2.x, v2.y); o0.d = __floats2half2_rn(v3.x, v3.y);
        *(H8*)&g_agg_h[base] = o0;
        float2 v4 = upk2(accp[4]), v5 = upk2(accp[5]);
        float2 v6 = upk2(accp[6]), v7 = upk2(accp[7]);
        H8 o1;
        o1.a = __floats2half2_rn(v4.x, v4.y); o1.b = __floats2half2_rn(v5.x, v5.y);
        o1.c = __floats2half2_rn(v6.x, v6.y); o1.d = __floats2half2_rn(v7.x, v7.y);
        *(H8*)&g_agg_h[base + 8] = o1;
    }
}

// =====================================================================
// Kernel C v2: tensor-core (mma.sync m16n8k16 fp16->fp32). (unchanged)
// =====================================================================
__global__ __launch_bounds__(256) void kC(
    const float* __restrict__ wlin, const float* __restrict__ blin,
    const float* __restrict__ wu2, const float* __restrict__ bu2,
    const float* __restrict__ wsc, const float* __restrict__ bsc,
    float* __restrict__ out) {
    extern __shared__ char smc[];
    __half* Bs   = (__half*)smc;                    // [64][520]
    __half* wu2h = (__half*)smc;                    // [128][72] (alias)
    __half* wsch = (__half*)(smc + 18432);          // [128][72] (alias)
    __half* o64h = (__half*)(smc + 66560);          // [128][72]
    __half* mfsh = (__half*)(smc + 66560 + 18432);  // [128][72]

    int tid = threadIdx.x;
    int lane = tid & 31, w = tid >> 5;
    int g = lane >> 2, t = lane & 3;
    int m0 = blockIdx.x * 128;

    // 1) wlin [512][64] f32 -> Bs[n][k] fp16 (stride 520)
    for (int i = tid; i < 512 * 16; i += 256) {
        int k = i >> 4, n4 = (i & 15) * 4;
        float4 v = *(const float4*)&wlin[k * 64 + n4];
        Bs[(n4 + 0) * 520 + k] = __float2half_rn(v.x);
        Bs[(n4 + 1) * 520 + k] = __float2half_rn(v.y);
        Bs[(n4 + 2) * 520 + k] = __float2half_rn(v.z);
        Bs[(n4 + 3) * 520 + k] = __float2half_rn(v.w);
    }
    // mfs tile: g_maxf f32 -> mfsh fp16 (stride 72)
    for (int i = tid; i < 128 * 16; i += 256) {
        int r = i >> 4, c4 = (i & 15) * 4;
        int mm = m0 + r;
        float4 v = (mm < M_PTS) ? *(const float4*)&g_maxf[(size_t)mm * 64 + c4]
                                : make_float4(0.f, 0.f, 0.f, 0.f);
        mfsh[r * 72 + c4 + 0] = __float2half_rn(v.x);
        mfsh[r * 72 + c4 + 1] = __float2half_rn(v.y);
        mfsh[r * 72 + c4 + 2] = __float2half_rn(v.z);
        mfsh[r * 72 + c4 + 3] = __float2half_rn(v.w);
    }
    __syncthreads();

    // 2) main GEMM
    int mrA = m0 + w * 16 + g;
    int mrB = mrA + 8;
    int mrAc = mrA < M_PTS ? mrA : M_PTS - 1;
    int mrBc = mrB < M_PTS ? mrB : M_PTS - 1;
    const __half* arow0 = &g_agg_h[(size_t)mrAc * 512];
    const __half* arow1 = &g_agg_h[(size_t)mrBc * 512];
    const __half* brow  = &Bs[(size_t)g * 520 + t * 2];

    float acc[8][4];
#pragma unroll
    for (int i = 0; i < 8; i++)
#pragma unroll
        for (int j = 0; j < 4; j++) acc[i][j] = 0.f;

#pragma unroll 2
    for (int ks = 0; ks < 32; ks++) {
        int kb = ks * 16 + t * 2;
        u32 a0 = *(const u32*)&arow0[kb];
        u32 a1 = *(const u32*)&arow1[kb];
        u32 a2 = *(const u32*)&arow0[kb + 8];
        u32 a3 = *(const u32*)&arow1[kb + 8];
#pragma unroll
        for (int nf = 0; nf < 8; nf++) {
            u32 b0 = *(const u32*)&brow[nf * 8 * 520 + ks * 16];
            u32 b1 = *(const u32*)&brow[nf * 8 * 520 + ks * 16 + 8];
            mma16816(acc[nf], a0, a1, a2, a3, b0, b1);
        }
    }

    // bias + relu -> o64h fp16
    {
        int r = w * 16 + g;
#pragma unroll
        for (int nf = 0; nf < 8; nf++) {
            int c = nf * 8 + t * 2;
            float b0v = __ldg(&blin[c]), b1v = __ldg(&blin[c + 1]);
            *(__half2*)&o64h[r * 72 + c] =
                __floats2half2_rn(fmaxf(acc[nf][0] + b0v, 0.f),
                                  fmaxf(acc[nf][1] + b1v, 0.f));
            *(__half2*)&o64h[(r + 8) * 72 + c] =
                __floats2half2_rn(fmaxf(acc[nf][2] + b0v, 0.f),
                                  fmaxf(acc[nf][3] + b1v, 0.f));
        }
    }
    __syncthreads();   // Bs reads done; safe to overwrite with wu2h/wsch

    // 3) wu2/wsc [64][128] f32 -> [n][k] fp16 (stride 72)
    for (int i = tid; i < 64 * 32; i += 256) {
        int k = i >> 5, n4 = (i & 31) * 4;
        float4 u = *(const float4*)&wu2[k * 128 + n4];
        float4 s = *(const float4*)&wsc[k * 128 + n4];
        wu2h[(n4 + 0) * 72 + k] = __float2half_rn(u.x);
        wu2h[(n4 + 1) * 72 + k] = __float2half_rn(u.y);
        wu2h[(n4 + 2) * 72 + k] = __float2half_rn(u.z);
        wu2h[(n4 + 3) * 72 + k] = __float2half_rn(u.w);
        wsch[(n4 + 0) * 72 + k] = __float2half_rn(s.x);
        wsch[(n4 + 1) * 72 + k] = __float2half_rn(s.y);
        wsch[(n4 + 2) * 72 + k] = __float2half_rn(s.z);
        wsch[(n4 + 3) * 72 + k] = __float2half_rn(s.w);
    }
    __syncthreads();

    // 4) epilogue GEMM: 16 n-frags over 128 cols, k=64 (4 k-steps)
    float acc2[16][4];
#pragma unroll
    for (int i = 0; i < 16; i++)
#pragma unroll
        for (int j = 0; j < 4; j++) acc2[i][j] = 0.f;

    const __half* orow0 = &o64h[(size_t)(w * 16 + g) * 72];
    const __half* orow1 = orow0 + 8 * 72;
    const __half* mrow0 = &mfsh[(size_t)(w * 16 + g) * 72];
    const __half* mrow1 = mrow0 + 8 * 72;
    const __half* urow  = &wu2h[(size_t)g * 72 + t * 2];
    const __half* srow  = &wsch[(size_t)g * 72 + t * 2];

#pragma unroll
    for (int ks = 0; ks < 4; ks++) {
        int kb = ks * 16 + t * 2;
        u32 ao0 = *(const u32*)&orow0[kb];
        u32 ao1 = *(const u32*)&orow1[kb];
        u32 ao2 = *(const u32*)&orow0[kb + 8];
        u32 ao3 = *(const u32*)&orow1[kb + 8];
        u32 am0 = *(const u32*)&mrow0[kb];
        u32 am1 = *(const u32*)&mrow1[kb];
        u32 am2 = *(const u32*)&mrow0[kb + 8];
        u32 am3 = *(const u32*)&mrow1[kb + 8];
#pragma unroll
        for (int nf = 0; nf < 16; nf++) {
            u32 bu0 = *(const u32*)&urow[nf * 8 * 72 + ks * 16];
            u32 bu1 = *(const u32*)&urow[nf * 8 * 72 + ks * 16 + 8];
            mma16816(acc2[nf], ao0, ao1, ao2, ao3, bu0, bu1);
            u32 bs0 = *(const u32*)&srow[nf * 8 * 72 + ks * 16];
            u32 bs1 = *(const u32*)&srow[nf * 8 * 72 + ks * 16 + 8];
            mma16816(acc2[nf], am0, am1, am2, am3, bs0, bs1);
        }
    }

    // 5) bias + leaky-relu + store (f32)
    {
        int r0 = m0 + w * 16 + g;
        int r1 = r0 + 8;
#pragma unroll
        for (int nf = 0; nf < 16; nf++) {
            int c = nf * 8 + t * 2;
            float bb0 = __ldg(&bu2[c]) + __ldg(&bsc[c]);
            float bb1 = __ldg(&bu2[c + 1]) + __ldg(&bsc[c + 1]);
            if (r0 < M_PTS) {
                float2 o = make_float2(lrelu(acc2[nf][0] + bb0),
                                       lrelu(acc2[nf][1] + bb1));
                *(float2*)&out[(size_t)r0 * 128 + c] = o;
            }
            if (r1 < M_PTS) {
                float2 o = make_float2(lrelu(acc2[nf][2] + bb0),
                                       lrelu(acc2[nf][3] + bb1));
                *(float2*)&out[(size_t)r1 * 128 + c] = o;
            }
        }
    }
}

// =====================================================================
extern "C" void kernel_launch(void* const* d_in, const int* in_sizes, int n_in,
                              void* d_out, int out_size) {
    const float* dense_feats = (const float*)d_in[1];
    const float* vi          = (const float*)d_in[5];
    const int*   nei         = (const int*)d_in[6];
    const float* w_u1  = (const float*)d_in[7];  const float* b_u1  = (const float*)d_in[8];
    const float* w_gu  = (const float*)d_in[9];  const float* b_gu  = (const float*)d_in[10];
    const float* w_pe  = (const float*)d_in[11]; const float* b_pe  = (const float*)d_in[12];
    const float* w_g1  = (const float*)d_in[13]; const float* b_g1  = (const float*)d_in[14];
    const float* w_g2  = (const float*)d_in[15]; const float* b_g2  = (const float*)d_in[16];
    const float* w_wn1 = (const float*)d_in[17]; const float* b_wn1 = (const float*)d_in[18];
    const float* w_wn2 = (const float*)d_in[19]; const float* b_wn2 = (const float*)d_in[20];
    const float* w_wn3 = (const float*)d_in[21]; const float* b_wn3 = (const float*)d_in[22];
    const float* w_lin = (const float*)d_in[23]; const float* b_lin = (const float*)d_in[24];
    const float* w_u2  = (const float*)d_in[25]; const float* b_u2  = (const float*)d_in[26];
    const float* w_sc  = (const float*)d_in[27]; const float* b_sc  = (const float*)d_in[28];
    float* out = (float*)d_out;

    int smemA = (64 * 130 + 64 * 32 + 32 * 32 + 32 * 130) * 4;   // 62208 B
    cudaFuncSetAttribute(kA, cudaFuncAttributeMaxDynamicSharedMemorySize, smemA);
    kA<<<(N_PTS + 127) / 128, 256, smemA>>>(dense_feats, w_u1, b_u1, w_gu, b_gu);

    kD<<<(M_PTS + 7) / 8, 256>>>(nei);

    kB<<<(M_PTS + 3) / 4, 128>>>(vi, nei,
                                 w_pe, b_pe, w_g1, b_g1, w_g2, b_g2,
                                 w_wn1, b_wn1, w_wn2, b_wn2, w_wn3, b_wn3);

    int smemC = 66560 + 18432 + 18432;                           // 103424 B
    cudaFuncSetAttribute(kC, cudaFuncAttributeMaxDynamicSharedMemorySize, smemC);
    kC<<<(M_PTS + 127) / 128, 256, smemC>>>(w_lin, b_lin, w_u2, b_u2, w_sc, b_sc, out);
}